// round 9
// baseline (speedup 1.0000x reference)
#include <cuda_runtime.h>
#include <math.h>

#define NW 512      // num windows (B_)
#define LQ 256      // tokens per window (L)
#define CD 128      // channels (C)
#define NH 4        // heads
#define HD 32       // head dim
#define MT 1575     // rel table rows (15*15*7)

// ---------------- packed f32x2 helpers (Blackwell PTX-only ops) ----------------
__device__ __forceinline__ unsigned long long f2pack(float lo, float hi) {
    unsigned long long r;
    asm("mov.b64 %0, {%1, %2};" : "=l"(r) : "f"(lo), "f"(hi));
    return r;
}
__device__ __forceinline__ void f2unpack(unsigned long long v, float& lo, float& hi) {
    asm("mov.b64 {%0, %1}, %2;" : "=f"(lo), "=f"(hi) : "l"(v));
}
__device__ __forceinline__ unsigned long long f2fma(unsigned long long a,
                                                    unsigned long long b,
                                                    unsigned long long c) {
    unsigned long long d;
    asm("fma.rn.f32x2 %0, %1, %2, %3;" : "=l"(d) : "l"(a), "l"(b), "l"(c));
    return d;
}
__device__ __forceinline__ unsigned long long f2add(unsigned long long a,
                                                    unsigned long long b) {
    unsigned long long d;
    asm("add.rn.f32x2 %0, %1, %2;" : "=l"(d) : "l"(a), "l"(b));
    return d;
}
__device__ __forceinline__ unsigned long long f2mul(unsigned long long a,
                                                    unsigned long long b) {
    unsigned long long d;
    asm("mul.rn.f32x2 %0, %1, %2;" : "=l"(d) : "l"(a), "l"(b));
    return d;
}

// ---------------- device scratch (no runtime allocation allowed) ----------------
static __device__ float g_bias_table[MT * NH];                    // (M, H)
static __device__ float g_bias[NH * LQ * LQ];                     // 16*sigmoid - M_h, (H,L,L)
static __device__ float g_q[(size_t)NW * NH * LQ * HD];           // normalized+scaled q
static __device__ float g_k[(size_t)NW * NH * LQ * HD];           // normalized k
static __device__ float g_v[(size_t)NW * NH * LQ * HD];           // v
static __device__ float g_att[(size_t)NW * LQ * CD];              // attention output (B,L,C)

// ---------------- CPB MLP ----------------
__global__ void cpb_kernel(const float* __restrict__ table, const float* __restrict__ w1,
                           const float* __restrict__ b1, const float* __restrict__ w2)
{
    int t  = threadIdx.x;
    int mi = t >> 3, ui = t & 7;
    int m  = blockIdx.x * 32 + mi;
    float a0 = 0.f, a1 = 0.f, a2 = 0.f, a3 = 0.f;
    if (m < MT) {
        float t0 = table[m*3+0], t1 = table[m*3+1], t2 = table[m*3+2];
        for (int u = ui; u < 512; u += 8) {
            float hid = fmaf(w1[u*3+0], t0, fmaf(w1[u*3+1], t1, fmaf(w1[u*3+2], t2, b1[u])));
            hid = fmaxf(hid, 0.f);
            a0 = fmaf(hid, w2[u],        a0);
            a1 = fmaf(hid, w2[512+u],    a1);
            a2 = fmaf(hid, w2[1024+u],   a2);
            a3 = fmaf(hid, w2[1536+u],   a3);
        }
    }
    #pragma unroll
    for (int off = 4; off >= 1; off >>= 1) {
        a0 += __shfl_down_sync(0xffffffffu, a0, off, 8);
        a1 += __shfl_down_sync(0xffffffffu, a1, off, 8);
        a2 += __shfl_down_sync(0xffffffffu, a2, off, 8);
        a3 += __shfl_down_sync(0xffffffffu, a3, off, 8);
    }
    if (ui == 0 && m < MT) {
        g_bias_table[m*NH+0] = a0;
        g_bias_table[m*NH+1] = a1;
        g_bias_table[m*NH+2] = a2;
        g_bias_table[m*NH+3] = a3;
    }
}

// ---------------- bias gather + 16*sigmoid - M_h ----------------
// Folds the per-head logit upper bound M_h = scale_h + 16 into the bias table
// so attention needs NO online max: s' <= 0 always, and the diagonal term
// (q_i.k_i = scale_h exactly) keeps the softmax denominator >= exp(-16).
__global__ void bias_gather_kernel(const int* __restrict__ idx, const float* __restrict__ ls)
{
    int i = blockIdx.x * blockDim.x + threadIdx.x;   // over NH*LQ*LQ = 262144
    if (i >= NH * LQ * LQ) return;
    int h  = i >> 16;
    int ij = i & 65535;
    float mh = expf(fminf(ls[h], 4.60517018598809136804f)) + 16.f;  // scale_h + 16
    float x = g_bias_table[idx[ij] * NH + h];
    g_bias[i] = 16.f / (1.f + __expf(-x)) - mh;
}

// ---------------- QKV GEMM (64x128 tile) + fused bias/normalize, f32x2 math ------
__global__ __launch_bounds__(256, 2) void qkv_gemm_kernel(
    const float* __restrict__ A,      // x flattened (131072, 128)
    const float* __restrict__ W,      // qkv_w (384, 128)
    const float* __restrict__ qb,     // (128,)
    const float* __restrict__ vb,     // (128,)
    const float* __restrict__ ls)     // logit_scale (4,)
{
    __shared__ float sm[8448];
    __shared__ float fac[64 * 4];
    float* As = sm;                   // 64 x 36
    float* Ws = sm + 64*36;           // 128 x 36
    const int tid = threadIdx.x;
    const int tmode = blockIdx.y;     // 0 q, 1 k, 2 v
    const int r0 = blockIdx.x * 64;
    const int tr = tid >> 4, tc = tid & 15;

    unsigned long long acc2[4][8];
    #pragma unroll
    for (int r = 0; r < 4; r++)
        #pragma unroll
        for (int i = 0; i < 8; i++) acc2[r][i] = 0ull;

    const float* Wbase = W + tmode * 128 * 128;

    for (int kc = 0; kc < 4; kc++) {
        const int k0 = kc * 32;
        {
            int f = tid;
            #pragma unroll
            for (int rep = 0; rep < 2; rep++, f += 256) {
                int row = f >> 3, c4 = f & 7;
                float4 v = *(const float4*)(A + (size_t)(r0 + row) * CD + k0 + c4 * 4);
                float* d = As + row * 36 + c4 * 4;
                d[0] = v.x; d[1] = v.y; d[2] = v.z; d[3] = v.w;
            }
        }
        {
            int f = tid;
            #pragma unroll
            for (int rep = 0; rep < 4; rep++, f += 256) {
                int row = f >> 3, c4 = f & 7;
                float4 v = *(const float4*)(Wbase + row * CD + k0 + c4 * 4);
                float* d = Ws + row * 36 + c4 * 4;
                d[0] = v.x; d[1] = v.y; d[2] = v.z; d[3] = v.w;
            }
        }
        __syncthreads();
        #pragma unroll
        for (int k4 = 0; k4 < 8; k4++) {
            ulonglong2 a2[4], b2[8];
            #pragma unroll
            for (int r = 0; r < 4; r++)
                a2[r] = *(const ulonglong2*)(As + (tr*4 + r) * 36 + k4 * 4);
            #pragma unroll
            for (int i = 0; i < 8; i++)
                b2[i] = *(const ulonglong2*)(Ws + (tc + 16*i) * 36 + k4 * 4);
            #pragma unroll
            for (int r = 0; r < 4; r++)
                #pragma unroll
                for (int i = 0; i < 8; i++) {
                    acc2[r][i] = f2fma(a2[r].x, b2[i].x, acc2[r][i]);
                    acc2[r][i] = f2fma(a2[r].y, b2[i].y, acc2[r][i]);
                }
        }
        __syncthreads();
    }

    float acc[4][8];
    #pragma unroll
    for (int r = 0; r < 4; r++)
        #pragma unroll
        for (int i = 0; i < 8; i++) {
            float lo, hi;
            f2unpack(acc2[r][i], lo, hi);
            acc[r][i] = lo + hi;
        }

    float* S = sm;   // 64 x 132
    #pragma unroll
    for (int r = 0; r < 4; r++)
        #pragma unroll
        for (int i = 0; i < 8; i++) {
            int col = tc + 16*i;
            float bias = (tmode == 0) ? qb[col] : (tmode == 2) ? vb[col] : 0.f;
            S[(tr*4 + r) * 132 + col] = acc[r][i] + bias;
        }
    __syncthreads();
    {
        int row = tid >> 2, hh = tid & 3;
        float f;
        if (tmode == 2) {
            f = 1.f;
        } else {
            const float* p = S + row * 132 + hh * 32;
            float ss = 0.f;
            #pragma unroll
            for (int d = 0; d < 32; d++) ss = fmaf(p[d], p[d], ss);
            f = 1.f / fmaxf(sqrtf(ss), 1e-12f);
            if (tmode == 0) f *= expf(fminf(ls[hh], 4.60517018598809136804f)); // log(100)
        }
        fac[tid] = f;
    }
    __syncthreads();

    float* out = (tmode == 0) ? g_q : (tmode == 1) ? g_k : g_v;
    #pragma unroll
    for (int r = 0; r < 4; r++) {
        int row = tr*4 + r;
        int gr  = r0 + row;
        int b   = gr >> 8, l = gr & 255;
        #pragma unroll
        for (int i = 0; i < 8; i++) {
            int col = tc + 16*i;
            int hh = col >> 5, d = col & 31;
            out[(size_t)(((b * NH + hh) * LQ) + l) * HD + d] = S[row * 132 + col] * fac[row * 4 + hh];
        }
    }
}

// ---------------- flash-style attention per (window, head) ----------------
// 128 threads/CTA; each thread owns TWO query rows (tid, tid+128).
// Branch-free softmax (bound folded into bias). Bias rows are LDG from L2
// (234-262 cyc): DOUBLE-BUFFER them one 4-key block ahead so the latency
// drains behind the current block's ~240 cycles of f2fma work.
__global__ __launch_bounds__(128, 3) void attn_kernel()
{
    extern __shared__ float sh[];
    float* ks = sh;                 // 256 x 32
    float* vs = sh + LQ * HD;       // 256 x 32
    const int bh = blockIdx.x;      // b*4 + h
    const int h  = bh & 3;
    const int b  = bh >> 2;
    const float* qg = g_q + (size_t)bh * LQ * HD;
    const float* kg = g_k + (size_t)bh * LQ * HD;
    const float* vg = g_v + (size_t)bh * LQ * HD;
    const int tid = threadIdx.x;

    // stage k and v: 2048 float4 each, 128 threads -> 16 reps
    #pragma unroll
    for (int rep = 0; rep < 16; rep++) {
        int f = tid + rep * 128;            // float4 index
        *(float4*)(ks + (size_t)f * 4) = *(const float4*)(kg + (size_t)f * 4);
        *(float4*)(vs + (size_t)f * 4) = *(const float4*)(vg + (size_t)f * 4);
    }
    // two query rows into packed registers
    unsigned long long q0p[16], q1p[16];
    {
        const unsigned long long* q0g = (const unsigned long long*)(qg + (size_t)tid * HD);
        const unsigned long long* q1g = (const unsigned long long*)(qg + (size_t)(tid + 128) * HD);
        #pragma unroll
        for (int i = 0; i < 16; i++) { q0p[i] = q0g[i]; q1p[i] = q1g[i]; }
    }
    __syncthreads();

    const float* b0ptr = g_bias + h * (LQ * LQ) + tid * LQ;
    const float* b1ptr = b0ptr + 128 * LQ;

    float l0 = 0.f, l1 = 0.f;
    unsigned long long acc0[16], acc1[16];
    #pragma unroll
    for (int i = 0; i < 16; i++) { acc0[i] = 0ull; acc1[i] = 0ull; }

    // prefetch bias block 0
    float4 b0w = *(const float4*)(b0ptr);
    float4 b1w = *(const float4*)(b1ptr);

    #pragma unroll 1
    for (int j4 = 0; j4 < LQ / 4; j4++) {
        float4 b0c = b0w, b1c = b1w;
        if (j4 + 1 < LQ / 4) {                 // prefetch next block NOW
            b0w = *(const float4*)(b0ptr + (j4 + 1) * 4);
            b1w = *(const float4*)(b1ptr + (j4 + 1) * 4);
        }
        #pragma unroll
        for (int jj = 0; jj < 4; jj++) {
            int j = j4 * 4 + jj;
            const ulonglong2* krow = (const ulonglong2*)(ks + j * HD);

            unsigned long long sa0 = 0ull, sb0 = 0ull, sa1 = 0ull, sb1 = 0ull;
            #pragma unroll
            for (int i = 0; i < 8; i++) {
                ulonglong2 kk = krow[i];
                sa0 = f2fma(q0p[2*i],   kk.x, sa0);
                sb0 = f2fma(q0p[2*i+1], kk.y, sb0);
                sa1 = f2fma(q1p[2*i],   kk.x, sa1);
                sb1 = f2fma(q1p[2*i+1], kk.y, sb1);
            }
            float x0, y0, x1, y1;
            f2unpack(f2add(sa0, sb0), x0, y0);
            f2unpack(f2add(sa1, sb1), x1, y1);
            float bj0 = (jj == 0) ? b0c.x : (jj == 1) ? b0c.y : (jj == 2) ? b0c.z : b0c.w;
            float bj1 = (jj == 0) ? b1c.x : (jj == 1) ? b1c.y : (jj == 2) ? b1c.z : b1c.w;

            float p0 = __expf(x0 + y0 + bj0);   // arg <= 0: never overflows
            float p1 = __expf(x1 + y1 + bj1);
            l0 += p0;
            l1 += p1;

            unsigned long long pp0 = f2pack(p0, p0);
            unsigned long long pp1 = f2pack(p1, p1);
            const ulonglong2* vrow = (const ulonglong2*)(vs + j * HD);
            #pragma unroll
            for (int i = 0; i < 8; i++) {
                ulonglong2 vv = vrow[i];
                acc0[2*i]   = f2fma(pp0, vv.x, acc0[2*i]);
                acc0[2*i+1] = f2fma(pp0, vv.y, acc0[2*i+1]);
                acc1[2*i]   = f2fma(pp1, vv.x, acc1[2*i]);
                acc1[2*i+1] = f2fma(pp1, vv.y, acc1[2*i+1]);
            }
        }
    }

    unsigned long long inv0 = f2pack(1.f / l0, 1.f / l0);
    unsigned long long inv1 = f2pack(1.f / l1, 1.f / l1);
    unsigned long long* op0 = (unsigned long long*)(g_att + ((size_t)(b * LQ + tid)) * CD + h * HD);
    unsigned long long* op1 = (unsigned long long*)(g_att + ((size_t)(b * LQ + tid + 128)) * CD + h * HD);
    #pragma unroll
    for (int i = 0; i < 16; i++) {
        op0[i] = f2mul(inv0, acc0[i]);
        op1[i] = f2mul(inv1, acc1[i]);
    }
}

// ---------------- projection GEMM: out = att @ proj_w^T + proj_b, f32x2 math ------
__global__ __launch_bounds__(256, 2) void proj_gemm_kernel(
    const float* __restrict__ W,     // proj_w (128,128)
    const float* __restrict__ pb,    // (128,)
    float* __restrict__ out)
{
    __shared__ float sm[64*36 + 128*36];
    float* As = sm;
    float* Ws = sm + 64*36;
    const int tid = threadIdx.x;
    const int r0 = blockIdx.x * 64;
    const int tr = tid >> 4, tc = tid & 15;
    const float* A = g_att;

    unsigned long long acc2[4][8];
    #pragma unroll
    for (int r = 0; r < 4; r++)
        #pragma unroll
        for (int i = 0; i < 8; i++) acc2[r][i] = 0ull;

    for (int kc = 0; kc < 4; kc++) {
        const int k0 = kc * 32;
        {
            int f = tid;
            #pragma unroll
            for (int rep = 0; rep < 2; rep++, f += 256) {
                int row = f >> 3, c4 = f & 7;
                float4 v = *(const float4*)(A + (size_t)(r0 + row) * CD + k0 + c4 * 4);
                float* d = As + row * 36 + c4 * 4;
                d[0] = v.x; d[1] = v.y; d[2] = v.z; d[3] = v.w;
            }
        }
        {
            int f = tid;
            #pragma unroll
            for (int rep = 0; rep < 4; rep++, f += 256) {
                int row = f >> 3, c4 = f & 7;
                float4 v = *(const float4*)(W + row * CD + k0 + c4 * 4);
                float* d = Ws + row * 36 + c4 * 4;
                d[0] = v.x; d[1] = v.y; d[2] = v.z; d[3] = v.w;
            }
        }
        __syncthreads();
        #pragma unroll
        for (int k4 = 0; k4 < 8; k4++) {
            ulonglong2 a2[4], b2[8];
            #pragma unroll
            for (int r = 0; r < 4; r++)
                a2[r] = *(const ulonglong2*)(As + (tr*4 + r) * 36 + k4 * 4);
            #pragma unroll
            for (int i = 0; i < 8; i++)
                b2[i] = *(const ulonglong2*)(Ws + (tc + 16*i) * 36 + k4 * 4);
            #pragma unroll
            for (int r = 0; r < 4; r++)
                #pragma unroll
                for (int i = 0; i < 8; i++) {
                    acc2[r][i] = f2fma(a2[r].x, b2[i].x, acc2[r][i]);
                    acc2[r][i] = f2fma(a2[r].y, b2[i].y, acc2[r][i]);
                }
        }
        __syncthreads();
    }

    #pragma unroll
    for (int r = 0; r < 4; r++) {
        int gr = r0 + tr*4 + r;
        #pragma unroll
        for (int i = 0; i < 8; i++) {
            int col = tc + 16*i;
            float lo, hi;
            f2unpack(acc2[r][i], lo, hi);
            out[(size_t)gr * CD + col] = lo + hi + pb[col];
        }
    }
}

// ---------------- launch ----------------
extern "C" void kernel_launch(void* const* d_in, const int* in_sizes, int n_in,
                              void* d_out, int out_size)
{
    (void)in_sizes; (void)n_in; (void)out_size;
    const float* x       = (const float*)d_in[0];
    const float* qkv_w   = (const float*)d_in[1];
    const float* q_bias  = (const float*)d_in[2];
    const float* v_bias  = (const float*)d_in[3];
    const float* lscale  = (const float*)d_in[4];
    const float* cpb_w1  = (const float*)d_in[5];
    const float* cpb_b1  = (const float*)d_in[6];
    const float* cpb_w2  = (const float*)d_in[7];
    const float* proj_w  = (const float*)d_in[8];
    const float* proj_b  = (const float*)d_in[9];
    const float* rtable  = (const float*)d_in[10];
    const int*   ridx    = (const int*)d_in[11];
    float* out = (float*)d_out;

    static const int attn_smem = 2 * LQ * HD * 4;   // 65536 bytes
    cudaFuncSetAttribute(attn_kernel, cudaFuncAttributeMaxDynamicSharedMemorySize, attn_smem);

    cpb_kernel<<<(MT + 31) / 32, 256>>>(rtable, cpb_w1, cpb_b1, cpb_w2);
    bias_gather_kernel<<<(NH * LQ * LQ) / 256, 256>>>(ridx, lscale);
    qkv_gemm_kernel<<<dim3((NW * LQ) / 64, 3), 256>>>(x, qkv_w, q_bias, v_bias, lscale);
    attn_kernel<<<NW * NH, 128, attn_smem>>>();
    proj_gemm_kernel<<<(NW * LQ) / 64, 256>>>(proj_w, proj_b, out);
}

// round 10
// speedup vs baseline: 1.1123x; 1.1123x over previous
#include <cuda_runtime.h>
#include <math.h>

#define NW 512      // num windows (B_)
#define LQ 256      // tokens per window (L)
#define CD 128      // channels (C)
#define NH 4        // heads
#define HD 32       // head dim
#define MT 1575     // rel table rows (15*15*7)

// ---------------- packed f32x2 helpers (Blackwell PTX-only ops) ----------------
__device__ __forceinline__ unsigned long long f2pack(float lo, float hi) {
    unsigned long long r;
    asm("mov.b64 %0, {%1, %2};" : "=l"(r) : "f"(lo), "f"(hi));
    return r;
}
__device__ __forceinline__ void f2unpack(unsigned long long v, float& lo, float& hi) {
    asm("mov.b64 {%0, %1}, %2;" : "=f"(lo), "=f"(hi) : "l"(v));
}
__device__ __forceinline__ unsigned long long f2fma(unsigned long long a,
                                                    unsigned long long b,
                                                    unsigned long long c) {
    unsigned long long d;
    asm("fma.rn.f32x2 %0, %1, %2, %3;" : "=l"(d) : "l"(a), "l"(b), "l"(c));
    return d;
}
__device__ __forceinline__ unsigned long long f2add(unsigned long long a,
                                                    unsigned long long b) {
    unsigned long long d;
    asm("add.rn.f32x2 %0, %1, %2;" : "=l"(d) : "l"(a), "l"(b));
    return d;
}
__device__ __forceinline__ unsigned long long f2mul(unsigned long long a,
                                                    unsigned long long b) {
    unsigned long long d;
    asm("mul.rn.f32x2 %0, %1, %2;" : "=l"(d) : "l"(a), "l"(b));
    return d;
}

// ---------------- device scratch (no runtime allocation allowed) ----------------
static __device__ float g_bias_table[MT * NH];                    // (M, H)
static __device__ float g_bias[NH * LQ * LQ];                     // TRANSPOSED: [h][key][query]
static __device__ float g_q[(size_t)NW * NH * LQ * HD];           // normalized+scaled q
static __device__ float g_k[(size_t)NW * NH * LQ * HD];           // normalized k
static __device__ float g_v[(size_t)NW * NH * LQ * HD];           // v
static __device__ float g_att[(size_t)NW * LQ * CD];              // attention output (B,L,C)

// ---------------- CPB MLP ----------------
__global__ void cpb_kernel(const float* __restrict__ table, const float* __restrict__ w1,
                           const float* __restrict__ b1, const float* __restrict__ w2)
{
    int t  = threadIdx.x;
    int mi = t >> 3, ui = t & 7;
    int m  = blockIdx.x * 32 + mi;
    float a0 = 0.f, a1 = 0.f, a2 = 0.f, a3 = 0.f;
    if (m < MT) {
        float t0 = table[m*3+0], t1 = table[m*3+1], t2 = table[m*3+2];
        for (int u = ui; u < 512; u += 8) {
            float hid = fmaf(w1[u*3+0], t0, fmaf(w1[u*3+1], t1, fmaf(w1[u*3+2], t2, b1[u])));
            hid = fmaxf(hid, 0.f);
            a0 = fmaf(hid, w2[u],        a0);
            a1 = fmaf(hid, w2[512+u],    a1);
            a2 = fmaf(hid, w2[1024+u],   a2);
            a3 = fmaf(hid, w2[1536+u],   a3);
        }
    }
    #pragma unroll
    for (int off = 4; off >= 1; off >>= 1) {
        a0 += __shfl_down_sync(0xffffffffu, a0, off, 8);
        a1 += __shfl_down_sync(0xffffffffu, a1, off, 8);
        a2 += __shfl_down_sync(0xffffffffu, a2, off, 8);
        a3 += __shfl_down_sync(0xffffffffu, a3, off, 8);
    }
    if (ui == 0 && m < MT) {
        g_bias_table[m*NH+0] = a0;
        g_bias_table[m*NH+1] = a1;
        g_bias_table[m*NH+2] = a2;
        g_bias_table[m*NH+3] = a3;
    }
}

// ---------------- bias gather + 16*sigmoid - M_h, TRANSPOSED output -----------
// Output layout [h][key][query] so the attention kernel's per-key read of all
// queries' biases is COALESCED (thread == query == fastest dim).
// M_h = scale_h + 16 folded in: shifted logits <= 0, denominator >= exp(-16).
__global__ void bias_gather_kernel(const int* __restrict__ idx, const float* __restrict__ ls)
{
    int i = blockIdx.x * blockDim.x + threadIdx.x;   // over NH*LQ*LQ = 262144
    if (i >= NH * LQ * LQ) return;
    int h  = i >> 16;
    int jk = (i >> 8) & 255;   // key
    int iq = i & 255;          // query (fastest -> coalesced write)
    float mh = expf(fminf(ls[h], 4.60517018598809136804f)) + 16.f;  // scale_h + 16
    float x = g_bias_table[idx[iq * LQ + jk] * NH + h];   // rel_index[(query, key)]
    g_bias[i] = 16.f / (1.f + __expf(-x)) - mh;
}

// ---------------- QKV GEMM (64x128 tile) + fused bias/normalize, f32x2 math ------
__global__ __launch_bounds__(256, 2) void qkv_gemm_kernel(
    const float* __restrict__ A,      // x flattened (131072, 128)
    const float* __restrict__ W,      // qkv_w (384, 128)
    const float* __restrict__ qb,     // (128,)
    const float* __restrict__ vb,     // (128,)
    const float* __restrict__ ls)     // logit_scale (4,)
{
    __shared__ float sm[8448];
    __shared__ float fac[64 * 4];
    float* As = sm;                   // 64 x 36
    float* Ws = sm + 64*36;           // 128 x 36
    const int tid = threadIdx.x;
    const int tmode = blockIdx.y;     // 0 q, 1 k, 2 v
    const int r0 = blockIdx.x * 64;
    const int tr = tid >> 4, tc = tid & 15;

    unsigned long long acc2[4][8];
    #pragma unroll
    for (int r = 0; r < 4; r++)
        #pragma unroll
        for (int i = 0; i < 8; i++) acc2[r][i] = 0ull;

    const float* Wbase = W + tmode * 128 * 128;

    for (int kc = 0; kc < 4; kc++) {
        const int k0 = kc * 32;
        {
            int f = tid;
            #pragma unroll
            for (int rep = 0; rep < 2; rep++, f += 256) {
                int row = f >> 3, c4 = f & 7;
                float4 v = *(const float4*)(A + (size_t)(r0 + row) * CD + k0 + c4 * 4);
                float* d = As + row * 36 + c4 * 4;
                d[0] = v.x; d[1] = v.y; d[2] = v.z; d[3] = v.w;
            }
        }
        {
            int f = tid;
            #pragma unroll
            for (int rep = 0; rep < 4; rep++, f += 256) {
                int row = f >> 3, c4 = f & 7;
                float4 v = *(const float4*)(Wbase + row * CD + k0 + c4 * 4);
                float* d = Ws + row * 36 + c4 * 4;
                d[0] = v.x; d[1] = v.y; d[2] = v.z; d[3] = v.w;
            }
        }
        __syncthreads();
        #pragma unroll
        for (int k4 = 0; k4 < 8; k4++) {
            ulonglong2 a2[4], b2[8];
            #pragma unroll
            for (int r = 0; r < 4; r++)
                a2[r] = *(const ulonglong2*)(As + (tr*4 + r) * 36 + k4 * 4);
            #pragma unroll
            for (int i = 0; i < 8; i++)
                b2[i] = *(const ulonglong2*)(Ws + (tc + 16*i) * 36 + k4 * 4);
            #pragma unroll
            for (int r = 0; r < 4; r++)
                #pragma unroll
                for (int i = 0; i < 8; i++) {
                    acc2[r][i] = f2fma(a2[r].x, b2[i].x, acc2[r][i]);
                    acc2[r][i] = f2fma(a2[r].y, b2[i].y, acc2[r][i]);
                }
        }
        __syncthreads();
    }

    float acc[4][8];
    #pragma unroll
    for (int r = 0; r < 4; r++)
        #pragma unroll
        for (int i = 0; i < 8; i++) {
            float lo, hi;
            f2unpack(acc2[r][i], lo, hi);
            acc[r][i] = lo + hi;
        }

    float* S = sm;   // 64 x 132
    #pragma unroll
    for (int r = 0; r < 4; r++)
        #pragma unroll
        for (int i = 0; i < 8; i++) {
            int col = tc + 16*i;
            float bias = (tmode == 0) ? qb[col] : (tmode == 2) ? vb[col] : 0.f;
            S[(tr*4 + r) * 132 + col] = acc[r][i] + bias;
        }
    __syncthreads();
    {
        int row = tid >> 2, hh = tid & 3;
        float f;
        if (tmode == 2) {
            f = 1.f;
        } else {
            const float* p = S + row * 132 + hh * 32;
            float ss = 0.f;
            #pragma unroll
            for (int d = 0; d < 32; d++) ss = fmaf(p[d], p[d], ss);
            f = 1.f / fmaxf(sqrtf(ss), 1e-12f);
            if (tmode == 0) f *= expf(fminf(ls[hh], 4.60517018598809136804f)); // log(100)
        }
        fac[tid] = f;
    }
    __syncthreads();

    float* out = (tmode == 0) ? g_q : (tmode == 1) ? g_k : g_v;
    #pragma unroll
    for (int r = 0; r < 4; r++) {
        int row = tr*4 + r;
        int gr  = r0 + row;
        int b   = gr >> 8, l = gr & 255;
        #pragma unroll
        for (int i = 0; i < 8; i++) {
            int col = tc + 16*i;
            int hh = col >> 5, d = col & 31;
            out[(size_t)(((b * NH + hh) * LQ) + l) * HD + d] = S[row * 132 + col] * fac[row * 4 + hh];
        }
    }
}

// ---------------- flash-style attention per (window, head) ----------------
// 128 threads/CTA; each thread owns TWO query rows (tid, tid+128).
// Branch-free softmax (bound folded into bias). Bias table is TRANSPOSED
// [h][key][query]: per-key reads are coalesced (thread == query), cutting
// bias L1 wavefronts 32x vs the [h][query][key] layout. Loads are register
// double-buffered one 4-key block ahead.
__global__ __launch_bounds__(128, 3) void attn_kernel()
{
    extern __shared__ float sh[];
    float* ks = sh;                 // 256 x 32
    float* vs = sh + LQ * HD;       // 256 x 32
    const int bh = blockIdx.x;      // b*4 + h
    const int h  = bh & 3;
    const int b  = bh >> 2;
    const float* qg = g_q + (size_t)bh * LQ * HD;
    const float* kg = g_k + (size_t)bh * LQ * HD;
    const float* vg = g_v + (size_t)bh * LQ * HD;
    const int tid = threadIdx.x;

    // stage k and v: 2048 float4 each, 128 threads -> 16 reps
    #pragma unroll
    for (int rep = 0; rep < 16; rep++) {
        int f = tid + rep * 128;            // float4 index
        *(float4*)(ks + (size_t)f * 4) = *(const float4*)(kg + (size_t)f * 4);
        *(float4*)(vs + (size_t)f * 4) = *(const float4*)(vg + (size_t)f * 4);
    }
    // two query rows into packed registers
    unsigned long long q0p[16], q1p[16];
    {
        const unsigned long long* q0g = (const unsigned long long*)(qg + (size_t)tid * HD);
        const unsigned long long* q1g = (const unsigned long long*)(qg + (size_t)(tid + 128) * HD);
        #pragma unroll
        for (int i = 0; i < 16; i++) { q0p[i] = q0g[i]; q1p[i] = q1g[i]; }
    }
    __syncthreads();

    // transposed bias: [h][key][query]; this thread's queries are tid, tid+128
    const float* bp = g_bias + h * (LQ * LQ) + tid;

    float l0 = 0.f, l1 = 0.f;
    unsigned long long acc0[16], acc1[16];
    #pragma unroll
    for (int i = 0; i < 16; i++) { acc0[i] = 0ull; acc1[i] = 0ull; }

    // prefetch bias for key block 0 (coalesced scalar loads)
    float b0w[4], b1w[4];
    #pragma unroll
    for (int t = 0; t < 4; t++) {
        b0w[t] = bp[t * LQ];
        b1w[t] = bp[t * LQ + 128];
    }

    #pragma unroll 1
    for (int j4 = 0; j4 < LQ / 4; j4++) {
        float b0c[4], b1c[4];
        #pragma unroll
        for (int t = 0; t < 4; t++) { b0c[t] = b0w[t]; b1c[t] = b1w[t]; }
        if (j4 + 1 < LQ / 4) {                 // prefetch next block NOW (coalesced)
            const float* nb = bp + (j4 + 1) * 4 * LQ;
            #pragma unroll
            for (int t = 0; t < 4; t++) {
                b0w[t] = nb[t * LQ];
                b1w[t] = nb[t * LQ + 128];
            }
        }
        #pragma unroll
        for (int jj = 0; jj < 4; jj++) {
            int j = j4 * 4 + jj;
            const ulonglong2* krow = (const ulonglong2*)(ks + j * HD);

            unsigned long long sa0 = 0ull, sb0 = 0ull, sa1 = 0ull, sb1 = 0ull;
            #pragma unroll
            for (int i = 0; i < 8; i++) {
                ulonglong2 kk = krow[i];
                sa0 = f2fma(q0p[2*i],   kk.x, sa0);
                sb0 = f2fma(q0p[2*i+1], kk.y, sb0);
                sa1 = f2fma(q1p[2*i],   kk.x, sa1);
                sb1 = f2fma(q1p[2*i+1], kk.y, sb1);
            }
            float x0, y0, x1, y1;
            f2unpack(f2add(sa0, sb0), x0, y0);
            f2unpack(f2add(sa1, sb1), x1, y1);

            float p0 = __expf(x0 + y0 + b0c[jj]);   // arg <= 0: never overflows
            float p1 = __expf(x1 + y1 + b1c[jj]);
            l0 += p0;
            l1 += p1;

            unsigned long long pp0 = f2pack(p0, p0);
            unsigned long long pp1 = f2pack(p1, p1);
            const ulonglong2* vrow = (const ulonglong2*)(vs + j * HD);
            #pragma unroll
            for (int i = 0; i < 8; i++) {
                ulonglong2 vv = vrow[i];
                acc0[2*i]   = f2fma(pp0, vv.x, acc0[2*i]);
                acc0[2*i+1] = f2fma(pp0, vv.y, acc0[2*i+1]);
                acc1[2*i]   = f2fma(pp1, vv.x, acc1[2*i]);
                acc1[2*i+1] = f2fma(pp1, vv.y, acc1[2*i+1]);
            }
        }
    }

    unsigned long long inv0 = f2pack(1.f / l0, 1.f / l0);
    unsigned long long inv1 = f2pack(1.f / l1, 1.f / l1);
    unsigned long long* op0 = (unsigned long long*)(g_att + ((size_t)(b * LQ + tid)) * CD + h * HD);
    unsigned long long* op1 = (unsigned long long*)(g_att + ((size_t)(b * LQ + tid + 128)) * CD + h * HD);
    #pragma unroll
    for (int i = 0; i < 16; i++) {
        op0[i] = f2mul(inv0, acc0[i]);
        op1[i] = f2mul(inv1, acc1[i]);
    }
}

// ---------------- projection GEMM: out = att @ proj_w^T + proj_b, f32x2 math ------
__global__ __launch_bounds__(256, 2) void proj_gemm_kernel(
    const float* __restrict__ W,     // proj_w (128,128)
    const float* __restrict__ pb,    // (128,)
    float* __restrict__ out)
{
    __shared__ float sm[64*36 + 128*36];
    float* As = sm;
    float* Ws = sm + 64*36;
    const int tid = threadIdx.x;
    const int r0 = blockIdx.x * 64;
    const int tr = tid >> 4, tc = tid & 15;
    const float* A = g_att;

    unsigned long long acc2[4][8];
    #pragma unroll
    for (int r = 0; r < 4; r++)
        #pragma unroll
        for (int i = 0; i < 8; i++) acc2[r][i] = 0ull;

    for (int kc = 0; kc < 4; kc++) {
        const int k0 = kc * 32;
        {
            int f = tid;
            #pragma unroll
            for (int rep = 0; rep < 2; rep++, f += 256) {
                int row = f >> 3, c4 = f & 7;
                float4 v = *(const float4*)(A + (size_t)(r0 + row) * CD + k0 + c4 * 4);
                float* d = As + row * 36 + c4 * 4;
                d[0] = v.x; d[1] = v.y; d[2] = v.z; d[3] = v.w;
            }
        }
        {
            int f = tid;
            #pragma unroll
            for (int rep = 0; rep < 4; rep++, f += 256) {
                int row = f >> 3, c4 = f & 7;
                float4 v = *(const float4*)(W + row * CD + k0 + c4 * 4);
                float* d = Ws + row * 36 + c4 * 4;
                d[0] = v.x; d[1] = v.y; d[2] = v.z; d[3] = v.w;
            }
        }
        __syncthreads();
        #pragma unroll
        for (int k4 = 0; k4 < 8; k4++) {
            ulonglong2 a2[4], b2[8];
            #pragma unroll
            for (int r = 0; r < 4; r++)
                a2[r] = *(const ulonglong2*)(As + (tr*4 + r) * 36 + k4 * 4);
            #pragma unroll
            for (int i = 0; i < 8; i++)
                b2[i] = *(const ulonglong2*)(Ws + (tc + 16*i) * 36 + k4 * 4);
            #pragma unroll
            for (int r = 0; r < 4; r++)
                #pragma unroll
                for (int i = 0; i < 8; i++) {
                    acc2[r][i] = f2fma(a2[r].x, b2[i].x, acc2[r][i]);
                    acc2[r][i] = f2fma(a2[r].y, b2[i].y, acc2[r][i]);
                }
        }
        __syncthreads();
    }

    #pragma unroll
    for (int r = 0; r < 4; r++) {
        int gr = r0 + tr*4 + r;
        #pragma unroll
        for (int i = 0; i < 8; i++) {
            int col = tc + 16*i;
            float lo, hi;
            f2unpack(acc2[r][i], lo, hi);
            out[(size_t)gr * CD + col] = lo + hi + pb[col];
        }
    }
}

// ---------------- launch ----------------
extern "C" void kernel_launch(void* const* d_in, const int* in_sizes, int n_in,
                              void* d_out, int out_size)
{
    (void)in_sizes; (void)n_in; (void)out_size;
    const float* x       = (const float*)d_in[0];
    const float* qkv_w   = (const float*)d_in[1];
    const float* q_bias  = (const float*)d_in[2];
    const float* v_bias  = (const float*)d_in[3];
    const float* lscale  = (const float*)d_in[4];
    const float* cpb_w1  = (const float*)d_in[5];
    const float* cpb_b1  = (const float*)d_in[6];
    const float* cpb_w2  = (const float*)d_in[7];
    const float* proj_w  = (const float*)d_in[8];
    const float* proj_b  = (const float*)d_in[9];
    const float* rtable  = (const float*)d_in[10];
    const int*   ridx    = (const int*)d_in[11];
    float* out = (float*)d_out;

    static const int attn_smem = 2 * LQ * HD * 4;   // 65536 bytes
    cudaFuncSetAttribute(attn_kernel, cudaFuncAttributeMaxDynamicSharedMemorySize, attn_smem);

    cpb_kernel<<<(MT + 31) / 32, 256>>>(rtable, cpb_w1, cpb_b1, cpb_w2);
    bias_gather_kernel<<<(NH * LQ * LQ) / 256, 256>>>(ridx, lscale);
    qkv_gemm_kernel<<<dim3((NW * LQ) / 64, 3), 256>>>(x, qkv_w, q_bias, v_bias, lscale);
    attn_kernel<<<NW * NH, 128, attn_smem>>>();
    proj_gemm_kernel<<<(NW * LQ) / 64, 256>>>(proj_w, proj_b, out);
}

// round 11
// speedup vs baseline: 1.3478x; 1.2118x over previous
#include <cuda_runtime.h>
#include <math.h>

#define NW 512      // num windows (B_)
#define LQ 256      // tokens per window (L)
#define CD 128      // channels (C)
#define NH 4        // heads
#define HD 32       // head dim
#define MT 1575     // rel table rows (15*15*7)

// ---------------- packed f32x2 helpers ----------------
__device__ __forceinline__ unsigned long long f2pack(float lo, float hi) {
    unsigned long long r;
    asm("mov.b64 %0, {%1, %2};" : "=l"(r) : "f"(lo), "f"(hi));
    return r;
}
__device__ __forceinline__ void f2unpack(unsigned long long v, float& lo, float& hi) {
    asm("mov.b64 {%0, %1}, %2;" : "=f"(lo), "=f"(hi) : "l"(v));
}
__device__ __forceinline__ unsigned long long f2fma(unsigned long long a,
                                                    unsigned long long b,
                                                    unsigned long long c) {
    unsigned long long d;
    asm("fma.rn.f32x2 %0, %1, %2, %3;" : "=l"(d) : "l"(a), "l"(b), "l"(c));
    return d;
}
__device__ __forceinline__ unsigned long long f2add(unsigned long long a,
                                                    unsigned long long b) {
    unsigned long long d;
    asm("add.rn.f32x2 %0, %1, %2;" : "=l"(d) : "l"(a), "l"(b));
    return d;
}
__device__ __forceinline__ unsigned long long f2mul(unsigned long long a,
                                                    unsigned long long b) {
    unsigned long long d;
    asm("mul.rn.f32x2 %0, %1, %2;" : "=l"(d) : "l"(a), "l"(b));
    return d;
}

// ---------------- tf32 helpers ----------------
__device__ __forceinline__ void tf32_split(float x, float& hi, float& lo) {
    unsigned h;
    asm("cvt.rna.tf32.f32 %0, %1;" : "=r"(h) : "f"(x));
    hi = __uint_as_float(h);
    float r = x - hi;
    unsigned l;
    asm("cvt.rna.tf32.f32 %0, %1;" : "=r"(l) : "f"(r));
    lo = __uint_as_float(l);
}
__device__ __forceinline__ void mma_tf32(float c[4], const unsigned a[4], const unsigned b[2]) {
    asm("mma.sync.aligned.m16n8k8.row.col.f32.tf32.tf32.f32 "
        "{%0,%1,%2,%3}, {%4,%5,%6,%7}, {%8,%9}, {%0,%1,%2,%3};"
        : "+f"(c[0]), "+f"(c[1]), "+f"(c[2]), "+f"(c[3])
        : "r"(a[0]), "r"(a[1]), "r"(a[2]), "r"(a[3]), "r"(b[0]), "r"(b[1]));
}

// ---------------- device scratch ----------------
static __device__ float g_bias_table[MT * NH];                    // (M, H)
static __device__ float g_bias[NH * LQ * LQ];                     // TRANSPOSED: [h][key][query]
static __device__ float g_q[(size_t)NW * NH * LQ * HD];
static __device__ float g_k[(size_t)NW * NH * LQ * HD];
static __device__ float g_v[(size_t)NW * NH * LQ * HD];
static __device__ float g_att[(size_t)NW * LQ * CD];

// ---------------- CPB MLP ----------------
__global__ void cpb_kernel(const float* __restrict__ table, const float* __restrict__ w1,
                           const float* __restrict__ b1, const float* __restrict__ w2)
{
    int t  = threadIdx.x;
    int mi = t >> 3, ui = t & 7;
    int m  = blockIdx.x * 32 + mi;
    float a0 = 0.f, a1 = 0.f, a2 = 0.f, a3 = 0.f;
    if (m < MT) {
        float t0 = table[m*3+0], t1 = table[m*3+1], t2 = table[m*3+2];
        for (int u = ui; u < 512; u += 8) {
            float hid = fmaf(w1[u*3+0], t0, fmaf(w1[u*3+1], t1, fmaf(w1[u*3+2], t2, b1[u])));
            hid = fmaxf(hid, 0.f);
            a0 = fmaf(hid, w2[u],        a0);
            a1 = fmaf(hid, w2[512+u],    a1);
            a2 = fmaf(hid, w2[1024+u],   a2);
            a3 = fmaf(hid, w2[1536+u],   a3);
        }
    }
    #pragma unroll
    for (int off = 4; off >= 1; off >>= 1) {
        a0 += __shfl_down_sync(0xffffffffu, a0, off, 8);
        a1 += __shfl_down_sync(0xffffffffu, a1, off, 8);
        a2 += __shfl_down_sync(0xffffffffu, a2, off, 8);
        a3 += __shfl_down_sync(0xffffffffu, a3, off, 8);
    }
    if (ui == 0 && m < MT) {
        g_bias_table[m*NH+0] = a0;
        g_bias_table[m*NH+1] = a1;
        g_bias_table[m*NH+2] = a2;
        g_bias_table[m*NH+3] = a3;
    }
}

// ---------------- bias gather + 16*sigmoid - M_h, TRANSPOSED output -----------
__global__ void bias_gather_kernel(const int* __restrict__ idx, const float* __restrict__ ls)
{
    int i = blockIdx.x * blockDim.x + threadIdx.x;   // over NH*LQ*LQ = 262144
    if (i >= NH * LQ * LQ) return;
    int h  = i >> 16;
    int jk = (i >> 8) & 255;   // key
    int iq = i & 255;          // query (fastest -> coalesced write)
    float mh = expf(fminf(ls[h], 4.60517018598809136804f)) + 16.f;  // scale_h + 16
    float x = g_bias_table[idx[iq * LQ + jk] * NH + h];
    g_bias[i] = 16.f / (1.f + __expf(-x)) - mh;
}

// ---------------- QKV GEMM via 3xTF32 tensor cores + fused bias/normalize ------
// CTA: 256 thr = 8 warps; tile M=128, N=128, K in 32-chunks.
// Warp w: rows 32*(w>>1) .. +32 (two m16 tiles), cols 64*(w&1) .. +64 (8 n8 tiles).
// hi/lo tf32 split done ONCE at smem staging (two images, stride-36 pad).
__global__ __launch_bounds__(256, 2) void qkv_tc_kernel(
    const float* __restrict__ A,      // x flattened (131072, 128)
    const float* __restrict__ W,      // qkv_w (384, 128)
    const float* __restrict__ qb,
    const float* __restrict__ vb,
    const float* __restrict__ ls)
{
    extern __shared__ float smx[];    // 4 * 128*36 floats = 73728 B
    __shared__ float fac[512];
    float* Ah = smx;
    float* Al = smx + 128*36;
    float* Wh = smx + 2*128*36;
    float* Wl = smx + 3*128*36;
    const int tid  = threadIdx.x;
    const int warp = tid >> 5, lane = tid & 31;
    const int wm = warp >> 1, wn = warp & 1;
    const int grp = lane >> 2, tig = lane & 3;
    const int r0 = blockIdx.x * 128;
    const int tmode = blockIdx.y;     // 0 q, 1 k, 2 v
    const float* Wbase = W + tmode * 128 * 128;

    float c[2][8][4];
    #pragma unroll
    for (int mt = 0; mt < 2; mt++)
        #pragma unroll
        for (int nt = 0; nt < 8; nt++)
            #pragma unroll
            for (int i = 0; i < 4; i++) c[mt][nt][i] = 0.f;

    for (int kc = 0; kc < 4; kc++) {
        const int k0c = kc * 32;
        // stage A chunk 128x32 (1024 float4, 4 reps)
        #pragma unroll
        for (int rep = 0; rep < 4; rep++) {
            int f = tid + rep * 256;
            int row = f >> 3, c4 = f & 7;
            float4 v = *(const float4*)(A + (size_t)(r0 + row) * CD + k0c + c4 * 4);
            float4 h4, l4;
            tf32_split(v.x, h4.x, l4.x); tf32_split(v.y, h4.y, l4.y);
            tf32_split(v.z, h4.z, l4.z); tf32_split(v.w, h4.w, l4.w);
            *(float4*)(Ah + row*36 + c4*4) = h4;
            *(float4*)(Al + row*36 + c4*4) = l4;
        }
        // stage W chunk 128x32
        #pragma unroll
        for (int rep = 0; rep < 4; rep++) {
            int f = tid + rep * 256;
            int row = f >> 3, c4 = f & 7;
            float4 v = *(const float4*)(Wbase + row * CD + k0c + c4 * 4);
            float4 h4, l4;
            tf32_split(v.x, h4.x, l4.x); tf32_split(v.y, h4.y, l4.y);
            tf32_split(v.z, h4.z, l4.z); tf32_split(v.w, h4.w, l4.w);
            *(float4*)(Wh + row*36 + c4*4) = h4;
            *(float4*)(Wl + row*36 + c4*4) = l4;
        }
        __syncthreads();
        #pragma unroll
        for (int ks = 0; ks < 4; ks++) {
            const int k0 = ks * 8;
            unsigned ah[2][4], al[2][4];
            #pragma unroll
            for (int mt = 0; mt < 2; mt++) {
                int rb = wm*32 + mt*16 + grp;
                ah[mt][0] = __float_as_uint(Ah[rb*36 + k0 + tig]);
                ah[mt][1] = __float_as_uint(Ah[(rb+8)*36 + k0 + tig]);
                ah[mt][2] = __float_as_uint(Ah[rb*36 + k0 + tig + 4]);
                ah[mt][3] = __float_as_uint(Ah[(rb+8)*36 + k0 + tig + 4]);
                al[mt][0] = __float_as_uint(Al[rb*36 + k0 + tig]);
                al[mt][1] = __float_as_uint(Al[(rb+8)*36 + k0 + tig]);
                al[mt][2] = __float_as_uint(Al[rb*36 + k0 + tig + 4]);
                al[mt][3] = __float_as_uint(Al[(rb+8)*36 + k0 + tig + 4]);
            }
            #pragma unroll
            for (int nt = 0; nt < 8; nt++) {
                int n = wn*64 + nt*8 + grp;
                unsigned bh[2], bl[2];
                bh[0] = __float_as_uint(Wh[n*36 + k0 + tig]);
                bh[1] = __float_as_uint(Wh[n*36 + k0 + tig + 4]);
                bl[0] = __float_as_uint(Wl[n*36 + k0 + tig]);
                bl[1] = __float_as_uint(Wl[n*36 + k0 + tig + 4]);
                mma_tf32(c[0][nt], ah[0], bh);
                mma_tf32(c[1][nt], ah[1], bh);
                mma_tf32(c[0][nt], ah[0], bl);
                mma_tf32(c[1][nt], ah[1], bl);
                mma_tf32(c[0][nt], al[0], bh);
                mma_tf32(c[1][nt], al[1], bh);
            }
        }
        __syncthreads();
    }

    // epilogue: bias + stash tile in smem (reuses staging memory)
    float* S = smx;   // 128 x 132
    #pragma unroll
    for (int mt = 0; mt < 2; mt++)
        #pragma unroll
        for (int nt = 0; nt < 8; nt++) {
            int r   = wm*32 + mt*16 + grp;
            int col = wn*64 + nt*8 + 2*tig;
            float b0 = 0.f, b1 = 0.f;
            if (tmode == 0)      { b0 = qb[col]; b1 = qb[col+1]; }
            else if (tmode == 2) { b0 = vb[col]; b1 = vb[col+1]; }
            float2 v01 = make_float2(c[mt][nt][0] + b0, c[mt][nt][1] + b1);
            float2 v23 = make_float2(c[mt][nt][2] + b0, c[mt][nt][3] + b1);
            *(float2*)(S + r * 132 + col)       = v01;
            *(float2*)(S + (r + 8) * 132 + col) = v23;
        }
    __syncthreads();
    // per-(row,head) factors
    #pragma unroll
    for (int it = 0; it < 2; it++) {
        int idx = tid + it * 256;
        int row = idx >> 2, hh = idx & 3;
        float f;
        if (tmode == 2) {
            f = 1.f;
        } else {
            const float* p = S + row * 132 + hh * 32;
            float ss = 0.f;
            #pragma unroll
            for (int d = 0; d < 32; d++) ss = fmaf(p[d], p[d], ss);
            f = 1.f / fmaxf(sqrtf(ss), 1e-12f);
            if (tmode == 0) f *= expf(fminf(ls[hh], 4.60517018598809136804f));
        }
        fac[idx] = f;
    }
    __syncthreads();
    // scatter to (B,H,L,hd)
    float* out = (tmode == 0) ? g_q : (tmode == 1) ? g_k : g_v;
    #pragma unroll
    for (int rep = 0; rep < 16; rep++) {
        int f = tid + rep * 256;
        int row = f >> 5, c4 = f & 31;
        int col = c4 * 4;
        int hh = col >> 5, d = col & 31;
        int gr = r0 + row;
        int b = gr >> 8, l = gr & 255;
        float4 v = *(const float4*)(S + row * 132 + col);
        float fc = fac[row * 4 + hh];
        v.x *= fc; v.y *= fc; v.z *= fc; v.w *= fc;
        *(float4*)(out + (size_t)(((b * NH + hh) * LQ) + l) * HD + d) = v;
    }
}

// ---------------- flash-style attention per (window, head) ----------------
__global__ __launch_bounds__(128, 3) void attn_kernel()
{
    extern __shared__ float sh[];
    float* ks = sh;                 // 256 x 32
    float* vs = sh + LQ * HD;       // 256 x 32
    const int bh = blockIdx.x;
    const int h  = bh & 3;
    const int b  = bh >> 2;
    const float* qg = g_q + (size_t)bh * LQ * HD;
    const float* kg = g_k + (size_t)bh * LQ * HD;
    const float* vg = g_v + (size_t)bh * LQ * HD;
    const int tid = threadIdx.x;

    #pragma unroll
    for (int rep = 0; rep < 16; rep++) {
        int f = tid + rep * 128;
        *(float4*)(ks + (size_t)f * 4) = *(const float4*)(kg + (size_t)f * 4);
        *(float4*)(vs + (size_t)f * 4) = *(const float4*)(vg + (size_t)f * 4);
    }
    unsigned long long q0p[16], q1p[16];
    {
        const unsigned long long* q0g = (const unsigned long long*)(qg + (size_t)tid * HD);
        const unsigned long long* q1g = (const unsigned long long*)(qg + (size_t)(tid + 128) * HD);
        #pragma unroll
        for (int i = 0; i < 16; i++) { q0p[i] = q0g[i]; q1p[i] = q1g[i]; }
    }
    __syncthreads();

    const float* bp = g_bias + h * (LQ * LQ) + tid;

    float l0 = 0.f, l1 = 0.f;
    unsigned long long acc0[16], acc1[16];
    #pragma unroll
    for (int i = 0; i < 16; i++) { acc0[i] = 0ull; acc1[i] = 0ull; }

    float b0w[4], b1w[4];
    #pragma unroll
    for (int t = 0; t < 4; t++) {
        b0w[t] = bp[t * LQ];
        b1w[t] = bp[t * LQ + 128];
    }

    #pragma unroll 1
    for (int j4 = 0; j4 < LQ / 4; j4++) {
        float b0c[4], b1c[4];
        #pragma unroll
        for (int t = 0; t < 4; t++) { b0c[t] = b0w[t]; b1c[t] = b1w[t]; }
        if (j4 + 1 < LQ / 4) {
            const float* nb = bp + (j4 + 1) * 4 * LQ;
            #pragma unroll
            for (int t = 0; t < 4; t++) {
                b0w[t] = nb[t * LQ];
                b1w[t] = nb[t * LQ + 128];
            }
        }
        #pragma unroll
        for (int jj = 0; jj < 4; jj++) {
            int j = j4 * 4 + jj;
            const ulonglong2* krow = (const ulonglong2*)(ks + j * HD);

            unsigned long long sa0 = 0ull, sb0 = 0ull, sa1 = 0ull, sb1 = 0ull;
            #pragma unroll
            for (int i = 0; i < 8; i++) {
                ulonglong2 kk = krow[i];
                sa0 = f2fma(q0p[2*i],   kk.x, sa0);
                sb0 = f2fma(q0p[2*i+1], kk.y, sb0);
                sa1 = f2fma(q1p[2*i],   kk.x, sa1);
                sb1 = f2fma(q1p[2*i+1], kk.y, sb1);
            }
            float x0, y0, x1, y1;
            f2unpack(f2add(sa0, sb0), x0, y0);
            f2unpack(f2add(sa1, sb1), x1, y1);

            float p0 = __expf(x0 + y0 + b0c[jj]);
            float p1 = __expf(x1 + y1 + b1c[jj]);
            l0 += p0;
            l1 += p1;

            unsigned long long pp0 = f2pack(p0, p0);
            unsigned long long pp1 = f2pack(p1, p1);
            const ulonglong2* vrow = (const ulonglong2*)(vs + j * HD);
            #pragma unroll
            for (int i = 0; i < 8; i++) {
                ulonglong2 vv = vrow[i];
                acc0[2*i]   = f2fma(pp0, vv.x, acc0[2*i]);
                acc0[2*i+1] = f2fma(pp0, vv.y, acc0[2*i+1]);
                acc1[2*i]   = f2fma(pp1, vv.x, acc1[2*i]);
                acc1[2*i+1] = f2fma(pp1, vv.y, acc1[2*i+1]);
            }
        }
    }

    unsigned long long inv0 = f2pack(1.f / l0, 1.f / l0);
    unsigned long long inv1 = f2pack(1.f / l1, 1.f / l1);
    unsigned long long* op0 = (unsigned long long*)(g_att + ((size_t)(b * LQ + tid)) * CD + h * HD);
    unsigned long long* op1 = (unsigned long long*)(g_att + ((size_t)(b * LQ + tid + 128)) * CD + h * HD);
    #pragma unroll
    for (int i = 0; i < 16; i++) {
        op0[i] = f2mul(inv0, acc0[i]);
        op1[i] = f2mul(inv1, acc1[i]);
    }
}

// ---------------- projection GEMM via 3xTF32 tensor cores ----------------
__global__ __launch_bounds__(256, 2) void proj_tc_kernel(
    const float* __restrict__ W,     // proj_w (128,128)
    const float* __restrict__ pb,
    float* __restrict__ out)
{
    extern __shared__ float smx[];
    float* Ah = smx;
    float* Al = smx + 128*36;
    float* Wh = smx + 2*128*36;
    float* Wl = smx + 3*128*36;
    const int tid  = threadIdx.x;
    const int warp = tid >> 5, lane = tid & 31;
    const int wm = warp >> 1, wn = warp & 1;
    const int grp = lane >> 2, tig = lane & 3;
    const int r0 = blockIdx.x * 128;
    const float* A = g_att;

    float c[2][8][4];
    #pragma unroll
    for (int mt = 0; mt < 2; mt++)
        #pragma unroll
        for (int nt = 0; nt < 8; nt++)
            #pragma unroll
            for (int i = 0; i < 4; i++) c[mt][nt][i] = 0.f;

    for (int kc = 0; kc < 4; kc++) {
        const int k0c = kc * 32;
        #pragma unroll
        for (int rep = 0; rep < 4; rep++) {
            int f = tid + rep * 256;
            int row = f >> 3, c4 = f & 7;
            float4 v = *(const float4*)(A + (size_t)(r0 + row) * CD + k0c + c4 * 4);
            float4 h4, l4;
            tf32_split(v.x, h4.x, l4.x); tf32_split(v.y, h4.y, l4.y);
            tf32_split(v.z, h4.z, l4.z); tf32_split(v.w, h4.w, l4.w);
            *(float4*)(Ah + row*36 + c4*4) = h4;
            *(float4*)(Al + row*36 + c4*4) = l4;
        }
        #pragma unroll
        for (int rep = 0; rep < 4; rep++) {
            int f = tid + rep * 256;
            int row = f >> 3, c4 = f & 7;
            float4 v = *(const float4*)(W + row * CD + k0c + c4 * 4);
            float4 h4, l4;
            tf32_split(v.x, h4.x, l4.x); tf32_split(v.y, h4.y, l4.y);
            tf32_split(v.z, h4.z, l4.z); tf32_split(v.w, h4.w, l4.w);
            *(float4*)(Wh + row*36 + c4*4) = h4;
            *(float4*)(Wl + row*36 + c4*4) = l4;
        }
        __syncthreads();
        #pragma unroll
        for (int ks = 0; ks < 4; ks++) {
            const int k0 = ks * 8;
            unsigned ah[2][4], al[2][4];
            #pragma unroll
            for (int mt = 0; mt < 2; mt++) {
                int rb = wm*32 + mt*16 + grp;
                ah[mt][0] = __float_as_uint(Ah[rb*36 + k0 + tig]);
                ah[mt][1] = __float_as_uint(Ah[(rb+8)*36 + k0 + tig]);
                ah[mt][2] = __float_as_uint(Ah[rb*36 + k0 + tig + 4]);
                ah[mt][3] = __float_as_uint(Ah[(rb+8)*36 + k0 + tig + 4]);
                al[mt][0] = __float_as_uint(Al[rb*36 + k0 + tig]);
                al[mt][1] = __float_as_uint(Al[(rb+8)*36 + k0 + tig]);
                al[mt][2] = __float_as_uint(Al[rb*36 + k0 + tig + 4]);
                al[mt][3] = __float_as_uint(Al[(rb+8)*36 + k0 + tig + 4]);
            }
            #pragma unroll
            for (int nt = 0; nt < 8; nt++) {
                int n = wn*64 + nt*8 + grp;
                unsigned bh[2], bl[2];
                bh[0] = __float_as_uint(Wh[n*36 + k0 + tig]);
                bh[1] = __float_as_uint(Wh[n*36 + k0 + tig + 4]);
                bl[0] = __float_as_uint(Wl[n*36 + k0 + tig]);
                bl[1] = __float_as_uint(Wl[n*36 + k0 + tig + 4]);
                mma_tf32(c[0][nt], ah[0], bh);
                mma_tf32(c[1][nt], ah[1], bh);
                mma_tf32(c[0][nt], ah[0], bl);
                mma_tf32(c[1][nt], ah[1], bl);
                mma_tf32(c[0][nt], al[0], bh);
                mma_tf32(c[1][nt], al[1], bh);
            }
        }
        __syncthreads();
    }

    // epilogue: direct stores with bias
    #pragma unroll
    for (int mt = 0; mt < 2; mt++)
        #pragma unroll
        for (int nt = 0; nt < 8; nt++) {
            int r   = r0 + wm*32 + mt*16 + grp;
            int col = wn*64 + nt*8 + 2*tig;
            float b0 = pb[col], b1 = pb[col+1];
            float2 v01 = make_float2(c[mt][nt][0] + b0, c[mt][nt][1] + b1);
            float2 v23 = make_float2(c[mt][nt][2] + b0, c[mt][nt][3] + b1);
            *(float2*)(out + (size_t)r * CD + col)       = v01;
            *(float2*)(out + (size_t)(r + 8) * CD + col) = v23;
        }
}

// ---------------- launch ----------------
extern "C" void kernel_launch(void* const* d_in, const int* in_sizes, int n_in,
                              void* d_out, int out_size)
{
    (void)in_sizes; (void)n_in; (void)out_size;
    const float* x       = (const float*)d_in[0];
    const float* qkv_w   = (const float*)d_in[1];
    const float* q_bias  = (const float*)d_in[2];
    const float* v_bias  = (const float*)d_in[3];
    const float* lscale  = (const float*)d_in[4];
    const float* cpb_w1  = (const float*)d_in[5];
    const float* cpb_b1  = (const float*)d_in[6];
    const float* cpb_w2  = (const float*)d_in[7];
    const float* proj_w  = (const float*)d_in[8];
    const float* proj_b  = (const float*)d_in[9];
    const float* rtable  = (const float*)d_in[10];
    const int*   ridx    = (const int*)d_in[11];
    float* out = (float*)d_out;

    static const int attn_smem = 2 * LQ * HD * 4;      // 65536 bytes
    static const int tc_smem   = 4 * 128 * 36 * 4;     // 73728 bytes
    cudaFuncSetAttribute(attn_kernel, cudaFuncAttributeMaxDynamicSharedMemorySize, attn_smem);
    cudaFuncSetAttribute(qkv_tc_kernel, cudaFuncAttributeMaxDynamicSharedMemorySize, tc_smem);
    cudaFuncSetAttribute(proj_tc_kernel, cudaFuncAttributeMaxDynamicSharedMemorySize, tc_smem);

    cpb_kernel<<<(MT + 31) / 32, 256>>>(rtable, cpb_w1, cpb_b1, cpb_w2);
    bias_gather_kernel<<<(NH * LQ * LQ) / 256, 256>>>(ridx, lscale);
    qkv_tc_kernel<<<dim3((NW * LQ) / 128, 3), 256, tc_smem>>>(x, qkv_w, q_bias, v_bias, lscale);
    attn_kernel<<<NW * NH, 128, attn_smem>>>();
    proj_tc_kernel<<<(NW * LQ) / 128, 256, tc_smem>>>(proj_w, proj_b, out);
}

// round 12
// speedup vs baseline: 1.5811x; 1.1731x over previous
#include <cuda_runtime.h>
#include <math.h>

#define NW 512      // num windows (B_)
#define LQ 256      // tokens per window (L)
#define CD 128      // channels (C)
#define NH 4        // heads
#define HD 32       // head dim
#define MT 1575     // rel table rows (15*15*7)
#define LOG2E 1.44269504088896340736f

// ---------------- tf32 helpers ----------------
__device__ __forceinline__ void tf32_split(float x, float& hi, float& lo) {
    unsigned h;
    asm("cvt.rna.tf32.f32 %0, %1;" : "=r"(h) : "f"(x));
    hi = __uint_as_float(h);
    float r = x - hi;
    unsigned l;
    asm("cvt.rna.tf32.f32 %0, %1;" : "=r"(l) : "f"(r));
    lo = __uint_as_float(l);
}
__device__ __forceinline__ void tf32_split_u(float x, unsigned& h, unsigned& l) {
    asm("cvt.rna.tf32.f32 %0, %1;" : "=r"(h) : "f"(x));
    float r = x - __uint_as_float(h);
    asm("cvt.rna.tf32.f32 %0, %1;" : "=r"(l) : "f"(r));
}
__device__ __forceinline__ void mma_tf32(float c[4], const unsigned a[4], const unsigned b[2]) {
    asm("mma.sync.aligned.m16n8k8.row.col.f32.tf32.tf32.f32 "
        "{%0,%1,%2,%3}, {%4,%5,%6,%7}, {%8,%9}, {%0,%1,%2,%3};"
        : "+f"(c[0]), "+f"(c[1]), "+f"(c[2]), "+f"(c[3])
        : "r"(a[0]), "r"(a[1]), "r"(a[2]), "r"(a[3]), "r"(b[0]), "r"(b[1]));
}
__device__ __forceinline__ float ex2f(float x) {
    float y;
    asm("ex2.approx.f32 %0, %1;" : "=f"(y) : "f"(x));
    return y;
}

// ---------------- device scratch ----------------
static __device__ float g_bias_table[MT * NH];                    // (M, H)
static __device__ float g_bias[NH * LQ * LQ];                     // log2e*(16sig - M_h), [h][key][query]
static __device__ float g_q[(size_t)NW * NH * LQ * HD];           // normalized * scale * log2e
static __device__ float g_k[(size_t)NW * NH * LQ * HD];
static __device__ float g_v[(size_t)NW * NH * LQ * HD];
static __device__ float g_att[(size_t)NW * LQ * CD];

// ---------------- CPB MLP ----------------
__global__ void cpb_kernel(const float* __restrict__ table, const float* __restrict__ w1,
                           const float* __restrict__ b1, const float* __restrict__ w2)
{
    int t  = threadIdx.x;
    int mi = t >> 3, ui = t & 7;
    int m  = blockIdx.x * 32 + mi;
    float a0 = 0.f, a1 = 0.f, a2 = 0.f, a3 = 0.f;
    if (m < MT) {
        float t0 = table[m*3+0], t1 = table[m*3+1], t2 = table[m*3+2];
        for (int u = ui; u < 512; u += 8) {
            float hid = fmaf(w1[u*3+0], t0, fmaf(w1[u*3+1], t1, fmaf(w1[u*3+2], t2, b1[u])));
            hid = fmaxf(hid, 0.f);
            a0 = fmaf(hid, w2[u],        a0);
            a1 = fmaf(hid, w2[512+u],    a1);
            a2 = fmaf(hid, w2[1024+u],   a2);
            a3 = fmaf(hid, w2[1536+u],   a3);
        }
    }
    #pragma unroll
    for (int off = 4; off >= 1; off >>= 1) {
        a0 += __shfl_down_sync(0xffffffffu, a0, off, 8);
        a1 += __shfl_down_sync(0xffffffffu, a1, off, 8);
        a2 += __shfl_down_sync(0xffffffffu, a2, off, 8);
        a3 += __shfl_down_sync(0xffffffffu, a3, off, 8);
    }
    if (ui == 0 && m < MT) {
        g_bias_table[m*NH+0] = a0;
        g_bias_table[m*NH+1] = a1;
        g_bias_table[m*NH+2] = a2;
        g_bias_table[m*NH+3] = a3;
    }
}

// ---------------- bias gather: log2e * (16*sigmoid - M_h), transposed ----------
__global__ void bias_gather_kernel(const int* __restrict__ idx, const float* __restrict__ ls)
{
    int i = blockIdx.x * blockDim.x + threadIdx.x;   // over NH*LQ*LQ
    if (i >= NH * LQ * LQ) return;
    int h  = i >> 16;
    int jk = (i >> 8) & 255;   // key
    int iq = i & 255;          // query (fastest)
    float mh = expf(fminf(ls[h], 4.60517018598809136804f)) + 16.f;
    float x = g_bias_table[idx[iq * LQ + jk] * NH + h];
    g_bias[i] = (16.f / (1.f + __expf(-x)) - mh) * LOG2E;
}

// ---------------- QKV GEMM via 3xTF32 tensor cores + fused bias/normalize ------
__global__ __launch_bounds__(256, 2) void qkv_tc_kernel(
    const float* __restrict__ A,
    const float* __restrict__ W,
    const float* __restrict__ qb,
    const float* __restrict__ vb,
    const float* __restrict__ ls)
{
    extern __shared__ float smx[];    // 4 * 128*36 floats
    __shared__ float fac[512];
    float* Ah = smx;
    float* Al = smx + 128*36;
    float* Wh = smx + 2*128*36;
    float* Wl = smx + 3*128*36;
    const int tid  = threadIdx.x;
    const int warp = tid >> 5, lane = tid & 31;
    const int wm = warp >> 1, wn = warp & 1;
    const int grp = lane >> 2, tig = lane & 3;
    const int r0 = blockIdx.x * 128;
    const int tmode = blockIdx.y;
    const float* Wbase = W + tmode * 128 * 128;

    float c[2][8][4];
    #pragma unroll
    for (int mt = 0; mt < 2; mt++)
        #pragma unroll
        for (int nt = 0; nt < 8; nt++)
            #pragma unroll
            for (int i = 0; i < 4; i++) c[mt][nt][i] = 0.f;

    for (int kc = 0; kc < 4; kc++) {
        const int k0c = kc * 32;
        #pragma unroll
        for (int rep = 0; rep < 4; rep++) {
            int f = tid + rep * 256;
            int row = f >> 3, c4 = f & 7;
            float4 v = *(const float4*)(A + (size_t)(r0 + row) * CD + k0c + c4 * 4);
            float4 h4, l4;
            tf32_split(v.x, h4.x, l4.x); tf32_split(v.y, h4.y, l4.y);
            tf32_split(v.z, h4.z, l4.z); tf32_split(v.w, h4.w, l4.w);
            *(float4*)(Ah + row*36 + c4*4) = h4;
            *(float4*)(Al + row*36 + c4*4) = l4;
        }
        #pragma unroll
        for (int rep = 0; rep < 4; rep++) {
            int f = tid + rep * 256;
            int row = f >> 3, c4 = f & 7;
            float4 v = *(const float4*)(Wbase + row * CD + k0c + c4 * 4);
            float4 h4, l4;
            tf32_split(v.x, h4.x, l4.x); tf32_split(v.y, h4.y, l4.y);
            tf32_split(v.z, h4.z, l4.z); tf32_split(v.w, h4.w, l4.w);
            *(float4*)(Wh + row*36 + c4*4) = h4;
            *(float4*)(Wl + row*36 + c4*4) = l4;
        }
        __syncthreads();
        #pragma unroll
        for (int ks = 0; ks < 4; ks++) {
            const int k0 = ks * 8;
            unsigned ah[2][4], al[2][4];
            #pragma unroll
            for (int mt = 0; mt < 2; mt++) {
                int rb = wm*32 + mt*16 + grp;
                ah[mt][0] = __float_as_uint(Ah[rb*36 + k0 + tig]);
                ah[mt][1] = __float_as_uint(Ah[(rb+8)*36 + k0 + tig]);
                ah[mt][2] = __float_as_uint(Ah[rb*36 + k0 + tig + 4]);
                ah[mt][3] = __float_as_uint(Ah[(rb+8)*36 + k0 + tig + 4]);
                al[mt][0] = __float_as_uint(Al[rb*36 + k0 + tig]);
                al[mt][1] = __float_as_uint(Al[(rb+8)*36 + k0 + tig]);
                al[mt][2] = __float_as_uint(Al[rb*36 + k0 + tig + 4]);
                al[mt][3] = __float_as_uint(Al[(rb+8)*36 + k0 + tig + 4]);
            }
            #pragma unroll
            for (int nt = 0; nt < 8; nt++) {
                int n = wn*64 + nt*8 + grp;
                unsigned bh[2], bl[2];
                bh[0] = __float_as_uint(Wh[n*36 + k0 + tig]);
                bh[1] = __float_as_uint(Wh[n*36 + k0 + tig + 4]);
                bl[0] = __float_as_uint(Wl[n*36 + k0 + tig]);
                bl[1] = __float_as_uint(Wl[n*36 + k0 + tig + 4]);
                mma_tf32(c[0][nt], ah[0], bh);
                mma_tf32(c[1][nt], ah[1], bh);
                mma_tf32(c[0][nt], ah[0], bl);
                mma_tf32(c[1][nt], ah[1], bl);
                mma_tf32(c[0][nt], al[0], bh);
                mma_tf32(c[1][nt], al[1], bh);
            }
        }
        __syncthreads();
    }

    float* S = smx;   // 128 x 132
    #pragma unroll
    for (int mt = 0; mt < 2; mt++)
        #pragma unroll
        for (int nt = 0; nt < 8; nt++) {
            int r   = wm*32 + mt*16 + grp;
            int col = wn*64 + nt*8 + 2*tig;
            float b0 = 0.f, b1 = 0.f;
            if (tmode == 0)      { b0 = qb[col]; b1 = qb[col+1]; }
            else if (tmode == 2) { b0 = vb[col]; b1 = vb[col+1]; }
            float2 v01 = make_float2(c[mt][nt][0] + b0, c[mt][nt][1] + b1);
            float2 v23 = make_float2(c[mt][nt][2] + b0, c[mt][nt][3] + b1);
            *(float2*)(S + r * 132 + col)       = v01;
            *(float2*)(S + (r + 8) * 132 + col) = v23;
        }
    __syncthreads();
    #pragma unroll
    for (int it = 0; it < 2; it++) {
        int idx = tid + it * 256;
        int row = idx >> 2, hh = idx & 3;
        float f;
        if (tmode == 2) {
            f = 1.f;
        } else {
            const float* p = S + row * 132 + hh * 32;
            float ss = 0.f;
            #pragma unroll
            for (int d = 0; d < 32; d++) ss = fmaf(p[d], p[d], ss);
            f = 1.f / fmaxf(sqrtf(ss), 1e-12f);
            if (tmode == 0) f *= expf(fminf(ls[hh], 4.60517018598809136804f)) * LOG2E;
        }
        fac[idx] = f;
    }
    __syncthreads();
    float* out = (tmode == 0) ? g_q : (tmode == 1) ? g_k : g_v;
    #pragma unroll
    for (int rep = 0; rep < 16; rep++) {
        int f = tid + rep * 256;
        int row = f >> 5, c4 = f & 31;
        int col = c4 * 4;
        int hh = col >> 5, d = col & 31;
        int gr = r0 + row;
        int b = gr >> 8, l = gr & 255;
        float4 v = *(const float4*)(S + row * 132 + col);
        float fc = fac[row * 4 + hh];
        v.x *= fc; v.y *= fc; v.z *= fc; v.w *= fc;
        *(float4*)(out + (size_t)(((b * NH + hh) * LQ) + l) * HD + d) = v;
    }
}

// ---------------- tensor-core attention per (window, head) ----------------
// 256 thr = 8 warps; warp w owns query rows [32w, 32w+32).
// smem: ks = K fp32 [256][36], vt = V^T fp32 [32][260], ps = Q then P [256][36].
// All TF32 mma use 3-term splits (hi*hi + hi*lo + lo*hi).
#define KS_OFF 0
#define VT_OFF 9216
#define PS_OFF 17536
#define ATTN_SMEM ((PS_OFF + 9216) * 4)   // 107008 bytes

__global__ __launch_bounds__(256, 1) void attn_tc_kernel()
{
    extern __shared__ float sh[];
    float* ks = sh + KS_OFF;
    float* vt = sh + VT_OFF;
    float* ps = sh + PS_OFF;
    const int bh = blockIdx.x;
    const int h  = bh & 3;
    const int b  = bh >> 2;
    const float* qg = g_q + (size_t)bh * LQ * HD;
    const float* kg = g_k + (size_t)bh * LQ * HD;
    const float* vg = g_v + (size_t)bh * LQ * HD;
    const int tid  = threadIdx.x;
    const int warp = tid >> 5, lane = tid & 31;
    const int grp  = lane >> 2, tig = lane & 3;

    // stage K [key][d] stride 36, V^T [d][key] stride 260, Q into ps [q][d] stride 36
    #pragma unroll
    for (int rep = 0; rep < 8; rep++) {
        int f = tid + rep * 256;
        int row = f >> 3, c4 = f & 7;
        *(float4*)(ks + row*36 + c4*4) = *(const float4*)(kg + (size_t)f * 4);
        *(float4*)(ps + row*36 + c4*4) = *(const float4*)(qg + (size_t)f * 4);
        float4 v = *(const float4*)(vg + (size_t)f * 4);
        int dg = c4 * 4;
        vt[(dg+0)*260 + row] = v.x;
        vt[(dg+1)*260 + row] = v.y;
        vt[(dg+2)*260 + row] = v.z;
        vt[(dg+3)*260 + row] = v.w;
    }
    __syncthreads();

    // load + split Q fragments (rows owned by this warp)
    unsigned qh[2][4][4], ql[2][4][4];
    #pragma unroll
    for (int mt = 0; mt < 2; mt++) {
        int rb = warp*32 + mt*16 + grp;
        #pragma unroll
        for (int k8 = 0; k8 < 4; k8++) {
            int k0 = k8 * 8;
            tf32_split_u(ps[rb*36     + k0 + tig    ], qh[mt][k8][0], ql[mt][k8][0]);
            tf32_split_u(ps[(rb+8)*36 + k0 + tig    ], qh[mt][k8][1], ql[mt][k8][1]);
            tf32_split_u(ps[rb*36     + k0 + tig + 4], qh[mt][k8][2], ql[mt][k8][2]);
            tf32_split_u(ps[(rb+8)*36 + k0 + tig + 4], qh[mt][k8][3], ql[mt][k8][3]);
        }
    }
    __syncthreads();    // everyone done reading Q from ps before it becomes P

    const float* bb = g_bias + h * (LQ * LQ);

    float o[2][4][4];
    #pragma unroll
    for (int mt = 0; mt < 2; mt++)
        #pragma unroll
        for (int nt = 0; nt < 4; nt++)
            #pragma unroll
            for (int i = 0; i < 4; i++) o[mt][nt][i] = 0.f;
    float lsum[2][2] = {{0.f, 0.f}, {0.f, 0.f}};

    #pragma unroll 1
    for (int kb = 0; kb < 8; kb++) {
        const int kbase = kb * 32;
        // ---- QK^T: S frags for this 32-key block ----
        float cqk[2][4][4];
        #pragma unroll
        for (int mt = 0; mt < 2; mt++)
            #pragma unroll
            for (int nt = 0; nt < 4; nt++)
                #pragma unroll
                for (int i = 0; i < 4; i++) cqk[mt][nt][i] = 0.f;
        #pragma unroll
        for (int k8 = 0; k8 < 4; k8++) {
            int k0 = k8 * 8;
            #pragma unroll
            for (int nt = 0; nt < 4; nt++) {
                int key = kbase + nt*8 + grp;
                unsigned bhf[2], blf[2];
                tf32_split_u(ks[key*36 + k0 + tig    ], bhf[0], blf[0]);
                tf32_split_u(ks[key*36 + k0 + tig + 4], bhf[1], blf[1]);
                mma_tf32(cqk[0][nt], qh[0][k8], bhf);
                mma_tf32(cqk[1][nt], qh[1][k8], bhf);
                mma_tf32(cqk[0][nt], qh[0][k8], blf);
                mma_tf32(cqk[1][nt], qh[1][k8], blf);
                mma_tf32(cqk[0][nt], ql[0][k8], bhf);
                mma_tf32(cqk[1][nt], ql[1][k8], bhf);
            }
        }
        // ---- exp2(S + bias') -> P into ps (warp-private rows), accumulate l ----
        #pragma unroll
        for (int mt = 0; mt < 2; mt++) {
            int rb = warp*32 + mt*16 + grp;
            #pragma unroll
            for (int nt = 0; nt < 4; nt++) {
                int col = kbase + nt*8 + 2*tig;     // global key
                float b00 = bb[col*256 + rb];
                float b01 = bb[(col+1)*256 + rb];
                float b10 = bb[col*256 + rb + 8];
                float b11 = bb[(col+1)*256 + rb + 8];
                float p0 = ex2f(cqk[mt][nt][0] + b00);
                float p1 = ex2f(cqk[mt][nt][1] + b01);
                float p2 = ex2f(cqk[mt][nt][2] + b10);
                float p3 = ex2f(cqk[mt][nt][3] + b11);
                lsum[mt][0] += p0 + p1;
                lsum[mt][1] += p2 + p3;
                int lc = nt*8 + 2*tig;
                *(float2*)(ps + rb*36     + lc) = make_float2(p0, p1);
                *(float2*)(ps + (rb+8)*36 + lc) = make_float2(p2, p3);
            }
        }
        // ---- P · V (no sync needed: ps rows are warp-private) ----
        #pragma unroll
        for (int k8 = 0; k8 < 4; k8++) {
            int k0 = k8 * 8;
            unsigned pah[2][4], pal[2][4];
            #pragma unroll
            for (int mt = 0; mt < 2; mt++) {
                int rb = warp*32 + mt*16 + grp;
                tf32_split_u(ps[rb*36     + k0 + tig    ], pah[mt][0], pal[mt][0]);
                tf32_split_u(ps[(rb+8)*36 + k0 + tig    ], pah[mt][1], pal[mt][1]);
                tf32_split_u(ps[rb*36     + k0 + tig + 4], pah[mt][2], pal[mt][2]);
                tf32_split_u(ps[(rb+8)*36 + k0 + tig + 4], pah[mt][3], pal[mt][3]);
            }
            #pragma unroll
            for (int nt = 0; nt < 4; nt++) {
                int d = nt*8 + grp;
                unsigned vbh[2], vbl[2];
                tf32_split_u(vt[d*260 + kbase + k0 + tig    ], vbh[0], vbl[0]);
                tf32_split_u(vt[d*260 + kbase + k0 + tig + 4], vbh[1], vbl[1]);
                mma_tf32(o[0][nt], pah[0], vbh);
                mma_tf32(o[1][nt], pah[1], vbh);
                mma_tf32(o[0][nt], pah[0], vbl);
                mma_tf32(o[1][nt], pah[1], vbl);
                mma_tf32(o[0][nt], pal[0], vbh);
                mma_tf32(o[1][nt], pal[1], vbh);
            }
        }
    }

    // ---- epilogue: reduce l across tig lanes, scale, store ----
    #pragma unroll
    for (int mt = 0; mt < 2; mt++)
        #pragma unroll
        for (int j = 0; j < 2; j++) {
            lsum[mt][j] += __shfl_xor_sync(0xffffffffu, lsum[mt][j], 1);
            lsum[mt][j] += __shfl_xor_sync(0xffffffffu, lsum[mt][j], 2);
        }
    #pragma unroll
    for (int mt = 0; mt < 2; mt++) {
        int rb = warp*32 + mt*16 + grp;
        float inv0 = 1.f / lsum[mt][0];
        float inv1 = 1.f / lsum[mt][1];
        #pragma unroll
        for (int nt = 0; nt < 4; nt++) {
            int col = h*HD + nt*8 + 2*tig;
            float* o0 = g_att + (size_t)(b*LQ + rb) * CD + col;
            float* o1 = g_att + (size_t)(b*LQ + rb + 8) * CD + col;
            *(float2*)o0 = make_float2(o[mt][nt][0] * inv0, o[mt][nt][1] * inv0);
            *(float2*)o1 = make_float2(o[mt][nt][2] * inv1, o[mt][nt][3] * inv1);
        }
    }
}

// ---------------- projection GEMM via 3xTF32 tensor cores ----------------
__global__ __launch_bounds__(256, 2) void proj_tc_kernel(
    const float* __restrict__ W,
    const float* __restrict__ pb,
    float* __restrict__ out)
{
    extern __shared__ float smx[];
    float* Ah = smx;
    float* Al = smx + 128*36;
    float* Wh = smx + 2*128*36;
    float* Wl = smx + 3*128*36;
    const int tid  = threadIdx.x;
    const int warp = tid >> 5, lane = tid & 31;
    const int wm = warp >> 1, wn = warp & 1;
    const int grp = lane >> 2, tig = lane & 3;
    const int r0 = blockIdx.x * 128;
    const float* A = g_att;

    float c[2][8][4];
    #pragma unroll
    for (int mt = 0; mt < 2; mt++)
        #pragma unroll
        for (int nt = 0; nt < 8; nt++)
            #pragma unroll
            for (int i = 0; i < 4; i++) c[mt][nt][i] = 0.f;

    for (int kc = 0; kc < 4; kc++) {
        const int k0c = kc * 32;
        #pragma unroll
        for (int rep = 0; rep < 4; rep++) {
            int f = tid + rep * 256;
            int row = f >> 3, c4 = f & 7;
            float4 v = *(const float4*)(A + (size_t)(r0 + row) * CD + k0c + c4 * 4);
            float4 h4, l4;
            tf32_split(v.x, h4.x, l4.x); tf32_split(v.y, h4.y, l4.y);
            tf32_split(v.z, h4.z, l4.z); tf32_split(v.w, h4.w, l4.w);
            *(float4*)(Ah + row*36 + c4*4) = h4;
            *(float4*)(Al + row*36 + c4*4) = l4;
        }
        #pragma unroll
        for (int rep = 0; rep < 4; rep++) {
            int f = tid + rep * 256;
            int row = f >> 3, c4 = f & 7;
            float4 v = *(const float4*)(W + row * CD + k0c + c4 * 4);
            float4 h4, l4;
            tf32_split(v.x, h4.x, l4.x); tf32_split(v.y, h4.y, l4.y);
            tf32_split(v.z, h4.z, l4.z); tf32_split(v.w, h4.w, l4.w);
            *(float4*)(Wh + row*36 + c4*4) = h4;
            *(float4*)(Wl + row*36 + c4*4) = l4;
        }
        __syncthreads();
        #pragma unroll
        for (int ks = 0; ks < 4; ks++) {
            const int k0 = ks * 8;
            unsigned ah[2][4], al[2][4];
            #pragma unroll
            for (int mt = 0; mt < 2; mt++) {
                int rb = wm*32 + mt*16 + grp;
                ah[mt][0] = __float_as_uint(Ah[rb*36 + k0 + tig]);
                ah[mt][1] = __float_as_uint(Ah[(rb+8)*36 + k0 + tig]);
                ah[mt][2] = __float_as_uint(Ah[rb*36 + k0 + tig + 4]);
                ah[mt][3] = __float_as_uint(Ah[(rb+8)*36 + k0 + tig + 4]);
                al[mt][0] = __float_as_uint(Al[rb*36 + k0 + tig]);
                al[mt][1] = __float_as_uint(Al[(rb+8)*36 + k0 + tig]);
                al[mt][2] = __float_as_uint(Al[rb*36 + k0 + tig + 4]);
                al[mt][3] = __float_as_uint(Al[(rb+8)*36 + k0 + tig + 4]);
            }
            #pragma unroll
            for (int nt = 0; nt < 8; nt++) {
                int n = wn*64 + nt*8 + grp;
                unsigned bh[2], bl[2];
                bh[0] = __float_as_uint(Wh[n*36 + k0 + tig]);
                bh[1] = __float_as_uint(Wh[n*36 + k0 + tig + 4]);
                bl[0] = __float_as_uint(Wl[n*36 + k0 + tig]);
                bl[1] = __float_as_uint(Wl[n*36 + k0 + tig + 4]);
                mma_tf32(c[0][nt], ah[0], bh);
                mma_tf32(c[1][nt], ah[1], bh);
                mma_tf32(c[0][nt], ah[0], bl);
                mma_tf32(c[1][nt], ah[1], bl);
                mma_tf32(c[0][nt], al[0], bh);
                mma_tf32(c[1][nt], al[1], bh);
            }
        }
        __syncthreads();
    }

    #pragma unroll
    for (int mt = 0; mt < 2; mt++)
        #pragma unroll
        for (int nt = 0; nt < 8; nt++) {
            int r   = r0 + wm*32 + mt*16 + grp;
            int col = wn*64 + nt*8 + 2*tig;
            float b0 = pb[col], b1 = pb[col+1];
            float2 v01 = make_float2(c[mt][nt][0] + b0, c[mt][nt][1] + b1);
            float2 v23 = make_float2(c[mt][nt][2] + b0, c[mt][nt][3] + b1);
            *(float2*)(out + (size_t)r * CD + col)       = v01;
            *(float2*)(out + (size_t)(r + 8) * CD + col) = v23;
        }
}

// ---------------- launch ----------------
extern "C" void kernel_launch(void* const* d_in, const int* in_sizes, int n_in,
                              void* d_out, int out_size)
{
    (void)in_sizes; (void)n_in; (void)out_size;
    const float* x       = (const float*)d_in[0];
    const float* qkv_w   = (const float*)d_in[1];
    const float* q_bias  = (const float*)d_in[2];
    const float* v_bias  = (const float*)d_in[3];
    const float* lscale  = (const float*)d_in[4];
    const float* cpb_w1  = (const float*)d_in[5];
    const float* cpb_b1  = (const float*)d_in[6];
    const float* cpb_w2  = (const float*)d_in[7];
    const float* proj_w  = (const float*)d_in[8];
    const float* proj_b  = (const float*)d_in[9];
    const float* rtable  = (const float*)d_in[10];
    const int*   ridx    = (const int*)d_in[11];
    float* out = (float*)d_out;

    static const int tc_smem = 4 * 128 * 36 * 4;     // 73728 bytes
    cudaFuncSetAttribute(qkv_tc_kernel, cudaFuncAttributeMaxDynamicSharedMemorySize, tc_smem);
    cudaFuncSetAttribute(proj_tc_kernel, cudaFuncAttributeMaxDynamicSharedMemorySize, tc_smem);
    cudaFuncSetAttribute(attn_tc_kernel, cudaFuncAttributeMaxDynamicSharedMemorySize, ATTN_SMEM);

    cpb_kernel<<<(MT + 31) / 32, 256>>>(rtable, cpb_w1, cpb_b1, cpb_w2);
    bias_gather_kernel<<<(NH * LQ * LQ) / 256, 256>>>(ridx, lscale);
    qkv_tc_kernel<<<dim3((NW * LQ) / 128, 3), 256, tc_smem>>>(x, qkv_w, q_bias, v_bias, lscale);
    attn_tc_kernel<<<NW * NH, 256, ATTN_SMEM>>>();
    proj_tc_kernel<<<(NW * LQ) / 128, 256, tc_smem>>>(proj_w, proj_b, out);
}

// round 13
// speedup vs baseline: 1.6169x; 1.0226x over previous
#include <cuda_runtime.h>
#include <math.h>

#define NW 512      // num windows (B_)
#define LQ 256      // tokens per window (L)
#define CD 128      // channels (C)
#define NH 4        // heads
#define HD 32       // head dim
#define MT 1575     // rel table rows (15*15*7)
#define LOG2E 1.44269504088896340736f

// ---------------- tf32 helpers ----------------
__device__ __forceinline__ void tf32_split(float x, float& hi, float& lo) {
    unsigned h;
    asm("cvt.rna.tf32.f32 %0, %1;" : "=r"(h) : "f"(x));
    hi = __uint_as_float(h);
    float r = x - hi;
    unsigned l;
    asm("cvt.rna.tf32.f32 %0, %1;" : "=r"(l) : "f"(r));
    lo = __uint_as_float(l);
}
__device__ __forceinline__ void tf32_split_u(float x, unsigned& h, unsigned& l) {
    asm("cvt.rna.tf32.f32 %0, %1;" : "=r"(h) : "f"(x));
    float r = x - __uint_as_float(h);
    asm("cvt.rna.tf32.f32 %0, %1;" : "=r"(l) : "f"(r));
}
__device__ __forceinline__ void mma_tf32(float c[4], const unsigned a[4], const unsigned b[2]) {
    asm("mma.sync.aligned.m16n8k8.row.col.f32.tf32.tf32.f32 "
        "{%0,%1,%2,%3}, {%4,%5,%6,%7}, {%8,%9}, {%0,%1,%2,%3};"
        : "+f"(c[0]), "+f"(c[1]), "+f"(c[2]), "+f"(c[3])
        : "r"(a[0]), "r"(a[1]), "r"(a[2]), "r"(a[3]), "r"(b[0]), "r"(b[1]));
}
__device__ __forceinline__ float ex2f(float x) {
    float y;
    asm("ex2.approx.f32 %0, %1;" : "=f"(y) : "f"(x));
    return y;
}

// ---------------- device scratch ----------------
static __device__ float g_bias_table[MT * NH];                    // (M, H)
static __device__ float g_bias[NH * LQ * LQ];                     // log2e*(16sig - M_h), [h][key][query]
static __device__ float g_q[(size_t)NW * NH * LQ * HD];           // normalized * scale * log2e
static __device__ float g_k[(size_t)NW * NH * LQ * HD];
static __device__ float g_v[(size_t)NW * NH * LQ * HD];
static __device__ float g_att[(size_t)NW * LQ * CD];

// ---------------- CPB MLP ----------------
__global__ void cpb_kernel(const float* __restrict__ table, const float* __restrict__ w1,
                           const float* __restrict__ b1, const float* __restrict__ w2)
{
    int t  = threadIdx.x;
    int mi = t >> 3, ui = t & 7;
    int m  = blockIdx.x * 32 + mi;
    float a0 = 0.f, a1 = 0.f, a2 = 0.f, a3 = 0.f;
    if (m < MT) {
        float t0 = table[m*3+0], t1 = table[m*3+1], t2 = table[m*3+2];
        for (int u = ui; u < 512; u += 8) {
            float hid = fmaf(w1[u*3+0], t0, fmaf(w1[u*3+1], t1, fmaf(w1[u*3+2], t2, b1[u])));
            hid = fmaxf(hid, 0.f);
            a0 = fmaf(hid, w2[u],        a0);
            a1 = fmaf(hid, w2[512+u],    a1);
            a2 = fmaf(hid, w2[1024+u],   a2);
            a3 = fmaf(hid, w2[1536+u],   a3);
        }
    }
    #pragma unroll
    for (int off = 4; off >= 1; off >>= 1) {
        a0 += __shfl_down_sync(0xffffffffu, a0, off, 8);
        a1 += __shfl_down_sync(0xffffffffu, a1, off, 8);
        a2 += __shfl_down_sync(0xffffffffu, a2, off, 8);
        a3 += __shfl_down_sync(0xffffffffu, a3, off, 8);
    }
    if (ui == 0 && m < MT) {
        g_bias_table[m*NH+0] = a0;
        g_bias_table[m*NH+1] = a1;
        g_bias_table[m*NH+2] = a2;
        g_bias_table[m*NH+3] = a3;
    }
}

// ---------------- bias gather: log2e * (16*sigmoid - M_h), transposed ----------
__global__ void bias_gather_kernel(const int* __restrict__ idx, const float* __restrict__ ls)
{
    int i = blockIdx.x * blockDim.x + threadIdx.x;   // over NH*LQ*LQ
    if (i >= NH * LQ * LQ) return;
    int h  = i >> 16;
    int jk = (i >> 8) & 255;   // key
    int iq = i & 255;          // query (fastest)
    float mh = expf(fminf(ls[h], 4.60517018598809136804f)) + 16.f;
    float x = g_bias_table[idx[iq * LQ + jk] * NH + h];
    g_bias[i] = (16.f / (1.f + __expf(-x)) - mh) * LOG2E;
}

// ---------------- QKV GEMM via 3xTF32 tensor cores + fused bias/normalize ------
__global__ __launch_bounds__(256, 2) void qkv_tc_kernel(
    const float* __restrict__ A,
    const float* __restrict__ W,
    const float* __restrict__ qb,
    const float* __restrict__ vb,
    const float* __restrict__ ls)
{
    extern __shared__ float smx[];    // 4 * 128*36 floats
    __shared__ float fac[512];
    float* Ah = smx;
    float* Al = smx + 128*36;
    float* Wh = smx + 2*128*36;
    float* Wl = smx + 3*128*36;
    const int tid  = threadIdx.x;
    const int warp = tid >> 5, lane = tid & 31;
    const int wm = warp >> 1, wn = warp & 1;
    const int grp = lane >> 2, tig = lane & 3;
    const int r0 = blockIdx.x * 128;
    const int tmode = blockIdx.y;
    const float* Wbase = W + tmode * 128 * 128;

    float c[2][8][4];
    #pragma unroll
    for (int mt = 0; mt < 2; mt++)
        #pragma unroll
        for (int nt = 0; nt < 8; nt++)
            #pragma unroll
            for (int i = 0; i < 4; i++) c[mt][nt][i] = 0.f;

    for (int kc = 0; kc < 4; kc++) {
        const int k0c = kc * 32;
        #pragma unroll
        for (int rep = 0; rep < 4; rep++) {
            int f = tid + rep * 256;
            int row = f >> 3, c4 = f & 7;
            float4 v = *(const float4*)(A + (size_t)(r0 + row) * CD + k0c + c4 * 4);
            float4 h4, l4;
            tf32_split(v.x, h4.x, l4.x); tf32_split(v.y, h4.y, l4.y);
            tf32_split(v.z, h4.z, l4.z); tf32_split(v.w, h4.w, l4.w);
            *(float4*)(Ah + row*36 + c4*4) = h4;
            *(float4*)(Al + row*36 + c4*4) = l4;
        }
        #pragma unroll
        for (int rep = 0; rep < 4; rep++) {
            int f = tid + rep * 256;
            int row = f >> 3, c4 = f & 7;
            float4 v = *(const float4*)(Wbase + row * CD + k0c + c4 * 4);
            float4 h4, l4;
            tf32_split(v.x, h4.x, l4.x); tf32_split(v.y, h4.y, l4.y);
            tf32_split(v.z, h4.z, l4.z); tf32_split(v.w, h4.w, l4.w);
            *(float4*)(Wh + row*36 + c4*4) = h4;
            *(float4*)(Wl + row*36 + c4*4) = l4;
        }
        __syncthreads();
        #pragma unroll
        for (int ks = 0; ks < 4; ks++) {
            const int k0 = ks * 8;
            unsigned ah[2][4], al[2][4];
            #pragma unroll
            for (int mt = 0; mt < 2; mt++) {
                int rb = wm*32 + mt*16 + grp;
                ah[mt][0] = __float_as_uint(Ah[rb*36 + k0 + tig]);
                ah[mt][1] = __float_as_uint(Ah[(rb+8)*36 + k0 + tig]);
                ah[mt][2] = __float_as_uint(Ah[rb*36 + k0 + tig + 4]);
                ah[mt][3] = __float_as_uint(Ah[(rb+8)*36 + k0 + tig + 4]);
                al[mt][0] = __float_as_uint(Al[rb*36 + k0 + tig]);
                al[mt][1] = __float_as_uint(Al[(rb+8)*36 + k0 + tig]);
                al[mt][2] = __float_as_uint(Al[rb*36 + k0 + tig + 4]);
                al[mt][3] = __float_as_uint(Al[(rb+8)*36 + k0 + tig + 4]);
            }
            #pragma unroll
            for (int nt = 0; nt < 8; nt++) {
                int n = wn*64 + nt*8 + grp;
                unsigned bh[2], bl[2];
                bh[0] = __float_as_uint(Wh[n*36 + k0 + tig]);
                bh[1] = __float_as_uint(Wh[n*36 + k0 + tig + 4]);
                bl[0] = __float_as_uint(Wl[n*36 + k0 + tig]);
                bl[1] = __float_as_uint(Wl[n*36 + k0 + tig + 4]);
                mma_tf32(c[0][nt], ah[0], bh);
                mma_tf32(c[1][nt], ah[1], bh);
                mma_tf32(c[0][nt], ah[0], bl);
                mma_tf32(c[1][nt], ah[1], bl);
                mma_tf32(c[0][nt], al[0], bh);
                mma_tf32(c[1][nt], al[1], bh);
            }
        }
        __syncthreads();
    }

    float* S = smx;   // 128 x 132
    #pragma unroll
    for (int mt = 0; mt < 2; mt++)
        #pragma unroll
        for (int nt = 0; nt < 8; nt++) {
            int r   = wm*32 + mt*16 + grp;
            int col = wn*64 + nt*8 + 2*tig;
            float b0 = 0.f, b1 = 0.f;
            if (tmode == 0)      { b0 = qb[col]; b1 = qb[col+1]; }
            else if (tmode == 2) { b0 = vb[col]; b1 = vb[col+1]; }
            float2 v01 = make_float2(c[mt][nt][0] + b0, c[mt][nt][1] + b1);
            float2 v23 = make_float2(c[mt][nt][2] + b0, c[mt][nt][3] + b1);
            *(float2*)(S + r * 132 + col)       = v01;
            *(float2*)(S + (r + 8) * 132 + col) = v23;
        }
    __syncthreads();
    #pragma unroll
    for (int it = 0; it < 2; it++) {
        int idx = tid + it * 256;
        int row = idx >> 2, hh = idx & 3;
        float f;
        if (tmode == 2) {
            f = 1.f;
        } else {
            const float* p = S + row * 132 + hh * 32;
            float ss = 0.f;
            #pragma unroll
            for (int d = 0; d < 32; d++) ss = fmaf(p[d], p[d], ss);
            f = 1.f / fmaxf(sqrtf(ss), 1e-12f);
            if (tmode == 0) f *= expf(fminf(ls[hh], 4.60517018598809136804f)) * LOG2E;
        }
        fac[idx] = f;
    }
    __syncthreads();
    float* out = (tmode == 0) ? g_q : (tmode == 1) ? g_k : g_v;
    #pragma unroll
    for (int rep = 0; rep < 16; rep++) {
        int f = tid + rep * 256;
        int row = f >> 5, c4 = f & 31;
        int col = c4 * 4;
        int hh = col >> 5, d = col & 31;
        int gr = r0 + row;
        int b = gr >> 8, l = gr & 255;
        float4 v = *(const float4*)(S + row * 132 + col);
        float fc = fac[row * 4 + hh];
        v.x *= fc; v.y *= fc; v.z *= fc; v.w *= fc;
        *(float4*)(out + (size_t)(((b * NH + hh) * LQ) + l) * HD + d) = v;
    }
}

// ---------------- tensor-core attention per (window, head) ----------------
// 256 thr = 8 warps; warp w owns query rows [32w, 32w+32).
// K and V are PRE-SPLIT to tf32 hi/lo smem images at staging (split once per
// CTA instead of once per warp) -> inner loop is pure LDS + HMMA.
// Q fragments loaded directly from gmem (one-time). P staged in ps (warp-
// private rows -> no sync in main loop).
#define KSH_OFF 0
#define KSL_OFF 9216
#define VTH_OFF 18432
#define VTL_OFF 26752
#define PS_OFF  35072
#define ATTN_SMEM ((PS_OFF + 9216) * 4)   // 177152 bytes

__global__ __launch_bounds__(256, 1) void attn_tc_kernel()
{
    extern __shared__ float sh[];
    float* ksh = sh + KSH_OFF;   // [256][36]
    float* ksl = sh + KSL_OFF;   // [256][36]
    float* vth = sh + VTH_OFF;   // [32][260]
    float* vtl = sh + VTL_OFF;   // [32][260]
    float* ps  = sh + PS_OFF;    // [256][36] P tile
    const int bh = blockIdx.x;
    const int h  = bh & 3;
    const int b  = bh >> 2;
    const float* qg = g_q + (size_t)bh * LQ * HD;
    const float* kg = g_k + (size_t)bh * LQ * HD;
    const float* vg = g_v + (size_t)bh * LQ * HD;
    const int tid  = threadIdx.x;
    const int warp = tid >> 5, lane = tid & 31;
    const int grp  = lane >> 2, tig = lane & 3;

    // stage K (split hi/lo) and V^T (split hi/lo)
    #pragma unroll
    for (int rep = 0; rep < 8; rep++) {
        int f = tid + rep * 256;
        int row = f >> 3, c4 = f & 7;
        float4 kv = *(const float4*)(kg + (size_t)f * 4);
        float4 kh4, kl4;
        tf32_split(kv.x, kh4.x, kl4.x); tf32_split(kv.y, kh4.y, kl4.y);
        tf32_split(kv.z, kh4.z, kl4.z); tf32_split(kv.w, kh4.w, kl4.w);
        *(float4*)(ksh + row*36 + c4*4) = kh4;
        *(float4*)(ksl + row*36 + c4*4) = kl4;
        float4 vv = *(const float4*)(vg + (size_t)f * 4);
        int dg = c4 * 4;
        float hx, lx;
        tf32_split(vv.x, hx, lx); vth[(dg+0)*260 + row] = hx; vtl[(dg+0)*260 + row] = lx;
        tf32_split(vv.y, hx, lx); vth[(dg+1)*260 + row] = hx; vtl[(dg+1)*260 + row] = lx;
        tf32_split(vv.z, hx, lx); vth[(dg+2)*260 + row] = hx; vtl[(dg+2)*260 + row] = lx;
        tf32_split(vv.w, hx, lx); vth[(dg+3)*260 + row] = hx; vtl[(dg+3)*260 + row] = lx;
    }

    // Q fragments straight from gmem (warp-private rows)
    unsigned qh[2][4][4], ql[2][4][4];
    #pragma unroll
    for (int mt = 0; mt < 2; mt++) {
        int rb = warp*32 + mt*16 + grp;
        #pragma unroll
        for (int k8 = 0; k8 < 4; k8++) {
            int k0 = k8 * 8;
            tf32_split_u(__ldg(qg + rb*HD     + k0 + tig    ), qh[mt][k8][0], ql[mt][k8][0]);
            tf32_split_u(__ldg(qg + (rb+8)*HD + k0 + tig    ), qh[mt][k8][1], ql[mt][k8][1]);
            tf32_split_u(__ldg(qg + rb*HD     + k0 + tig + 4), qh[mt][k8][2], ql[mt][k8][2]);
            tf32_split_u(__ldg(qg + (rb+8)*HD + k0 + tig + 4), qh[mt][k8][3], ql[mt][k8][3]);
        }
    }
    __syncthreads();

    const float* bb = g_bias + h * (LQ * LQ);

    float o[2][4][4];
    #pragma unroll
    for (int mt = 0; mt < 2; mt++)
        #pragma unroll
        for (int nt = 0; nt < 4; nt++)
            #pragma unroll
            for (int i = 0; i < 4; i++) o[mt][nt][i] = 0.f;
    float lsum[2][2] = {{0.f, 0.f}, {0.f, 0.f}};

    #pragma unroll 1
    for (int kb = 0; kb < 8; kb++) {
        const int kbase = kb * 32;
        // ---- QK^T ----
        float cqk[2][4][4];
        #pragma unroll
        for (int mt = 0; mt < 2; mt++)
            #pragma unroll
            for (int nt = 0; nt < 4; nt++)
                #pragma unroll
                for (int i = 0; i < 4; i++) cqk[mt][nt][i] = 0.f;
        #pragma unroll
        for (int k8 = 0; k8 < 4; k8++) {
            int k0 = k8 * 8;
            #pragma unroll
            for (int nt = 0; nt < 4; nt++) {
                int key = kbase + nt*8 + grp;
                unsigned bhf[2], blf[2];
                bhf[0] = __float_as_uint(ksh[key*36 + k0 + tig]);
                bhf[1] = __float_as_uint(ksh[key*36 + k0 + tig + 4]);
                blf[0] = __float_as_uint(ksl[key*36 + k0 + tig]);
                blf[1] = __float_as_uint(ksl[key*36 + k0 + tig + 4]);
                mma_tf32(cqk[0][nt], qh[0][k8], bhf);
                mma_tf32(cqk[1][nt], qh[1][k8], bhf);
                mma_tf32(cqk[0][nt], qh[0][k8], blf);
                mma_tf32(cqk[1][nt], qh[1][k8], blf);
                mma_tf32(cqk[0][nt], ql[0][k8], bhf);
                mma_tf32(cqk[1][nt], ql[1][k8], bhf);
            }
        }
        // ---- exp2(S + bias') -> P into ps, accumulate l ----
        #pragma unroll
        for (int mt = 0; mt < 2; mt++) {
            int rb = warp*32 + mt*16 + grp;
            #pragma unroll
            for (int nt = 0; nt < 4; nt++) {
                int col = kbase + nt*8 + 2*tig;
                float b00 = bb[col*256 + rb];
                float b01 = bb[(col+1)*256 + rb];
                float b10 = bb[col*256 + rb + 8];
                float b11 = bb[(col+1)*256 + rb + 8];
                float p0 = ex2f(cqk[mt][nt][0] + b00);
                float p1 = ex2f(cqk[mt][nt][1] + b01);
                float p2 = ex2f(cqk[mt][nt][2] + b10);
                float p3 = ex2f(cqk[mt][nt][3] + b11);
                lsum[mt][0] += p0 + p1;
                lsum[mt][1] += p2 + p3;
                int lc = nt*8 + 2*tig;
                *(float2*)(ps + rb*36     + lc) = make_float2(p0, p1);
                *(float2*)(ps + (rb+8)*36 + lc) = make_float2(p2, p3);
            }
        }
        // ---- P · V (ps rows warp-private: no sync) ----
        #pragma unroll
        for (int k8 = 0; k8 < 4; k8++) {
            int k0 = k8 * 8;
            unsigned pah[2][4], pal[2][4];
            #pragma unroll
            for (int mt = 0; mt < 2; mt++) {
                int rb = warp*32 + mt*16 + grp;
                tf32_split_u(ps[rb*36     + k0 + tig    ], pah[mt][0], pal[mt][0]);
                tf32_split_u(ps[(rb+8)*36 + k0 + tig    ], pah[mt][1], pal[mt][1]);
                tf32_split_u(ps[rb*36     + k0 + tig + 4], pah[mt][2], pal[mt][2]);
                tf32_split_u(ps[(rb+8)*36 + k0 + tig + 4], pah[mt][3], pal[mt][3]);
            }
            #pragma unroll
            for (int nt = 0; nt < 4; nt++) {
                int d = nt*8 + grp;
                unsigned vbh[2], vbl[2];
                vbh[0] = __float_as_uint(vth[d*260 + kbase + k0 + tig]);
                vbh[1] = __float_as_uint(vth[d*260 + kbase + k0 + tig + 4]);
                vbl[0] = __float_as_uint(vtl[d*260 + kbase + k0 + tig]);
                vbl[1] = __float_as_uint(vtl[d*260 + kbase + k0 + tig + 4]);
                mma_tf32(o[0][nt], pah[0], vbh);
                mma_tf32(o[1][nt], pah[1], vbh);
                mma_tf32(o[0][nt], pah[0], vbl);
                mma_tf32(o[1][nt], pah[1], vbl);
                mma_tf32(o[0][nt], pal[0], vbh);
                mma_tf32(o[1][nt], pal[1], vbh);
            }
        }
    }

    // ---- epilogue ----
    #pragma unroll
    for (int mt = 0; mt < 2; mt++)
        #pragma unroll
        for (int j = 0; j < 2; j++) {
            lsum[mt][j] += __shfl_xor_sync(0xffffffffu, lsum[mt][j], 1);
            lsum[mt][j] += __shfl_xor_sync(0xffffffffu, lsum[mt][j], 2);
        }
    #pragma unroll
    for (int mt = 0; mt < 2; mt++) {
        int rb = warp*32 + mt*16 + grp;
        float inv0 = 1.f / lsum[mt][0];
        float inv1 = 1.f / lsum[mt][1];
        #pragma unroll
        for (int nt = 0; nt < 4; nt++) {
            int col = h*HD + nt*8 + 2*tig;
            float* o0 = g_att + (size_t)(b*LQ + rb) * CD + col;
            float* o1 = g_att + (size_t)(b*LQ + rb + 8) * CD + col;
            *(float2*)o0 = make_float2(o[mt][nt][0] * inv0, o[mt][nt][1] * inv0);
            *(float2*)o1 = make_float2(o[mt][nt][2] * inv1, o[mt][nt][3] * inv1);
        }
    }
}

// ---------------- projection GEMM via 3xTF32 tensor cores ----------------
__global__ __launch_bounds__(256, 2) void proj_tc_kernel(
    const float* __restrict__ W,
    const float* __restrict__ pb,
    float* __restrict__ out)
{
    extern __shared__ float smx[];
    float* Ah = smx;
    float* Al = smx + 128*36;
    float* Wh = smx + 2*128*36;
    float* Wl = smx + 3*128*36;
    const int tid  = threadIdx.x;
    const int warp = tid >> 5, lane = tid & 31;
    const int wm = warp >> 1, wn = warp & 1;
    const int grp = lane >> 2, tig = lane & 3;
    const int r0 = blockIdx.x * 128;
    const float* A = g_att;

    float c[2][8][4];
    #pragma unroll
    for (int mt = 0; mt < 2; mt++)
        #pragma unroll
        for (int nt = 0; nt < 8; nt++)
            #pragma unroll
            for (int i = 0; i < 4; i++) c[mt][nt][i] = 0.f;

    for (int kc = 0; kc < 4; kc++) {
        const int k0c = kc * 32;
        #pragma unroll
        for (int rep = 0; rep < 4; rep++) {
            int f = tid + rep * 256;
            int row = f >> 3, c4 = f & 7;
            float4 v = *(const float4*)(A + (size_t)(r0 + row) * CD + k0c + c4 * 4);
            float4 h4, l4;
            tf32_split(v.x, h4.x, l4.x); tf32_split(v.y, h4.y, l4.y);
            tf32_split(v.z, h4.z, l4.z); tf32_split(v.w, h4.w, l4.w);
            *(float4*)(Ah + row*36 + c4*4) = h4;
            *(float4*)(Al + row*36 + c4*4) = l4;
        }
        #pragma unroll
        for (int rep = 0; rep < 4; rep++) {
            int f = tid + rep * 256;
            int row = f >> 3, c4 = f & 7;
            float4 v = *(const float4*)(W + row * CD + k0c + c4 * 4);
            float4 h4, l4;
            tf32_split(v.x, h4.x, l4.x); tf32_split(v.y, h4.y, l4.y);
            tf32_split(v.z, h4.z, l4.z); tf32_split(v.w, h4.w, l4.w);
            *(float4*)(Wh + row*36 + c4*4) = h4;
            *(float4*)(Wl + row*36 + c4*4) = l4;
        }
        __syncthreads();
        #pragma unroll
        for (int ks = 0; ks < 4; ks++) {
            const int k0 = ks * 8;
            unsigned ah[2][4], al[2][4];
            #pragma unroll
            for (int mt = 0; mt < 2; mt++) {
                int rb = wm*32 + mt*16 + grp;
                ah[mt][0] = __float_as_uint(Ah[rb*36 + k0 + tig]);
                ah[mt][1] = __float_as_uint(Ah[(rb+8)*36 + k0 + tig]);
                ah[mt][2] = __float_as_uint(Ah[rb*36 + k0 + tig + 4]);
                ah[mt][3] = __float_as_uint(Ah[(rb+8)*36 + k0 + tig + 4]);
                al[mt][0] = __float_as_uint(Al[rb*36 + k0 + tig]);
                al[mt][1] = __float_as_uint(Al[(rb+8)*36 + k0 + tig]);
                al[mt][2] = __float_as_uint(Al[rb*36 + k0 + tig + 4]);
                al[mt][3] = __float_as_uint(Al[(rb+8)*36 + k0 + tig + 4]);
            }
            #pragma unroll
            for (int nt = 0; nt < 8; nt++) {
                int n = wn*64 + nt*8 + grp;
                unsigned bh[2], bl[2];
                bh[0] = __float_as_uint(Wh[n*36 + k0 + tig]);
                bh[1] = __float_as_uint(Wh[n*36 + k0 + tig + 4]);
                bl[0] = __float_as_uint(Wl[n*36 + k0 + tig]);
                bl[1] = __float_as_uint(Wl[n*36 + k0 + tig + 4]);
                mma_tf32(c[0][nt], ah[0], bh);
                mma_tf32(c[1][nt], ah[1], bh);
                mma_tf32(c[0][nt], ah[0], bl);
                mma_tf32(c[1][nt], ah[1], bl);
                mma_tf32(c[0][nt], al[0], bh);
                mma_tf32(c[1][nt], al[1], bh);
            }
        }
        __syncthreads();
    }

    #pragma unroll
    for (int mt = 0; mt < 2; mt++)
        #pragma unroll
        for (int nt = 0; nt < 8; nt++) {
            int r   = r0 + wm*32 + mt*16 + grp;
            int col = wn*64 + nt*8 + 2*tig;
            float b0 = pb[col], b1 = pb[col+1];
            float2 v01 = make_float2(c[mt][nt][0] + b0, c[mt][nt][1] + b1);
            float2 v23 = make_float2(c[mt][nt][2] + b0, c[mt][nt][3] + b1);
            *(float2*)(out + (size_t)r * CD + col)       = v01;
            *(float2*)(out + (size_t)(r + 8) * CD + col) = v23;
        }
}

// ---------------- launch ----------------
extern "C" void kernel_launch(void* const* d_in, const int* in_sizes, int n_in,
                              void* d_out, int out_size)
{
    (void)in_sizes; (void)n_in; (void)out_size;
    const float* x       = (const float*)d_in[0];
    const float* qkv_w   = (const float*)d_in[1];
    const float* q_bias  = (const float*)d_in[2];
    const float* v_bias  = (const float*)d_in[3];
    const float* lscale  = (const float*)d_in[4];
    const float* cpb_w1  = (const float*)d_in[5];
    const float* cpb_b1  = (const float*)d_in[6];
    const float* cpb_w2  = (const float*)d_in[7];
    const float* proj_w  = (const float*)d_in[8];
    const float* proj_b  = (const float*)d_in[9];
    const float* rtable  = (const float*)d_in[10];
    const int*   ridx    = (const int*)d_in[11];
    float* out = (float*)d_out;

    static const int tc_smem = 4 * 128 * 36 * 4;     // 73728 bytes
    cudaFuncSetAttribute(qkv_tc_kernel, cudaFuncAttributeMaxDynamicSharedMemorySize, tc_smem);
    cudaFuncSetAttribute(proj_tc_kernel, cudaFuncAttributeMaxDynamicSharedMemorySize, tc_smem);
    cudaFuncSetAttribute(attn_tc_kernel, cudaFuncAttributeMaxDynamicSharedMemorySize, ATTN_SMEM);

    cpb_kernel<<<(MT + 31) / 32, 256>>>(rtable, cpb_w1, cpb_b1, cpb_w2);
    bias_gather_kernel<<<(NH * LQ * LQ) / 256, 256>>>(ridx, lscale);
    qkv_tc_kernel<<<dim3((NW * LQ) / 128, 3), 256, tc_smem>>>(x, qkv_w, q_bias, v_bias, lscale);
    attn_tc_kernel<<<NW * NH, 256, ATTN_SMEM>>>();
    proj_tc_kernel<<<(NW * LQ) / 128, 256, tc_smem>>>(proj_w, proj_b, out);
}

// round 14
// speedup vs baseline: 1.7992x; 1.1128x over previous
#include <cuda_runtime.h>
#include <cuda_bf16.h>
#include <math.h>

#define NW 512      // num windows (B_)
#define LQ 256      // tokens per window (L)
#define CD 128      // channels (C)
#define NH 4        // heads
#define HD 32       // head dim
#define MT 1575     // rel table rows (15*15*7)
#define LOG2E 1.44269504088896340736f

// ---------------- tf32 helpers (GEMMs) ----------------
__device__ __forceinline__ void tf32_split(float x, float& hi, float& lo) {
    unsigned h;
    asm("cvt.rna.tf32.f32 %0, %1;" : "=r"(h) : "f"(x));
    hi = __uint_as_float(h);
    float r = x - hi;
    unsigned l;
    asm("cvt.rna.tf32.f32 %0, %1;" : "=r"(l) : "f"(r));
    lo = __uint_as_float(l);
}
__device__ __forceinline__ void mma_tf32(float c[4], const unsigned a[4], const unsigned b[2]) {
    asm("mma.sync.aligned.m16n8k8.row.col.f32.tf32.tf32.f32 "
        "{%0,%1,%2,%3}, {%4,%5,%6,%7}, {%8,%9}, {%0,%1,%2,%3};"
        : "+f"(c[0]), "+f"(c[1]), "+f"(c[2]), "+f"(c[3])
        : "r"(a[0]), "r"(a[1]), "r"(a[2]), "r"(a[3]), "r"(b[0]), "r"(b[1]));
}
__device__ __forceinline__ float ex2f(float x) {
    float y;
    asm("ex2.approx.f32 %0, %1;" : "=f"(y) : "f"(x));
    return y;
}

// ---------------- bf16 helpers (attention) ----------------
// split pair (x0,x1) into packed bf16x2 hi and lo (x0 in low half)
__device__ __forceinline__ void bf_split2(float x0, float x1, unsigned& h, unsigned& l) {
    __nv_bfloat16 h0 = __float2bfloat16(x0);
    __nv_bfloat16 h1 = __float2bfloat16(x1);
    float r0 = x0 - __bfloat162float(h0);
    float r1 = x1 - __bfloat162float(h1);
    __nv_bfloat162 hh; hh.x = h0; hh.y = h1;
    __nv_bfloat162 ll; ll.x = __float2bfloat16(r0); ll.y = __float2bfloat16(r1);
    h = *(unsigned*)&hh;
    l = *(unsigned*)&ll;
}
__device__ __forceinline__ void mma_bf16(float c[4], const unsigned a[4], const unsigned b[2]) {
    asm("mma.sync.aligned.m16n8k16.row.col.f32.bf16.bf16.f32 "
        "{%0,%1,%2,%3}, {%4,%5,%6,%7}, {%8,%9}, {%0,%1,%2,%3};"
        : "+f"(c[0]), "+f"(c[1]), "+f"(c[2]), "+f"(c[3])
        : "r"(a[0]), "r"(a[1]), "r"(a[2]), "r"(a[3]), "r"(b[0]), "r"(b[1]));
}

// ---------------- device scratch ----------------
static __device__ float g_bias_table[MT * NH];                    // (M, H)
static __device__ float g_bias[NH * LQ * LQ];                     // log2e*(16sig - M_h), [h][key][query]
static __device__ float g_q[(size_t)NW * NH * LQ * HD];           // normalized * scale * log2e
static __device__ float g_k[(size_t)NW * NH * LQ * HD];
static __device__ float g_v[(size_t)NW * NH * LQ * HD];
static __device__ float g_att[(size_t)NW * LQ * CD];

// ---------------- CPB MLP ----------------
__global__ void cpb_kernel(const float* __restrict__ table, const float* __restrict__ w1,
                           const float* __restrict__ b1, const float* __restrict__ w2)
{
    int t  = threadIdx.x;
    int mi = t >> 3, ui = t & 7;
    int m  = blockIdx.x * 32 + mi;
    float a0 = 0.f, a1 = 0.f, a2 = 0.f, a3 = 0.f;
    if (m < MT) {
        float t0 = table[m*3+0], t1 = table[m*3+1], t2 = table[m*3+2];
        for (int u = ui; u < 512; u += 8) {
            float hid = fmaf(w1[u*3+0], t0, fmaf(w1[u*3+1], t1, fmaf(w1[u*3+2], t2, b1[u])));
            hid = fmaxf(hid, 0.f);
            a0 = fmaf(hid, w2[u],        a0);
            a1 = fmaf(hid, w2[512+u],    a1);
            a2 = fmaf(hid, w2[1024+u],   a2);
            a3 = fmaf(hid, w2[1536+u],   a3);
        }
    }
    #pragma unroll
    for (int off = 4; off >= 1; off >>= 1) {
        a0 += __shfl_down_sync(0xffffffffu, a0, off, 8);
        a1 += __shfl_down_sync(0xffffffffu, a1, off, 8);
        a2 += __shfl_down_sync(0xffffffffu, a2, off, 8);
        a3 += __shfl_down_sync(0xffffffffu, a3, off, 8);
    }
    if (ui == 0 && m < MT) {
        g_bias_table[m*NH+0] = a0;
        g_bias_table[m*NH+1] = a1;
        g_bias_table[m*NH+2] = a2;
        g_bias_table[m*NH+3] = a3;
    }
}

// ---------------- bias gather: log2e * (16*sigmoid - M_h), transposed ----------
__global__ void bias_gather_kernel(const int* __restrict__ idx, const float* __restrict__ ls)
{
    int i = blockIdx.x * blockDim.x + threadIdx.x;   // over NH*LQ*LQ
    if (i >= NH * LQ * LQ) return;
    int h  = i >> 16;
    int jk = (i >> 8) & 255;   // key
    int iq = i & 255;          // query (fastest)
    float mh = expf(fminf(ls[h], 4.60517018598809136804f)) + 16.f;
    float x = g_bias_table[idx[iq * LQ + jk] * NH + h];
    g_bias[i] = (16.f / (1.f + __expf(-x)) - mh) * LOG2E;
}

// ---------------- QKV GEMM via 3xTF32 tensor cores + fused bias/normalize ------
__global__ __launch_bounds__(256, 2) void qkv_tc_kernel(
    const float* __restrict__ A,
    const float* __restrict__ W,
    const float* __restrict__ qb,
    const float* __restrict__ vb,
    const float* __restrict__ ls)
{
    extern __shared__ float smx[];    // 4 * 128*36 floats
    __shared__ float fac[512];
    float* Ah = smx;
    float* Al = smx + 128*36;
    float* Wh = smx + 2*128*36;
    float* Wl = smx + 3*128*36;
    const int tid  = threadIdx.x;
    const int warp = tid >> 5, lane = tid & 31;
    const int wm = warp >> 1, wn = warp & 1;
    const int grp = lane >> 2, tig = lane & 3;
    const int r0 = blockIdx.x * 128;
    const int tmode = blockIdx.y;
    const float* Wbase = W + tmode * 128 * 128;

    float c[2][8][4];
    #pragma unroll
    for (int mt = 0; mt < 2; mt++)
        #pragma unroll
        for (int nt = 0; nt < 8; nt++)
            #pragma unroll
            for (int i = 0; i < 4; i++) c[mt][nt][i] = 0.f;

    for (int kc = 0; kc < 4; kc++) {
        const int k0c = kc * 32;
        #pragma unroll
        for (int rep = 0; rep < 4; rep++) {
            int f = tid + rep * 256;
            int row = f >> 3, c4 = f & 7;
            float4 v = *(const float4*)(A + (size_t)(r0 + row) * CD + k0c + c4 * 4);
            float4 h4, l4;
            tf32_split(v.x, h4.x, l4.x); tf32_split(v.y, h4.y, l4.y);
            tf32_split(v.z, h4.z, l4.z); tf32_split(v.w, h4.w, l4.w);
            *(float4*)(Ah + row*36 + c4*4) = h4;
            *(float4*)(Al + row*36 + c4*4) = l4;
        }
        #pragma unroll
        for (int rep = 0; rep < 4; rep++) {
            int f = tid + rep * 256;
            int row = f >> 3, c4 = f & 7;
            float4 v = *(const float4*)(Wbase + row * CD + k0c + c4 * 4);
            float4 h4, l4;
            tf32_split(v.x, h4.x, l4.x); tf32_split(v.y, h4.y, l4.y);
            tf32_split(v.z, h4.z, l4.z); tf32_split(v.w, h4.w, l4.w);
            *(float4*)(Wh + row*36 + c4*4) = h4;
            *(float4*)(Wl + row*36 + c4*4) = l4;
        }
        __syncthreads();
        #pragma unroll
        for (int ks = 0; ks < 4; ks++) {
            const int k0 = ks * 8;
            unsigned ah[2][4], al[2][4];
            #pragma unroll
            for (int mt = 0; mt < 2; mt++) {
                int rb = wm*32 + mt*16 + grp;
                ah[mt][0] = __float_as_uint(Ah[rb*36 + k0 + tig]);
                ah[mt][1] = __float_as_uint(Ah[(rb+8)*36 + k0 + tig]);
                ah[mt][2] = __float_as_uint(Ah[rb*36 + k0 + tig + 4]);
                ah[mt][3] = __float_as_uint(Ah[(rb+8)*36 + k0 + tig + 4]);
                al[mt][0] = __float_as_uint(Al[rb*36 + k0 + tig]);
                al[mt][1] = __float_as_uint(Al[(rb+8)*36 + k0 + tig]);
                al[mt][2] = __float_as_uint(Al[rb*36 + k0 + tig + 4]);
                al[mt][3] = __float_as_uint(Al[(rb+8)*36 + k0 + tig + 4]);
            }
            #pragma unroll
            for (int nt = 0; nt < 8; nt++) {
                int n = wn*64 + nt*8 + grp;
                unsigned bh[2], bl[2];
                bh[0] = __float_as_uint(Wh[n*36 + k0 + tig]);
                bh[1] = __float_as_uint(Wh[n*36 + k0 + tig + 4]);
                bl[0] = __float_as_uint(Wl[n*36 + k0 + tig]);
                bl[1] = __float_as_uint(Wl[n*36 + k0 + tig + 4]);
                mma_tf32(c[0][nt], ah[0], bh);
                mma_tf32(c[1][nt], ah[1], bh);
                mma_tf32(c[0][nt], ah[0], bl);
                mma_tf32(c[1][nt], ah[1], bl);
                mma_tf32(c[0][nt], al[0], bh);
                mma_tf32(c[1][nt], al[1], bh);
            }
        }
        __syncthreads();
    }

    float* S = smx;   // 128 x 132
    #pragma unroll
    for (int mt = 0; mt < 2; mt++)
        #pragma unroll
        for (int nt = 0; nt < 8; nt++) {
            int r   = wm*32 + mt*16 + grp;
            int col = wn*64 + nt*8 + 2*tig;
            float b0 = 0.f, b1 = 0.f;
            if (tmode == 0)      { b0 = qb[col]; b1 = qb[col+1]; }
            else if (tmode == 2) { b0 = vb[col]; b1 = vb[col+1]; }
            float2 v01 = make_float2(c[mt][nt][0] + b0, c[mt][nt][1] + b1);
            float2 v23 = make_float2(c[mt][nt][2] + b0, c[mt][nt][3] + b1);
            *(float2*)(S + r * 132 + col)       = v01;
            *(float2*)(S + (r + 8) * 132 + col) = v23;
        }
    __syncthreads();
    #pragma unroll
    for (int it = 0; it < 2; it++) {
        int idx = tid + it * 256;
        int row = idx >> 2, hh = idx & 3;
        float f;
        if (tmode == 2) {
            f = 1.f;
        } else {
            const float* p = S + row * 132 + hh * 32;
            float ss = 0.f;
            #pragma unroll
            for (int d = 0; d < 32; d++) ss = fmaf(p[d], p[d], ss);
            f = 1.f / fmaxf(sqrtf(ss), 1e-12f);
            if (tmode == 0) f *= expf(fminf(ls[hh], 4.60517018598809136804f)) * LOG2E;
        }
        fac[idx] = f;
    }
    __syncthreads();
    float* out = (tmode == 0) ? g_q : (tmode == 1) ? g_k : g_v;
    #pragma unroll
    for (int rep = 0; rep < 16; rep++) {
        int f = tid + rep * 256;
        int row = f >> 5, c4 = f & 31;
        int col = c4 * 4;
        int hh = col >> 5, d = col & 31;
        int gr = r0 + row;
        int b = gr >> 8, l = gr & 255;
        float4 v = *(const float4*)(S + row * 132 + col);
        float fc = fac[row * 4 + hh];
        v.x *= fc; v.y *= fc; v.z *= fc; v.w *= fc;
        *(float4*)(out + (size_t)(((b * NH + hh) * LQ) + l) * HD + d) = v;
    }
}

// ---------------- bf16 tensor-core attention per (window, head) ----------------
// 256 thr = 8 warps; warp w owns query rows [32w, 32w+32).
// K, V, P stored as bf16 (hi, lo) pairs -> m16n8k16 mma (half the mma count
// and half the fragment LDS of tf32-k8). 3-term products keep ~1e-4 accuracy.
// smem (u32 units):
//   kh [256][20] (16 used), kl [256][20]      keys x d-pairs
//   vh [32][132] (128 used), vl [32][132]     d x key-pairs
//   pp [256][40] interleaved (hi,lo) pairs    queries x key-pairs
#define KH_OFF 0
#define KL_OFF 5120
#define VH_OFF 10240
#define VL_OFF 14464
#define PP_OFF 18688
#define ATTN_SMEM ((PP_OFF + 10240) * 4)   // 115712 bytes

__global__ __launch_bounds__(256, 1) void attn_tc_kernel()
{
    extern __shared__ unsigned shu[];
    unsigned* khu = shu + KH_OFF;
    unsigned* klu = shu + KL_OFF;
    unsigned* vhu = shu + VH_OFF;
    unsigned* vlu = shu + VL_OFF;
    unsigned* ppu = shu + PP_OFF;
    __nv_bfloat16* vhb = (__nv_bfloat16*)vhu;   // [32][264] halves
    __nv_bfloat16* vlb = (__nv_bfloat16*)vlu;
    const int bh = blockIdx.x;
    const int h  = bh & 3;
    const int b  = bh >> 2;
    const float* qg = g_q + (size_t)bh * LQ * HD;
    const float* kg = g_k + (size_t)bh * LQ * HD;
    const float* vg = g_v + (size_t)bh * LQ * HD;
    const int tid  = threadIdx.x;
    const int warp = tid >> 5, lane = tid & 31;
    const int grp  = lane >> 2, tig = lane & 3;

    // ---- stage K (bf16 hi/lo d-pairs) and V^T (bf16 hi/lo along key) ----
    #pragma unroll
    for (int rep = 0; rep < 8; rep++) {
        int f = tid + rep * 256;
        int row = f >> 3, c4 = f & 7;
        float4 kv = *(const float4*)(kg + (size_t)f * 4);
        unsigned h0, l0, h1, l1;
        bf_split2(kv.x, kv.y, h0, l0);
        bf_split2(kv.z, kv.w, h1, l1);
        khu[row*20 + 2*c4]     = h0;
        khu[row*20 + 2*c4 + 1] = h1;
        klu[row*20 + 2*c4]     = l0;
        klu[row*20 + 2*c4 + 1] = l1;
        float4 vv = *(const float4*)(vg + (size_t)f * 4);
        int dg = c4 * 4;
        {
            __nv_bfloat16 hh0 = __float2bfloat16(vv.x);
            vhb[(dg+0)*264 + row] = hh0;
            vlb[(dg+0)*264 + row] = __float2bfloat16(vv.x - __bfloat162float(hh0));
            __nv_bfloat16 hh1 = __float2bfloat16(vv.y);
            vhb[(dg+1)*264 + row] = hh1;
            vlb[(dg+1)*264 + row] = __float2bfloat16(vv.y - __bfloat162float(hh1));
            __nv_bfloat16 hh2 = __float2bfloat16(vv.z);
            vhb[(dg+2)*264 + row] = hh2;
            vlb[(dg+2)*264 + row] = __float2bfloat16(vv.z - __bfloat162float(hh2));
            __nv_bfloat16 hh3 = __float2bfloat16(vv.w);
            vhb[(dg+3)*264 + row] = hh3;
            vlb[(dg+3)*264 + row] = __float2bfloat16(vv.w - __bfloat162float(hh3));
        }
    }

    // ---- Q fragments from gmem, split to bf16 pairs ----
    unsigned qfh[2][2][4], qfl[2][2][4];   // [mt][s(k16 group)][reg]
    #pragma unroll
    for (int mt = 0; mt < 2; mt++) {
        int rb = warp*32 + mt*16 + grp;
        #pragma unroll
        for (int s = 0; s < 2; s++) {
            int kbq = s*16 + 2*tig;
            float2 q00 = *(const float2*)(qg + (size_t)rb*HD     + kbq);
            float2 q01 = *(const float2*)(qg + (size_t)(rb+8)*HD + kbq);
            float2 q10 = *(const float2*)(qg + (size_t)rb*HD     + kbq + 8);
            float2 q11 = *(const float2*)(qg + (size_t)(rb+8)*HD + kbq + 8);
            bf_split2(q00.x, q00.y, qfh[mt][s][0], qfl[mt][s][0]);
            bf_split2(q01.x, q01.y, qfh[mt][s][1], qfl[mt][s][1]);
            bf_split2(q10.x, q10.y, qfh[mt][s][2], qfl[mt][s][2]);
            bf_split2(q11.x, q11.y, qfh[mt][s][3], qfl[mt][s][3]);
        }
    }
    __syncthreads();

    const float* bb = g_bias + h * (LQ * LQ);

    float o[2][4][4];
    #pragma unroll
    for (int mt = 0; mt < 2; mt++)
        #pragma unroll
        for (int nt = 0; nt < 4; nt++)
            #pragma unroll
            for (int i = 0; i < 4; i++) o[mt][nt][i] = 0.f;
    float lsum[2][2] = {{0.f, 0.f}, {0.f, 0.f}};

    #pragma unroll 1
    for (int kb = 0; kb < 8; kb++) {
        const int kbase = kb * 32;
        // ---- QK^T ----
        float cqk[2][4][4];
        #pragma unroll
        for (int mt = 0; mt < 2; mt++)
            #pragma unroll
            for (int nt = 0; nt < 4; nt++)
                #pragma unroll
                for (int i = 0; i < 4; i++) cqk[mt][nt][i] = 0.f;
        #pragma unroll
        for (int s = 0; s < 2; s++) {
            #pragma unroll
            for (int nt = 0; nt < 4; nt++) {
                int key = kbase + nt*8 + grp;
                unsigned bhf[2], blf[2];
                bhf[0] = khu[key*20 + s*8 + tig];
                bhf[1] = khu[key*20 + s*8 + tig + 4];
                blf[0] = klu[key*20 + s*8 + tig];
                blf[1] = klu[key*20 + s*8 + tig + 4];
                mma_bf16(cqk[0][nt], qfh[0][s], bhf);
                mma_bf16(cqk[1][nt], qfh[1][s], bhf);
                mma_bf16(cqk[0][nt], qfh[0][s], blf);
                mma_bf16(cqk[1][nt], qfh[1][s], blf);
                mma_bf16(cqk[0][nt], qfl[0][s], bhf);
                mma_bf16(cqk[1][nt], qfl[1][s], bhf);
            }
        }
        // ---- exp2(S + bias') -> split P pairs -> pp, accumulate l ----
        #pragma unroll
        for (int mt = 0; mt < 2; mt++) {
            int rb = warp*32 + mt*16 + grp;
            #pragma unroll
            for (int nt = 0; nt < 4; nt++) {
                int col = kbase + nt*8 + 2*tig;
                float b00 = bb[col*256 + rb];
                float b01 = bb[(col+1)*256 + rb];
                float b10 = bb[col*256 + rb + 8];
                float b11 = bb[(col+1)*256 + rb + 8];
                float p0 = ex2f(cqk[mt][nt][0] + b00);
                float p1 = ex2f(cqk[mt][nt][1] + b01);
                float p2 = ex2f(cqk[mt][nt][2] + b10);
                float p3 = ex2f(cqk[mt][nt][3] + b11);
                lsum[mt][0] += p0 + p1;
                lsum[mt][1] += p2 + p3;
                int kp = nt*4 + tig;
                unsigned h01, l01, h23, l23;
                bf_split2(p0, p1, h01, l01);
                bf_split2(p2, p3, h23, l23);
                *(uint2*)(ppu + rb*40     + kp*2) = make_uint2(h01, l01);
                *(uint2*)(ppu + (rb+8)*40 + kp*2) = make_uint2(h23, l23);
            }
        }
        // ---- P · V (pp rows warp-private: no sync) ----
        #pragma unroll
        for (int s = 0; s < 2; s++) {
            unsigned pah[2][4], pal[2][4];
            #pragma unroll
            for (int mt = 0; mt < 2; mt++) {
                int rb = warp*32 + mt*16 + grp;
                uint2 t0 = *(uint2*)(ppu + rb*40     + (s*8 + tig)*2);
                uint2 t1 = *(uint2*)(ppu + (rb+8)*40 + (s*8 + tig)*2);
                uint2 t2 = *(uint2*)(ppu + rb*40     + (s*8 + tig + 4)*2);
                uint2 t3 = *(uint2*)(ppu + (rb+8)*40 + (s*8 + tig + 4)*2);
                pah[mt][0] = t0.x; pal[mt][0] = t0.y;
                pah[mt][1] = t1.x; pal[mt][1] = t1.y;
                pah[mt][2] = t2.x; pal[mt][2] = t2.y;
                pah[mt][3] = t3.x; pal[mt][3] = t3.y;
            }
            #pragma unroll
            for (int nt = 0; nt < 4; nt++) {
                int d = nt*8 + grp;
                int kpb = (kbase >> 1) + s*8 + tig;
                unsigned vbh[2], vbl[2];
                vbh[0] = vhu[d*132 + kpb];
                vbh[1] = vhu[d*132 + kpb + 4];
                vbl[0] = vlu[d*132 + kpb];
                vbl[1] = vlu[d*132 + kpb + 4];
                mma_bf16(o[0][nt], pah[0], vbh);
                mma_bf16(o[1][nt], pah[1], vbh);
                mma_bf16(o[0][nt], pah[0], vbl);
                mma_bf16(o[1][nt], pah[1], vbl);
                mma_bf16(o[0][nt], pal[0], vbh);
                mma_bf16(o[1][nt], pal[1], vbh);
            }
        }
    }

    // ---- epilogue ----
    #pragma unroll
    for (int mt = 0; mt < 2; mt++)
        #pragma unroll
        for (int j = 0; j < 2; j++) {
            lsum[mt][j] += __shfl_xor_sync(0xffffffffu, lsum[mt][j], 1);
            lsum[mt][j] += __shfl_xor_sync(0xffffffffu, lsum[mt][j], 2);
        }
    #pragma unroll
    for (int mt = 0; mt < 2; mt++) {
        int rb = warp*32 + mt*16 + grp;
        float inv0 = 1.f / lsum[mt][0];
        float inv1 = 1.f / lsum[mt][1];
        #pragma unroll
        for (int nt = 0; nt < 4; nt++) {
            int col = h*HD + nt*8 + 2*tig;
            float* o0 = g_att + (size_t)(b*LQ + rb) * CD + col;
            float* o1 = g_att + (size_t)(b*LQ + rb + 8) * CD + col;
            *(float2*)o0 = make_float2(o[mt][nt][0] * inv0, o[mt][nt][1] * inv0);
            *(float2*)o1 = make_float2(o[mt][nt][2] * inv1, o[mt][nt][3] * inv1);
        }
    }
}

// ---------------- projection GEMM via 3xTF32 tensor cores ----------------
__global__ __launch_bounds__(256, 2) void proj_tc_kernel(
    const float* __restrict__ W,
    const float* __restrict__ pb,
    float* __restrict__ out)
{
    extern __shared__ float smx[];
    float* Ah = smx;
    float* Al = smx + 128*36;
    float* Wh = smx + 2*128*36;
    float* Wl = smx + 3*128*36;
    const int tid  = threadIdx.x;
    const int warp = tid >> 5, lane = tid & 31;
    const int wm = warp >> 1, wn = warp & 1;
    const int grp = lane >> 2, tig = lane & 3;
    const int r0 = blockIdx.x * 128;
    const float* A = g_att;

    float c[2][8][4];
    #pragma unroll
    for (int mt = 0; mt < 2; mt++)
        #pragma unroll
        for (int nt = 0; nt < 8; nt++)
            #pragma unroll
            for (int i = 0; i < 4; i++) c[mt][nt][i] = 0.f;

    for (int kc = 0; kc < 4; kc++) {
        const int k0c = kc * 32;
        #pragma unroll
        for (int rep = 0; rep < 4; rep++) {
            int f = tid + rep * 256;
            int row = f >> 3, c4 = f & 7;
            float4 v = *(const float4*)(A + (size_t)(r0 + row) * CD + k0c + c4 * 4);
            float4 h4, l4;
            tf32_split(v.x, h4.x, l4.x); tf32_split(v.y, h4.y, l4.y);
            tf32_split(v.z, h4.z, l4.z); tf32_split(v.w, h4.w, l4.w);
            *(float4*)(Ah + row*36 + c4*4) = h4;
            *(float4*)(Al + row*36 + c4*4) = l4;
        }
        #pragma unroll
        for (int rep = 0; rep < 4; rep++) {
            int f = tid + rep * 256;
            int row = f >> 3, c4 = f & 7;
            float4 v = *(const float4*)(W + row * CD + k0c + c4 * 4);
            float4 h4, l4;
            tf32_split(v.x, h4.x, l4.x); tf32_split(v.y, h4.y, l4.y);
            tf32_split(v.z, h4.z, l4.z); tf32_split(v.w, h4.w, l4.w);
            *(float4*)(Wh + row*36 + c4*4) = h4;
            *(float4*)(Wl + row*36 + c4*4) = l4;
        }
        __syncthreads();
        #pragma unroll
        for (int ks = 0; ks < 4; ks++) {
            const int k0 = ks * 8;
            unsigned ah[2][4], al[2][4];
            #pragma unroll
            for (int mt = 0; mt < 2; mt++) {
                int rb = wm*32 + mt*16 + grp;
                ah[mt][0] = __float_as_uint(Ah[rb*36 + k0 + tig]);
                ah[mt][1] = __float_as_uint(Ah[(rb+8)*36 + k0 + tig]);
                ah[mt][2] = __float_as_uint(Ah[rb*36 + k0 + tig + 4]);
                ah[mt][3] = __float_as_uint(Ah[(rb+8)*36 + k0 + tig + 4]);
                al[mt][0] = __float_as_uint(Al[rb*36 + k0 + tig]);
                al[mt][1] = __float_as_uint(Al[(rb+8)*36 + k0 + tig]);
                al[mt][2] = __float_as_uint(Al[rb*36 + k0 + tig + 4]);
                al[mt][3] = __float_as_uint(Al[(rb+8)*36 + k0 + tig + 4]);
            }
            #pragma unroll
            for (int nt = 0; nt < 8; nt++) {
                int n = wn*64 + nt*8 + grp;
                unsigned bh[2], bl[2];
                bh[0] = __float_as_uint(Wh[n*36 + k0 + tig]);
                bh[1] = __float_as_uint(Wh[n*36 + k0 + tig + 4]);
                bl[0] = __float_as_uint(Wl[n*36 + k0 + tig]);
                bl[1] = __float_as_uint(Wl[n*36 + k0 + tig + 4]);
                mma_tf32(c[0][nt], ah[0], bh);
                mma_tf32(c[1][nt], ah[1], bh);
                mma_tf32(c[0][nt], ah[0], bl);
                mma_tf32(c[1][nt], ah[1], bl);
                mma_tf32(c[0][nt], al[0], bh);
                mma_tf32(c[1][nt], al[1], bh);
            }
        }
        __syncthreads();
    }

    #pragma unroll
    for (int mt = 0; mt < 2; mt++)
        #pragma unroll
        for (int nt = 0; nt < 8; nt++) {
            int r   = r0 + wm*32 + mt*16 + grp;
            int col = wn*64 + nt*8 + 2*tig;
            float b0 = pb[col], b1 = pb[col+1];
            float2 v01 = make_float2(c[mt][nt][0] + b0, c[mt][nt][1] + b1);
            float2 v23 = make_float2(c[mt][nt][2] + b0, c[mt][nt][3] + b1);
            *(float2*)(out + (size_t)r * CD + col)       = v01;
            *(float2*)(out + (size_t)(r + 8) * CD + col) = v23;
        }
}

// ---------------- launch ----------------
extern "C" void kernel_launch(void* const* d_in, const int* in_sizes, int n_in,
                              void* d_out, int out_size)
{
    (void)in_sizes; (void)n_in; (void)out_size;
    const float* x       = (const float*)d_in[0];
    const float* qkv_w   = (const float*)d_in[1];
    const float* q_bias  = (const float*)d_in[2];
    const float* v_bias  = (const float*)d_in[3];
    const float* lscale  = (const float*)d_in[4];
    const float* cpb_w1  = (const float*)d_in[5];
    const float* cpb_b1  = (const float*)d_in[6];
    const float* cpb_w2  = (const float*)d_in[7];
    const float* proj_w  = (const float*)d_in[8];
    const float* proj_b  = (const float*)d_in[9];
    const float* rtable  = (const float*)d_in[10];
    const int*   ridx    = (const int*)d_in[11];
    float* out = (float*)d_out;

    static const int tc_smem = 4 * 128 * 36 * 4;     // 73728 bytes
    cudaFuncSetAttribute(qkv_tc_kernel, cudaFuncAttributeMaxDynamicSharedMemorySize, tc_smem);
    cudaFuncSetAttribute(proj_tc_kernel, cudaFuncAttributeMaxDynamicSharedMemorySize, tc_smem);
    cudaFuncSetAttribute(attn_tc_kernel, cudaFuncAttributeMaxDynamicSharedMemorySize, ATTN_SMEM);

    cpb_kernel<<<(MT + 31) / 32, 256>>>(rtable, cpb_w1, cpb_b1, cpb_w2);
    bias_gather_kernel<<<(NH * LQ * LQ) / 256, 256>>>(ridx, lscale);
    qkv_tc_kernel<<<dim3((NW * LQ) / 128, 3), 256, tc_smem>>>(x, qkv_w, q_bias, v_bias, lscale);
    attn_tc_kernel<<<NW * NH, 256, ATTN_SMEM>>>();
    proj_tc_kernel<<<(NW * LQ) / 128, 256, tc_smem>>>(proj_w, proj_b, out);
}

// round 15
// speedup vs baseline: 2.0000x; 1.1116x over previous
#include <cuda_runtime.h>
#include <cuda_bf16.h>
#include <math.h>

#define NW 512      // num windows (B_)
#define LQ 256      // tokens per window (L)
#define CD 128      // channels (C)
#define NH 4        // heads
#define HD 32       // head dim
#define MT 1575     // rel table rows (15*15*7)
#define LOG2E 1.44269504088896340736f

__device__ __forceinline__ float ex2f(float x) {
    float y;
    asm("ex2.approx.f32 %0, %1;" : "=f"(y) : "f"(x));
    return y;
}

// ---------------- bf16 helpers ----------------
// split pair (x0,x1) into packed bf16x2 hi and lo (x0 in low half)
__device__ __forceinline__ void bf_split2(float x0, float x1, unsigned& h, unsigned& l) {
    __nv_bfloat16 h0 = __float2bfloat16(x0);
    __nv_bfloat16 h1 = __float2bfloat16(x1);
    float r0 = x0 - __bfloat162float(h0);
    float r1 = x1 - __bfloat162float(h1);
    __nv_bfloat162 hh; hh.x = h0; hh.y = h1;
    __nv_bfloat162 ll; ll.x = __float2bfloat16(r0); ll.y = __float2bfloat16(r1);
    h = *(unsigned*)&hh;
    l = *(unsigned*)&ll;
}
__device__ __forceinline__ void mma_bf16(float c[4], const unsigned a[4], const unsigned b[2]) {
    asm("mma.sync.aligned.m16n8k16.row.col.f32.bf16.bf16.f32 "
        "{%0,%1,%2,%3}, {%4,%5,%6,%7}, {%8,%9}, {%0,%1,%2,%3};"
        : "+f"(c[0]), "+f"(c[1]), "+f"(c[2]), "+f"(c[3])
        : "r"(a[0]), "r"(a[1]), "r"(a[2]), "r"(a[3]), "r"(b[0]), "r"(b[1]));
}

// ---------------- device scratch ----------------
static __device__ float g_bias_table[MT * NH];                    // (M, H)
static __device__ float g_bias[NH * LQ * LQ];                     // log2e*(16sig - M_h), [h][key][query]
static __device__ float g_q[(size_t)NW * NH * LQ * HD];           // normalized * scale * log2e
static __device__ float g_k[(size_t)NW * NH * LQ * HD];
static __device__ float g_v[(size_t)NW * NH * LQ * HD];
static __device__ float g_att[(size_t)NW * LQ * CD];

// ---------------- CPB MLP ----------------
__global__ void cpb_kernel(const float* __restrict__ table, const float* __restrict__ w1,
                           const float* __restrict__ b1, const float* __restrict__ w2)
{
    int t  = threadIdx.x;
    int mi = t >> 3, ui = t & 7;
    int m  = blockIdx.x * 32 + mi;
    float a0 = 0.f, a1 = 0.f, a2 = 0.f, a3 = 0.f;
    if (m < MT) {
        float t0 = table[m*3+0], t1 = table[m*3+1], t2 = table[m*3+2];
        for (int u = ui; u < 512; u += 8) {
            float hid = fmaf(w1[u*3+0], t0, fmaf(w1[u*3+1], t1, fmaf(w1[u*3+2], t2, b1[u])));
            hid = fmaxf(hid, 0.f);
            a0 = fmaf(hid, w2[u],        a0);
            a1 = fmaf(hid, w2[512+u],    a1);
            a2 = fmaf(hid, w2[1024+u],   a2);
            a3 = fmaf(hid, w2[1536+u],   a3);
        }
    }
    #pragma unroll
    for (int off = 4; off >= 1; off >>= 1) {
        a0 += __shfl_down_sync(0xffffffffu, a0, off, 8);
        a1 += __shfl_down_sync(0xffffffffu, a1, off, 8);
        a2 += __shfl_down_sync(0xffffffffu, a2, off, 8);
        a3 += __shfl_down_sync(0xffffffffu, a3, off, 8);
    }
    if (ui == 0 && m < MT) {
        g_bias_table[m*NH+0] = a0;
        g_bias_table[m*NH+1] = a1;
        g_bias_table[m*NH+2] = a2;
        g_bias_table[m*NH+3] = a3;
    }
}

// ---------------- bias gather: log2e * (16*sigmoid - M_h), transposed ----------
__global__ void bias_gather_kernel(const int* __restrict__ idx, const float* __restrict__ ls)
{
    int i = blockIdx.x * blockDim.x + threadIdx.x;   // over NH*LQ*LQ
    if (i >= NH * LQ * LQ) return;
    int h  = i >> 16;
    int jk = (i >> 8) & 255;   // key
    int iq = i & 255;          // query (fastest)
    float mh = expf(fminf(ls[h], 4.60517018598809136804f)) + 16.f;
    float x = g_bias_table[idx[iq * LQ + jk] * NH + h];
    g_bias[i] = (16.f / (1.f + __expf(-x)) - mh) * LOG2E;
}

// ---------------- QKV GEMM via 3xbf16-k16 tensor cores + fused bias/normalize --
// CTA 256 thr = 8 warps, tile M=128 x N=128, K in 32-chunks (2 k16 steps).
// A/W staged as bf16 (hi,lo) k-pair images [row][20] u32 (pad-20: conflict-free,
// verified by the attention kernel's K staging).
__global__ __launch_bounds__(256, 2) void qkv_tc_kernel(
    const float* __restrict__ A,
    const float* __restrict__ W,
    const float* __restrict__ qb,
    const float* __restrict__ vb,
    const float* __restrict__ ls)
{
    extern __shared__ unsigned smu[];   // staging: 4*2560 u32 = 40960 B; epilogue: S 128*132 f = 67584 B
    __shared__ float fac[512];
    unsigned* Ahu = smu;                // [128][20]
    unsigned* Alu = smu + 2560;
    unsigned* Whu = smu + 5120;
    unsigned* Wlu = smu + 7680;
    const int tid  = threadIdx.x;
    const int warp = tid >> 5, lane = tid & 31;
    const int wm = warp >> 1, wn = warp & 1;
    const int grp = lane >> 2, tig = lane & 3;
    const int r0 = blockIdx.x * 128;
    const int tmode = blockIdx.y;
    const float* Wbase = W + tmode * 128 * 128;

    float c[2][8][4];
    #pragma unroll
    for (int mt = 0; mt < 2; mt++)
        #pragma unroll
        for (int nt = 0; nt < 8; nt++)
            #pragma unroll
            for (int i = 0; i < 4; i++) c[mt][nt][i] = 0.f;

    for (int kc = 0; kc < 4; kc++) {
        const int k0c = kc * 32;
        #pragma unroll
        for (int rep = 0; rep < 4; rep++) {
            int f = tid + rep * 256;
            int row = f >> 3, c4 = f & 7;
            float4 v = *(const float4*)(A + (size_t)(r0 + row) * CD + k0c + c4 * 4);
            unsigned h0, l0, h1, l1;
            bf_split2(v.x, v.y, h0, l0);
            bf_split2(v.z, v.w, h1, l1);
            Ahu[row*20 + 2*c4]     = h0;
            Ahu[row*20 + 2*c4 + 1] = h1;
            Alu[row*20 + 2*c4]     = l0;
            Alu[row*20 + 2*c4 + 1] = l1;
        }
        #pragma unroll
        for (int rep = 0; rep < 4; rep++) {
            int f = tid + rep * 256;
            int row = f >> 3, c4 = f & 7;
            float4 v = *(const float4*)(Wbase + row * CD + k0c + c4 * 4);
            unsigned h0, l0, h1, l1;
            bf_split2(v.x, v.y, h0, l0);
            bf_split2(v.z, v.w, h1, l1);
            Whu[row*20 + 2*c4]     = h0;
            Whu[row*20 + 2*c4 + 1] = h1;
            Wlu[row*20 + 2*c4]     = l0;
            Wlu[row*20 + 2*c4 + 1] = l1;
        }
        __syncthreads();
        #pragma unroll
        for (int s = 0; s < 2; s++) {
            unsigned ah[2][4], al[2][4];
            #pragma unroll
            for (int mt = 0; mt < 2; mt++) {
                int rb = wm*32 + mt*16 + grp;
                ah[mt][0] = Ahu[rb*20     + s*8 + tig];
                ah[mt][1] = Ahu[(rb+8)*20 + s*8 + tig];
                ah[mt][2] = Ahu[rb*20     + s*8 + tig + 4];
                ah[mt][3] = Ahu[(rb+8)*20 + s*8 + tig + 4];
                al[mt][0] = Alu[rb*20     + s*8 + tig];
                al[mt][1] = Alu[(rb+8)*20 + s*8 + tig];
                al[mt][2] = Alu[rb*20     + s*8 + tig + 4];
                al[mt][3] = Alu[(rb+8)*20 + s*8 + tig + 4];
            }
            #pragma unroll
            for (int nt = 0; nt < 8; nt++) {
                int n = wn*64 + nt*8 + grp;
                unsigned bh[2], bl[2];
                bh[0] = Whu[n*20 + s*8 + tig];
                bh[1] = Whu[n*20 + s*8 + tig + 4];
                bl[0] = Wlu[n*20 + s*8 + tig];
                bl[1] = Wlu[n*20 + s*8 + tig + 4];
                mma_bf16(c[0][nt], ah[0], bh);
                mma_bf16(c[1][nt], ah[1], bh);
                mma_bf16(c[0][nt], ah[0], bl);
                mma_bf16(c[1][nt], ah[1], bl);
                mma_bf16(c[0][nt], al[0], bh);
                mma_bf16(c[1][nt], al[1], bh);
            }
        }
        __syncthreads();
    }

    float* S = (float*)smu;   // 128 x 132
    #pragma unroll
    for (int mt = 0; mt < 2; mt++)
        #pragma unroll
        for (int nt = 0; nt < 8; nt++) {
            int r   = wm*32 + mt*16 + grp;
            int col = wn*64 + nt*8 + 2*tig;
            float b0 = 0.f, b1 = 0.f;
            if (tmode == 0)      { b0 = qb[col]; b1 = qb[col+1]; }
            else if (tmode == 2) { b0 = vb[col]; b1 = vb[col+1]; }
            float2 v01 = make_float2(c[mt][nt][0] + b0, c[mt][nt][1] + b1);
            float2 v23 = make_float2(c[mt][nt][2] + b0, c[mt][nt][3] + b1);
            *(float2*)(S + r * 132 + col)       = v01;
            *(float2*)(S + (r + 8) * 132 + col) = v23;
        }
    __syncthreads();
    #pragma unroll
    for (int it = 0; it < 2; it++) {
        int idx = tid + it * 256;
        int row = idx >> 2, hh = idx & 3;
        float f;
        if (tmode == 2) {
            f = 1.f;
        } else {
            const float* p = S + row * 132 + hh * 32;
            float ss = 0.f;
            #pragma unroll
            for (int d = 0; d < 32; d++) ss = fmaf(p[d], p[d], ss);
            f = 1.f / fmaxf(sqrtf(ss), 1e-12f);
            if (tmode == 0) f *= expf(fminf(ls[hh], 4.60517018598809136804f)) * LOG2E;
        }
        fac[idx] = f;
    }
    __syncthreads();
    float* out = (tmode == 0) ? g_q : (tmode == 1) ? g_k : g_v;
    #pragma unroll
    for (int rep = 0; rep < 16; rep++) {
        int f = tid + rep * 256;
        int row = f >> 5, c4 = f & 31;
        int col = c4 * 4;
        int hh = col >> 5, d = col & 31;
        int gr = r0 + row;
        int b = gr >> 8, l = gr & 255;
        float4 v = *(const float4*)(S + row * 132 + col);
        float fc = fac[row * 4 + hh];
        v.x *= fc; v.y *= fc; v.z *= fc; v.w *= fc;
        *(float4*)(out + (size_t)(((b * NH + hh) * LQ) + l) * HD + d) = v;
    }
}

// ---------------- bf16 tensor-core attention per (window, head) ----------------
#define KH_OFF 0
#define KL_OFF 5120
#define VH_OFF 10240
#define VL_OFF 14464
#define PP_OFF 18688
#define ATTN_SMEM ((PP_OFF + 10240) * 4)   // 115712 bytes

__global__ __launch_bounds__(256, 1) void attn_tc_kernel()
{
    extern __shared__ unsigned shu[];
    unsigned* khu = shu + KH_OFF;
    unsigned* klu = shu + KL_OFF;
    unsigned* vhu = shu + VH_OFF;
    unsigned* vlu = shu + VL_OFF;
    unsigned* ppu = shu + PP_OFF;
    __nv_bfloat16* vhb = (__nv_bfloat16*)vhu;   // [32][264] halves
    __nv_bfloat16* vlb = (__nv_bfloat16*)vlu;
    const int bh = blockIdx.x;
    const int h  = bh & 3;
    const int b  = bh >> 2;
    const float* qg = g_q + (size_t)bh * LQ * HD;
    const float* kg = g_k + (size_t)bh * LQ * HD;
    const float* vg = g_v + (size_t)bh * LQ * HD;
    const int tid  = threadIdx.x;
    const int warp = tid >> 5, lane = tid & 31;
    const int grp  = lane >> 2, tig = lane & 3;

    #pragma unroll
    for (int rep = 0; rep < 8; rep++) {
        int f = tid + rep * 256;
        int row = f >> 3, c4 = f & 7;
        float4 kv = *(const float4*)(kg + (size_t)f * 4);
        unsigned h0, l0, h1, l1;
        bf_split2(kv.x, kv.y, h0, l0);
        bf_split2(kv.z, kv.w, h1, l1);
        khu[row*20 + 2*c4]     = h0;
        khu[row*20 + 2*c4 + 1] = h1;
        klu[row*20 + 2*c4]     = l0;
        klu[row*20 + 2*c4 + 1] = l1;
        float4 vv = *(const float4*)(vg + (size_t)f * 4);
        int dg = c4 * 4;
        {
            __nv_bfloat16 hh0 = __float2bfloat16(vv.x);
            vhb[(dg+0)*264 + row] = hh0;
            vlb[(dg+0)*264 + row] = __float2bfloat16(vv.x - __bfloat162float(hh0));
            __nv_bfloat16 hh1 = __float2bfloat16(vv.y);
            vhb[(dg+1)*264 + row] = hh1;
            vlb[(dg+1)*264 + row] = __float2bfloat16(vv.y - __bfloat162float(hh1));
            __nv_bfloat16 hh2 = __float2bfloat16(vv.z);
            vhb[(dg+2)*264 + row] = hh2;
            vlb[(dg+2)*264 + row] = __float2bfloat16(vv.z - __bfloat162float(hh2));
            __nv_bfloat16 hh3 = __float2bfloat16(vv.w);
            vhb[(dg+3)*264 + row] = hh3;
            vlb[(dg+3)*264 + row] = __float2bfloat16(vv.w - __bfloat162float(hh3));
        }
    }

    unsigned qfh[2][2][4], qfl[2][2][4];
    #pragma unroll
    for (int mt = 0; mt < 2; mt++) {
        int rb = warp*32 + mt*16 + grp;
        #pragma unroll
        for (int s = 0; s < 2; s++) {
            int kbq = s*16 + 2*tig;
            float2 q00 = *(const float2*)(qg + (size_t)rb*HD     + kbq);
            float2 q01 = *(const float2*)(qg + (size_t)(rb+8)*HD + kbq);
            float2 q10 = *(const float2*)(qg + (size_t)rb*HD     + kbq + 8);
            float2 q11 = *(const float2*)(qg + (size_t)(rb+8)*HD + kbq + 8);
            bf_split2(q00.x, q00.y, qfh[mt][s][0], qfl[mt][s][0]);
            bf_split2(q01.x, q01.y, qfh[mt][s][1], qfl[mt][s][1]);
            bf_split2(q10.x, q10.y, qfh[mt][s][2], qfl[mt][s][2]);
            bf_split2(q11.x, q11.y, qfh[mt][s][3], qfl[mt][s][3]);
        }
    }
    __syncthreads();

    const float* bb = g_bias + h * (LQ * LQ);

    float o[2][4][4];
    #pragma unroll
    for (int mt = 0; mt < 2; mt++)
        #pragma unroll
        for (int nt = 0; nt < 4; nt++)
            #pragma unroll
            for (int i = 0; i < 4; i++) o[mt][nt][i] = 0.f;
    float lsum[2][2] = {{0.f, 0.f}, {0.f, 0.f}};

    #pragma unroll 1
    for (int kb = 0; kb < 8; kb++) {
        const int kbase = kb * 32;
        float cqk[2][4][4];
        #pragma unroll
        for (int mt = 0; mt < 2; mt++)
            #pragma unroll
            for (int nt = 0; nt < 4; nt++)
                #pragma unroll
                for (int i = 0; i < 4; i++) cqk[mt][nt][i] = 0.f;
        #pragma unroll
        for (int s = 0; s < 2; s++) {
            #pragma unroll
            for (int nt = 0; nt < 4; nt++) {
                int key = kbase + nt*8 + grp;
                unsigned bhf[2], blf[2];
                bhf[0] = khu[key*20 + s*8 + tig];
                bhf[1] = khu[key*20 + s*8 + tig + 4];
                blf[0] = klu[key*20 + s*8 + tig];
                blf[1] = klu[key*20 + s*8 + tig + 4];
                mma_bf16(cqk[0][nt], qfh[0][s], bhf);
                mma_bf16(cqk[1][nt], qfh[1][s], bhf);
                mma_bf16(cqk[0][nt], qfh[0][s], blf);
                mma_bf16(cqk[1][nt], qfh[1][s], blf);
                mma_bf16(cqk[0][nt], qfl[0][s], bhf);
                mma_bf16(cqk[1][nt], qfl[1][s], bhf);
            }
        }
        #pragma unroll
        for (int mt = 0; mt < 2; mt++) {
            int rb = warp*32 + mt*16 + grp;
            #pragma unroll
            for (int nt = 0; nt < 4; nt++) {
                int col = kbase + nt*8 + 2*tig;
                float b00 = bb[col*256 + rb];
                float b01 = bb[(col+1)*256 + rb];
                float b10 = bb[col*256 + rb + 8];
                float b11 = bb[(col+1)*256 + rb + 8];
                float p0 = ex2f(cqk[mt][nt][0] + b00);
                float p1 = ex2f(cqk[mt][nt][1] + b01);
                float p2 = ex2f(cqk[mt][nt][2] + b10);
                float p3 = ex2f(cqk[mt][nt][3] + b11);
                lsum[mt][0] += p0 + p1;
                lsum[mt][1] += p2 + p3;
                int kp = nt*4 + tig;
                unsigned h01, l01, h23, l23;
                bf_split2(p0, p1, h01, l01);
                bf_split2(p2, p3, h23, l23);
                *(uint2*)(ppu + rb*40     + kp*2) = make_uint2(h01, l01);
                *(uint2*)(ppu + (rb+8)*40 + kp*2) = make_uint2(h23, l23);
            }
        }
        #pragma unroll
        for (int s = 0; s < 2; s++) {
            unsigned pah[2][4], pal[2][4];
            #pragma unroll
            for (int mt = 0; mt < 2; mt++) {
                int rb = warp*32 + mt*16 + grp;
                uint2 t0 = *(uint2*)(ppu + rb*40     + (s*8 + tig)*2);
                uint2 t1 = *(uint2*)(ppu + (rb+8)*40 + (s*8 + tig)*2);
                uint2 t2 = *(uint2*)(ppu + rb*40     + (s*8 + tig + 4)*2);
                uint2 t3 = *(uint2*)(ppu + (rb+8)*40 + (s*8 + tig + 4)*2);
                pah[mt][0] = t0.x; pal[mt][0] = t0.y;
                pah[mt][1] = t1.x; pal[mt][1] = t1.y;
                pah[mt][2] = t2.x; pal[mt][2] = t2.y;
                pah[mt][3] = t3.x; pal[mt][3] = t3.y;
            }
            #pragma unroll
            for (int nt = 0; nt < 4; nt++) {
                int d = nt*8 + grp;
                int kpb = (kbase >> 1) + s*8 + tig;
                unsigned vbh[2], vbl[2];
                vbh[0] = vhu[d*132 + kpb];
                vbh[1] = vhu[d*132 + kpb + 4];
                vbl[0] = vlu[d*132 + kpb];
                vbl[1] = vlu[d*132 + kpb + 4];
                mma_bf16(o[0][nt], pah[0], vbh);
                mma_bf16(o[1][nt], pah[1], vbh);
                mma_bf16(o[0][nt], pah[0], vbl);
                mma_bf16(o[1][nt], pah[1], vbl);
                mma_bf16(o[0][nt], pal[0], vbh);
                mma_bf16(o[1][nt], pal[1], vbh);
            }
        }
    }

    #pragma unroll
    for (int mt = 0; mt < 2; mt++)
        #pragma unroll
        for (int j = 0; j < 2; j++) {
            lsum[mt][j] += __shfl_xor_sync(0xffffffffu, lsum[mt][j], 1);
            lsum[mt][j] += __shfl_xor_sync(0xffffffffu, lsum[mt][j], 2);
        }
    #pragma unroll
    for (int mt = 0; mt < 2; mt++) {
        int rb = warp*32 + mt*16 + grp;
        float inv0 = 1.f / lsum[mt][0];
        float inv1 = 1.f / lsum[mt][1];
        #pragma unroll
        for (int nt = 0; nt < 4; nt++) {
            int col = h*HD + nt*8 + 2*tig;
            float* o0 = g_att + (size_t)(b*LQ + rb) * CD + col;
            float* o1 = g_att + (size_t)(b*LQ + rb + 8) * CD + col;
            *(float2*)o0 = make_float2(o[mt][nt][0] * inv0, o[mt][nt][1] * inv0);
            *(float2*)o1 = make_float2(o[mt][nt][2] * inv1, o[mt][nt][3] * inv1);
        }
    }
}

// ---------------- projection GEMM via 3xbf16-k16 tensor cores ----------------
__global__ __launch_bounds__(256, 2) void proj_tc_kernel(
    const float* __restrict__ W,
    const float* __restrict__ pb,
    float* __restrict__ out)
{
    extern __shared__ unsigned smu[];   // 4*2560 u32 = 40960 B
    unsigned* Ahu = smu;
    unsigned* Alu = smu + 2560;
    unsigned* Whu = smu + 5120;
    unsigned* Wlu = smu + 7680;
    const int tid  = threadIdx.x;
    const int warp = tid >> 5, lane = tid & 31;
    const int wm = warp >> 1, wn = warp & 1;
    const int grp = lane >> 2, tig = lane & 3;
    const int r0 = blockIdx.x * 128;
    const float* A = g_att;

    float c[2][8][4];
    #pragma unroll
    for (int mt = 0; mt < 2; mt++)
        #pragma unroll
        for (int nt = 0; nt < 8; nt++)
            #pragma unroll
            for (int i = 0; i < 4; i++) c[mt][nt][i] = 0.f;

    for (int kc = 0; kc < 4; kc++) {
        const int k0c = kc * 32;
        #pragma unroll
        for (int rep = 0; rep < 4; rep++) {
            int f = tid + rep * 256;
            int row = f >> 3, c4 = f & 7;
            float4 v = *(const float4*)(A + (size_t)(r0 + row) * CD + k0c + c4 * 4);
            unsigned h0, l0, h1, l1;
            bf_split2(v.x, v.y, h0, l0);
            bf_split2(v.z, v.w, h1, l1);
            Ahu[row*20 + 2*c4]     = h0;
            Ahu[row*20 + 2*c4 + 1] = h1;
            Alu[row*20 + 2*c4]     = l0;
            Alu[row*20 + 2*c4 + 1] = l1;
        }
        #pragma unroll
        for (int rep = 0; rep < 4; rep++) {
            int f = tid + rep * 256;
            int row = f >> 3, c4 = f & 7;
            float4 v = *(const float4*)(W + row * CD + k0c + c4 * 4);
            unsigned h0, l0, h1, l1;
            bf_split2(v.x, v.y, h0, l0);
            bf_split2(v.z, v.w, h1, l1);
            Whu[row*20 + 2*c4]     = h0;
            Whu[row*20 + 2*c4 + 1] = h1;
            Wlu[row*20 + 2*c4]     = l0;
            Wlu[row*20 + 2*c4 + 1] = l1;
        }
        __syncthreads();
        #pragma unroll
        for (int s = 0; s < 2; s++) {
            unsigned ah[2][4], al[2][4];
            #pragma unroll
            for (int mt = 0; mt < 2; mt++) {
                int rb = wm*32 + mt*16 + grp;
                ah[mt][0] = Ahu[rb*20     + s*8 + tig];
                ah[mt][1] = Ahu[(rb+8)*20 + s*8 + tig];
                ah[mt][2] = Ahu[rb*20     + s*8 + tig + 4];
                ah[mt][3] = Ahu[(rb+8)*20 + s*8 + tig + 4];
                al[mt][0] = Alu[rb*20     + s*8 + tig];
                al[mt][1] = Alu[(rb+8)*20 + s*8 + tig];
                al[mt][2] = Alu[rb*20     + s*8 + tig + 4];
                al[mt][3] = Alu[(rb+8)*20 + s*8 + tig + 4];
            }
            #pragma unroll
            for (int nt = 0; nt < 8; nt++) {
                int n = wn*64 + nt*8 + grp;
                unsigned bh[2], bl[2];
                bh[0] = Whu[n*20 + s*8 + tig];
                bh[1] = Whu[n*20 + s*8 + tig + 4];
                bl[0] = Wlu[n*20 + s*8 + tig];
                bl[1] = Wlu[n*20 + s*8 + tig + 4];
                mma_bf16(c[0][nt], ah[0], bh);
                mma_bf16(c[1][nt], ah[1], bh);
                mma_bf16(c[0][nt], ah[0], bl);
                mma_bf16(c[1][nt], ah[1], bl);
                mma_bf16(c[0][nt], al[0], bh);
                mma_bf16(c[1][nt], al[1], bh);
            }
        }
        __syncthreads();
    }

    #pragma unroll
    for (int mt = 0; mt < 2; mt++)
        #pragma unroll
        for (int nt = 0; nt < 8; nt++) {
            int r   = r0 + wm*32 + mt*16 + grp;
            int col = wn*64 + nt*8 + 2*tig;
            float b0 = pb[col], b1 = pb[col+1];
            float2 v01 = make_float2(c[mt][nt][0] + b0, c[mt][nt][1] + b1);
            float2 v23 = make_float2(c[mt][nt][2] + b0, c[mt][nt][3] + b1);
            *(float2*)(out + (size_t)r * CD + col)       = v01;
            *(float2*)(out + (size_t)(r + 8) * CD + col) = v23;
        }
}

// ---------------- launch ----------------
extern "C" void kernel_launch(void* const* d_in, const int* in_sizes, int n_in,
                              void* d_out, int out_size)
{
    (void)in_sizes; (void)n_in; (void)out_size;
    const float* x       = (const float*)d_in[0];
    const float* qkv_w   = (const float*)d_in[1];
    const float* q_bias  = (const float*)d_in[2];
    const float* v_bias  = (const float*)d_in[3];
    const float* lscale  = (const float*)d_in[4];
    const float* cpb_w1  = (const float*)d_in[5];
    const float* cpb_b1  = (const float*)d_in[6];
    const float* cpb_w2  = (const float*)d_in[7];
    const float* proj_w  = (const float*)d_in[8];
    const float* proj_b  = (const float*)d_in[9];
    const float* rtable  = (const float*)d_in[10];
    const int*   ridx    = (const int*)d_in[11];
    float* out = (float*)d_out;

    static const int qkv_smem  = 128 * 132 * 4;   // 67584 (epilogue S bound)
    static const int proj_smem = 4 * 2560 * 4;    // 40960
    cudaFuncSetAttribute(qkv_tc_kernel, cudaFuncAttributeMaxDynamicSharedMemorySize, qkv_smem);
    cudaFuncSetAttribute(proj_tc_kernel, cudaFuncAttributeMaxDynamicSharedMemorySize, proj_smem);
    cudaFuncSetAttribute(attn_tc_kernel, cudaFuncAttributeMaxDynamicSharedMemorySize, ATTN_SMEM);

    cpb_kernel<<<(MT + 31) / 32, 256>>>(rtable, cpb_w1, cpb_b1, cpb_w2);
    bias_gather_kernel<<<(NH * LQ * LQ) / 256, 256>>>(ridx, lscale);
    qkv_tc_kernel<<<dim3((NW * LQ) / 128, 3), 256, qkv_smem>>>(x, qkv_w, q_bias, v_bias, lscale);
    attn_tc_kernel<<<NW * NH, 256, ATTN_SMEM>>>();
    proj_tc_kernel<<<(NW * LQ) / 128, 256, proj_smem>>>(proj_w, proj_b, out);
}

// round 17
// speedup vs baseline: 2.0788x; 1.0394x over previous
#include <cuda_runtime.h>
#include <cuda_bf16.h>
#include <math.h>

#define NW 512      // num windows (B_)
#define LQ 256      // tokens per window (L)
#define CD 128      // channels (C)
#define NH 4        // heads
#define HD 32       // head dim
#define MT 1575     // rel table rows (15*15*7)
#define LOG2E 1.44269504088896340736f

__device__ __forceinline__ float ex2f(float x) {
    float y;
    asm("ex2.approx.f32 %0, %1;" : "=f"(y) : "f"(x));
    return y;
}

// ---------------- bf16 helpers ----------------
// split pair (x0,x1) into packed bf16x2 hi and lo (x0 in low half)
__device__ __forceinline__ void bf_split2(float x0, float x1, unsigned& h, unsigned& l) {
    __nv_bfloat16 h0 = __float2bfloat16(x0);
    __nv_bfloat16 h1 = __float2bfloat16(x1);
    float r0 = x0 - __bfloat162float(h0);
    float r1 = x1 - __bfloat162float(h1);
    __nv_bfloat162 hh; hh.x = h0; hh.y = h1;
    __nv_bfloat162 ll; ll.x = __float2bfloat16(r0); ll.y = __float2bfloat16(r1);
    h = *(unsigned*)&hh;
    l = *(unsigned*)&ll;
}
__device__ __forceinline__ void mma_bf16(float c[4], const unsigned a[4], const unsigned b[2]) {
    asm("mma.sync.aligned.m16n8k16.row.col.f32.bf16.bf16.f32 "
        "{%0,%1,%2,%3}, {%4,%5,%6,%7}, {%8,%9}, {%0,%1,%2,%3};"
        : "+f"(c[0]), "+f"(c[1]), "+f"(c[2]), "+f"(c[3])
        : "r"(a[0]), "r"(a[1]), "r"(a[2]), "r"(a[3]), "r"(b[0]), "r"(b[1]));
}

// ---------------- device scratch ----------------
static __device__ float g_bias_table[MT * NH];                    // (M, H)
static __device__ float g_bias[NH * LQ * LQ];                     // log2e*(16sig - M_h), [h][key][query]
static __device__ float g_q[(size_t)NW * NH * LQ * HD];           // normalized * scale * log2e
static __device__ float g_k[(size_t)NW * NH * LQ * HD];
static __device__ float g_v[(size_t)NW * NH * LQ * HD];
static __device__ float g_att[(size_t)NW * LQ * CD];

// ---------------- CPB MLP ----------------
__global__ void cpb_kernel(const float* __restrict__ table, const float* __restrict__ w1,
                           const float* __restrict__ b1, const float* __restrict__ w2)
{
    int t  = threadIdx.x;
    int mi = t >> 3, ui = t & 7;
    int m  = blockIdx.x * 32 + mi;
    float a0 = 0.f, a1 = 0.f, a2 = 0.f, a3 = 0.f;
    if (m < MT) {
        float t0 = table[m*3+0], t1 = table[m*3+1], t2 = table[m*3+2];
        for (int u = ui; u < 512; u += 8) {
            float hid = fmaf(w1[u*3+0], t0, fmaf(w1[u*3+1], t1, fmaf(w1[u*3+2], t2, b1[u])));
            hid = fmaxf(hid, 0.f);
            a0 = fmaf(hid, w2[u],        a0);
            a1 = fmaf(hid, w2[512+u],    a1);
            a2 = fmaf(hid, w2[1024+u],   a2);
            a3 = fmaf(hid, w2[1536+u],   a3);
        }
    }
    #pragma unroll
    for (int off = 4; off >= 1; off >>= 1) {
        a0 += __shfl_down_sync(0xffffffffu, a0, off, 8);
        a1 += __shfl_down_sync(0xffffffffu, a1, off, 8);
        a2 += __shfl_down_sync(0xffffffffu, a2, off, 8);
        a3 += __shfl_down_sync(0xffffffffu, a3, off, 8);
    }
    if (ui == 0 && m < MT) {
        g_bias_table[m*NH+0] = a0;
        g_bias_table[m*NH+1] = a1;
        g_bias_table[m*NH+2] = a2;
        g_bias_table[m*NH+3] = a3;
    }
}

// ---------------- bias gather: log2e * (16*sigmoid - M_h), transposed ----------
__global__ void bias_gather_kernel(const int* __restrict__ idx, const float* __restrict__ ls)
{
    int i = blockIdx.x * blockDim.x + threadIdx.x;   // over NH*LQ*LQ
    if (i >= NH * LQ * LQ) return;
    int h  = i >> 16;
    int jk = (i >> 8) & 255;   // key
    int iq = i & 255;          // query (fastest)
    float mh = expf(fminf(ls[h], 4.60517018598809136804f)) + 16.f;
    float x = g_bias_table[idx[iq * LQ + jk] * NH + h];
    g_bias[i] = (16.f / (1.f + __expf(-x)) - mh) * LOG2E;
}

// ---------------- QKV GEMM via 3xbf16-k16 tensor cores + fused bias/normalize --
__global__ __launch_bounds__(256, 2) void qkv_tc_kernel(
    const float* __restrict__ A,
    const float* __restrict__ W,
    const float* __restrict__ qb,
    const float* __restrict__ vb,
    const float* __restrict__ ls)
{
    extern __shared__ unsigned smu[];   // staging: 4*2560 u32; epilogue: S 128*132 f
    __shared__ float fac[512];
    unsigned* Ahu = smu;                // [128][20]
    unsigned* Alu = smu + 2560;
    unsigned* Whu = smu + 5120;
    unsigned* Wlu = smu + 7680;
    const int tid  = threadIdx.x;
    const int warp = tid >> 5, lane = tid & 31;
    const int wm = warp >> 1, wn = warp & 1;
    const int grp = lane >> 2, tig = lane & 3;
    const int r0 = blockIdx.x * 128;
    const int tmode = blockIdx.y;
    const float* Wbase = W + tmode * 128 * 128;

    float c[2][8][4];
    #pragma unroll
    for (int mt = 0; mt < 2; mt++)
        #pragma unroll
        for (int nt = 0; nt < 8; nt++)
            #pragma unroll
            for (int i = 0; i < 4; i++) c[mt][nt][i] = 0.f;

    for (int kc = 0; kc < 4; kc++) {
        const int k0c = kc * 32;
        #pragma unroll
        for (int rep = 0; rep < 4; rep++) {
            int f = tid + rep * 256;
            int row = f >> 3, c4 = f & 7;
            float4 v = *(const float4*)(A + (size_t)(r0 + row) * CD + k0c + c4 * 4);
            unsigned h0, l0, h1, l1;
            bf_split2(v.x, v.y, h0, l0);
            bf_split2(v.z, v.w, h1, l1);
            Ahu[row*20 + 2*c4]     = h0;
            Ahu[row*20 + 2*c4 + 1] = h1;
            Alu[row*20 + 2*c4]     = l0;
            Alu[row*20 + 2*c4 + 1] = l1;
        }
        #pragma unroll
        for (int rep = 0; rep < 4; rep++) {
            int f = tid + rep * 256;
            int row = f >> 3, c4 = f & 7;
            float4 v = *(const float4*)(Wbase + row * CD + k0c + c4 * 4);
            unsigned h0, l0, h1, l1;
            bf_split2(v.x, v.y, h0, l0);
            bf_split2(v.z, v.w, h1, l1);
            Whu[row*20 + 2*c4]     = h0;
            Whu[row*20 + 2*c4 + 1] = h1;
            Wlu[row*20 + 2*c4]     = l0;
            Wlu[row*20 + 2*c4 + 1] = l1;
        }
        __syncthreads();
        #pragma unroll
        for (int s = 0; s < 2; s++) {
            unsigned ah[2][4], al[2][4];
            #pragma unroll
            for (int mt = 0; mt < 2; mt++) {
                int rb = wm*32 + mt*16 + grp;
                ah[mt][0] = Ahu[rb*20     + s*8 + tig];
                ah[mt][1] = Ahu[(rb+8)*20 + s*8 + tig];
                ah[mt][2] = Ahu[rb*20     + s*8 + tig + 4];
                ah[mt][3] = Ahu[(rb+8)*20 + s*8 + tig + 4];
                al[mt][0] = Alu[rb*20     + s*8 + tig];
                al[mt][1] = Alu[(rb+8)*20 + s*8 + tig];
                al[mt][2] = Alu[rb*20     + s*8 + tig + 4];
                al[mt][3] = Alu[(rb+8)*20 + s*8 + tig + 4];
            }
            #pragma unroll
            for (int nt = 0; nt < 8; nt++) {
                int n = wn*64 + nt*8 + grp;
                unsigned bh[2], bl[2];
                bh[0] = Whu[n*20 + s*8 + tig];
                bh[1] = Whu[n*20 + s*8 + tig + 4];
                bl[0] = Wlu[n*20 + s*8 + tig];
                bl[1] = Wlu[n*20 + s*8 + tig + 4];
                mma_bf16(c[0][nt], ah[0], bh);
                mma_bf16(c[1][nt], ah[1], bh);
                mma_bf16(c[0][nt], ah[0], bl);
                mma_bf16(c[1][nt], ah[1], bl);
                mma_bf16(c[0][nt], al[0], bh);
                mma_bf16(c[1][nt], al[1], bh);
            }
        }
        __syncthreads();
    }

    float* S = (float*)smu;   // 128 x 132
    #pragma unroll
    for (int mt = 0; mt < 2; mt++)
        #pragma unroll
        for (int nt = 0; nt < 8; nt++) {
            int r   = wm*32 + mt*16 + grp;
            int col = wn*64 + nt*8 + 2*tig;
            float b0 = 0.f, b1 = 0.f;
            if (tmode == 0)      { b0 = qb[col]; b1 = qb[col+1]; }
            else if (tmode == 2) { b0 = vb[col]; b1 = vb[col+1]; }
            float2 v01 = make_float2(c[mt][nt][0] + b0, c[mt][nt][1] + b1);
            float2 v23 = make_float2(c[mt][nt][2] + b0, c[mt][nt][3] + b1);
            *(float2*)(S + r * 132 + col)       = v01;
            *(float2*)(S + (r + 8) * 132 + col) = v23;
        }
    __syncthreads();
    #pragma unroll
    for (int it = 0; it < 2; it++) {
        int idx = tid + it * 256;
        int row = idx >> 2, hh = idx & 3;
        float f;
        if (tmode == 2) {
            f = 1.f;
        } else {
            const float* p = S + row * 132 + hh * 32;
            float ss = 0.f;
            #pragma unroll
            for (int d = 0; d < 32; d++) ss = fmaf(p[d], p[d], ss);
            f = 1.f / fmaxf(sqrtf(ss), 1e-12f);
            if (tmode == 0) f *= expf(fminf(ls[hh], 4.60517018598809136804f)) * LOG2E;
        }
        fac[idx] = f;
    }
    __syncthreads();
    float* out = (tmode == 0) ? g_q : (tmode == 1) ? g_k : g_v;
    #pragma unroll
    for (int rep = 0; rep < 16; rep++) {
        int f = tid + rep * 256;
        int row = f >> 5, c4 = f & 31;
        int col = c4 * 4;
        int hh = col >> 5, d = col & 31;
        int gr = r0 + row;
        int b = gr >> 8, l = gr & 255;
        float4 v = *(const float4*)(S + row * 132 + col);
        float fc = fac[row * 4 + hh];
        v.x *= fc; v.y *= fc; v.z *= fc; v.w *= fc;
        *(float4*)(out + (size_t)(((b * NH + hh) * LQ) + l) * HD + d) = v;
    }
}

// ---------------- bf16 tensor-core attention, 2 CTAs per (window, head) -------
// CTA handles 128 query rows (half = blockIdx.x & 1); 256 thr = 8 warps,
// warp w owns the m16 tile at rows half*128 + w*16 .. +16.
// Per-thread state halved vs 1-CTA version -> fits 2 CTAs/SM (occupancy 2x).
// Full K, V staged per CTA (bf16 hi/lo pairs); pp holds 128 local query rows.
#define KH_OFF 0
#define KL_OFF 5120
#define VH_OFF 10240
#define VL_OFF 14464
#define PP_OFF 18688
#define ATTN_SMEM ((PP_OFF + 5120) * 4)   // 95232 bytes

__global__ __launch_bounds__(256, 2) void attn_tc_kernel()
{
    extern __shared__ unsigned shu[];
    unsigned* khu = shu + KH_OFF;   // [256][20] u32
    unsigned* klu = shu + KL_OFF;
    unsigned* vhu = shu + VH_OFF;   // [32][132] u32 key-pairs
    unsigned* vlu = shu + VL_OFF;
    unsigned* ppu = shu + PP_OFF;   // [128][40] u32 (hi,lo) interleaved
    __nv_bfloat16* vhb = (__nv_bfloat16*)vhu;   // [32][264] halves
    __nv_bfloat16* vlb = (__nv_bfloat16*)vlu;
    const int bh   = blockIdx.x >> 1;
    const int half = blockIdx.x & 1;
    const int h  = bh & 3;
    const int b  = bh >> 2;
    const float* qg = g_q + (size_t)bh * LQ * HD;
    const float* kg = g_k + (size_t)bh * LQ * HD;
    const float* vg = g_v + (size_t)bh * LQ * HD;
    const int tid  = threadIdx.x;
    const int warp = tid >> 5, lane = tid & 31;
    const int grp  = lane >> 2, tig = lane & 3;

    // ---- stage full K (bf16 hi/lo d-pairs) and V^T (bf16 hi/lo along key) ----
    #pragma unroll
    for (int rep = 0; rep < 8; rep++) {
        int f = tid + rep * 256;
        int row = f >> 3, c4 = f & 7;
        float4 kv = *(const float4*)(kg + (size_t)f * 4);
        unsigned h0, l0, h1, l1;
        bf_split2(kv.x, kv.y, h0, l0);
        bf_split2(kv.z, kv.w, h1, l1);
        khu[row*20 + 2*c4]     = h0;
        khu[row*20 + 2*c4 + 1] = h1;
        klu[row*20 + 2*c4]     = l0;
        klu[row*20 + 2*c4 + 1] = l1;
        float4 vv = *(const float4*)(vg + (size_t)f * 4);
        int dg = c4 * 4;
        {
            __nv_bfloat16 hh0 = __float2bfloat16(vv.x);
            vhb[(dg+0)*264 + row] = hh0;
            vlb[(dg+0)*264 + row] = __float2bfloat16(vv.x - __bfloat162float(hh0));
            __nv_bfloat16 hh1 = __float2bfloat16(vv.y);
            vhb[(dg+1)*264 + row] = hh1;
            vlb[(dg+1)*264 + row] = __float2bfloat16(vv.y - __bfloat162float(hh1));
            __nv_bfloat16 hh2 = __float2bfloat16(vv.z);
            vhb[(dg+2)*264 + row] = hh2;
            vlb[(dg+2)*264 + row] = __float2bfloat16(vv.z - __bfloat162float(hh2));
            __nv_bfloat16 hh3 = __float2bfloat16(vv.w);
            vhb[(dg+3)*264 + row] = hh3;
            vlb[(dg+3)*264 + row] = __float2bfloat16(vv.w - __bfloat162float(hh3));
        }
    }

    // ---- Q fragments from gmem (one m16 tile per warp) ----
    const int qrb = half*128 + warp*16 + grp;   // global query row
    unsigned qfh[2][4], qfl[2][4];              // [s][reg]
    #pragma unroll
    for (int s = 0; s < 2; s++) {
        int kbq = s*16 + 2*tig;
        float2 q00 = *(const float2*)(qg + (size_t)qrb*HD     + kbq);
        float2 q01 = *(const float2*)(qg + (size_t)(qrb+8)*HD + kbq);
        float2 q10 = *(const float2*)(qg + (size_t)qrb*HD     + kbq + 8);
        float2 q11 = *(const float2*)(qg + (size_t)(qrb+8)*HD + kbq + 8);
        bf_split2(q00.x, q00.y, qfh[s][0], qfl[s][0]);
        bf_split2(q01.x, q01.y, qfh[s][1], qfl[s][1]);
        bf_split2(q10.x, q10.y, qfh[s][2], qfl[s][2]);
        bf_split2(q11.x, q11.y, qfh[s][3], qfl[s][3]);
    }
    __syncthreads();

    const float* bb = g_bias + h * (LQ * LQ);
    const int lr = warp*16 + grp;               // local pp row

    float o[4][4];
    #pragma unroll
    for (int nt = 0; nt < 4; nt++)
        #pragma unroll
        for (int i = 0; i < 4; i++) o[nt][i] = 0.f;
    float lsum[2] = {0.f, 0.f};

    #pragma unroll 1
    for (int kb = 0; kb < 8; kb++) {
        const int kbase = kb * 32;
        // ---- QK^T ----
        float cqk[4][4];
        #pragma unroll
        for (int nt = 0; nt < 4; nt++)
            #pragma unroll
            for (int i = 0; i < 4; i++) cqk[nt][i] = 0.f;
        #pragma unroll
        for (int s = 0; s < 2; s++) {
            #pragma unroll
            for (int nt = 0; nt < 4; nt++) {
                int key = kbase + nt*8 + grp;
                unsigned bhf[2], blf[2];
                bhf[0] = khu[key*20 + s*8 + tig];
                bhf[1] = khu[key*20 + s*8 + tig + 4];
                blf[0] = klu[key*20 + s*8 + tig];
                blf[1] = klu[key*20 + s*8 + tig + 4];
                mma_bf16(cqk[nt], qfh[s], bhf);
                mma_bf16(cqk[nt], qfh[s], blf);
                mma_bf16(cqk[nt], qfl[s], bhf);
            }
        }
        // ---- exp2(S + bias') -> split P pairs -> pp, accumulate l ----
        #pragma unroll
        for (int nt = 0; nt < 4; nt++) {
            int col = kbase + nt*8 + 2*tig;
            float b00 = bb[col*256 + qrb];
            float b01 = bb[(col+1)*256 + qrb];
            float b10 = bb[col*256 + qrb + 8];
            float b11 = bb[(col+1)*256 + qrb + 8];
            float p0 = ex2f(cqk[nt][0] + b00);
            float p1 = ex2f(cqk[nt][1] + b01);
            float p2 = ex2f(cqk[nt][2] + b10);
            float p3 = ex2f(cqk[nt][3] + b11);
            lsum[0] += p0 + p1;
            lsum[1] += p2 + p3;
            int kp = nt*4 + tig;
            unsigned h01, l01, h23, l23;
            bf_split2(p0, p1, h01, l01);
            bf_split2(p2, p3, h23, l23);
            *(uint2*)(ppu + lr*40     + kp*2) = make_uint2(h01, l01);
            *(uint2*)(ppu + (lr+8)*40 + kp*2) = make_uint2(h23, l23);
        }
        // ---- P · V (pp rows warp-private: no sync) ----
        #pragma unroll
        for (int s = 0; s < 2; s++) {
            unsigned pah[4], pal[4];
            uint2 t0 = *(uint2*)(ppu + lr*40     + (s*8 + tig)*2);
            uint2 t1 = *(uint2*)(ppu + (lr+8)*40 + (s*8 + tig)*2);
            uint2 t2 = *(uint2*)(ppu + lr*40     + (s*8 + tig + 4)*2);
            uint2 t3 = *(uint2*)(ppu + (lr+8)*40 + (s*8 + tig + 4)*2);
            pah[0] = t0.x; pal[0] = t0.y;
            pah[1] = t1.x; pal[1] = t1.y;
            pah[2] = t2.x; pal[2] = t2.y;
            pah[3] = t3.x; pal[3] = t3.y;
            #pragma unroll
            for (int nt = 0; nt < 4; nt++) {
                int d = nt*8 + grp;
                int kpb = (kbase >> 1) + s*8 + tig;
                unsigned vbh[2], vbl[2];
                vbh[0] = vhu[d*132 + kpb];
                vbh[1] = vhu[d*132 + kpb + 4];
                vbl[0] = vlu[d*132 + kpb];
                vbl[1] = vlu[d*132 + kpb + 4];
                mma_bf16(o[nt], pah, vbh);
                mma_bf16(o[nt], pah, vbl);
                mma_bf16(o[nt], pal, vbh);
            }
        }
    }

    // ---- epilogue ----
    #pragma unroll
    for (int j = 0; j < 2; j++) {
        lsum[j] += __shfl_xor_sync(0xffffffffu, lsum[j], 1);
        lsum[j] += __shfl_xor_sync(0xffffffffu, lsum[j], 2);
    }
    float inv0 = 1.f / lsum[0];
    float inv1 = 1.f / lsum[1];
    #pragma unroll
    for (int nt = 0; nt < 4; nt++) {
        int col = h*HD + nt*8 + 2*tig;
        float* o0 = g_att + (size_t)(b*LQ + qrb) * CD + col;
        float* o1 = g_att + (size_t)(b*LQ + qrb + 8) * CD + col;
        *(float2*)o0 = make_float2(o[nt][0] * inv0, o[nt][1] * inv0);
        *(float2*)o1 = make_float2(o[nt][2] * inv1, o[nt][3] * inv1);
    }
}

// ---------------- projection GEMM via 3xbf16-k16 tensor cores ----------------
__global__ __launch_bounds__(256, 2) void proj_tc_kernel(
    const float* __restrict__ W,
    const float* __restrict__ pb,
    float* __restrict__ out)
{
    extern __shared__ unsigned smu[];   // 4*2560 u32
    unsigned* Ahu = smu;
    unsigned* Alu = smu + 2560;
    unsigned* Whu = smu + 5120;
    unsigned* Wlu = smu + 7680;
    const int tid  = threadIdx.x;
    const int warp = tid >> 5, lane = tid & 31;
    const int wm = warp >> 1, wn = warp & 1;
    const int grp = lane >> 2, tig = lane & 3;
    const int r0 = blockIdx.x * 128;
    const float* A = g_att;

    float c[2][8][4];
    #pragma unroll
    for (int mt = 0; mt < 2; mt++)
        #pragma unroll
        for (int nt = 0; nt < 8; nt++)
            #pragma unroll
            for (int i = 0; i < 4; i++) c[mt][nt][i] = 0.f;

    for (int kc = 0; kc < 4; kc++) {
        const int k0c = kc * 32;
        #pragma unroll
        for (int rep = 0; rep < 4; rep++) {
            int f = tid + rep * 256;
            int row = f >> 3, c4 = f & 7;
            float4 v = *(const float4*)(A + (size_t)(r0 + row) * CD + k0c + c4 * 4);
            unsigned h0, l0, h1, l1;
            bf_split2(v.x, v.y, h0, l0);
            bf_split2(v.z, v.w, h1, l1);
            Ahu[row*20 + 2*c4]     = h0;
            Ahu[row*20 + 2*c4 + 1] = h1;
            Alu[row*20 + 2*c4]     = l0;
            Alu[row*20 + 2*c4 + 1] = l1;
        }
        #pragma unroll
        for (int rep = 0; rep < 4; rep++) {
            int f = tid + rep * 256;
            int row = f >> 3, c4 = f & 7;
            float4 v = *(const float4*)(W + row * CD + k0c + c4 * 4);
            unsigned h0, l0, h1, l1;
            bf_split2(v.x, v.y, h0, l0);
            bf_split2(v.z, v.w, h1, l1);
            Whu[row*20 + 2*c4]     = h0;
            Whu[row*20 + 2*c4 + 1] = h1;
            Wlu[row*20 + 2*c4]     = l0;
            Wlu[row*20 + 2*c4 + 1] = l1;
        }
        __syncthreads();
        #pragma unroll
        for (int s = 0; s < 2; s++) {
            unsigned ah[2][4], al[2][4];
            #pragma unroll
            for (int mt = 0; mt < 2; mt++) {
                int rb = wm*32 + mt*16 + grp;
                ah[mt][0] = Ahu[rb*20     + s*8 + tig];
                ah[mt][1] = Ahu[(rb+8)*20 + s*8 + tig];
                ah[mt][2] = Ahu[rb*20     + s*8 + tig + 4];
                ah[mt][3] = Ahu[(rb+8)*20 + s*8 + tig + 4];
                al[mt][0] = Alu[rb*20     + s*8 + tig];
                al[mt][1] = Alu[(rb+8)*20 + s*8 + tig];
                al[mt][2] = Alu[rb*20     + s*8 + tig + 4];
                al[mt][3] = Alu[(rb+8)*20 + s*8 + tig + 4];
            }
            #pragma unroll
            for (int nt = 0; nt < 8; nt++) {
                int n = wn*64 + nt*8 + grp;
                unsigned bh[2], bl[2];
                bh[0] = Whu[n*20 + s*8 + tig];
                bh[1] = Whu[n*20 + s*8 + tig + 4];
                bl[0] = Wlu[n*20 + s*8 + tig];
                bl[1] = Wlu[n*20 + s*8 + tig + 4];
                mma_bf16(c[0][nt], ah[0], bh);
                mma_bf16(c[1][nt], ah[1], bh);
                mma_bf16(c[0][nt], ah[0], bl);
                mma_bf16(c[1][nt], ah[1], bl);
                mma_bf16(c[0][nt], al[0], bh);
                mma_bf16(c[1][nt], al[1], bh);
            }
        }
        __syncthreads();
    }

    #pragma unroll
    for (int mt = 0; mt < 2; mt++)
        #pragma unroll
        for (int nt = 0; nt < 8; nt++) {
            int r   = r0 + wm*32 + mt*16 + grp;
            int col = wn*64 + nt*8 + 2*tig;
            float b0 = pb[col], b1 = pb[col+1];
            float2 v01 = make_float2(c[mt][nt][0] + b0, c[mt][nt][1] + b1);
            float2 v23 = make_float2(c[mt][nt][2] + b0, c[mt][nt][3] + b1);
            *(float2*)(out + (size_t)r * CD + col)       = v01;
            *(float2*)(out + (size_t)(r + 8) * CD + col) = v23;
        }
}

// ---------------- launch ----------------
extern "C" void kernel_launch(void* const* d_in, const int* in_sizes, int n_in,
                              void* d_out, int out_size)
{
    (void)in_sizes; (void)n_in; (void)out_size;
    const float* x       = (const float*)d_in[0];
    const float* qkv_w   = (const float*)d_in[1];
    const float* q_bias  = (const float*)d_in[2];
    const float* v_bias  = (const float*)d_in[3];
    const float* lscale  = (const float*)d_in[4];
    const float* cpb_w1  = (const float*)d_in[5];
    const float* cpb_b1  = (const float*)d_in[6];
    const float* cpb_w2  = (const float*)d_in[7];
    const float* proj_w  = (const float*)d_in[8];
    const float* proj_b  = (const float*)d_in[9];
    const float* rtable  = (const float*)d_in[10];
    const int*   ridx    = (const int*)d_in[11];
    float* out = (float*)d_out;

    static const int qkv_smem  = 128 * 132 * 4;   // 67584 (epilogue S bound)
    static const int proj_smem = 4 * 2560 * 4;    // 40960
    cudaFuncSetAttribute(qkv_tc_kernel, cudaFuncAttributeMaxDynamicSharedMemorySize, qkv_smem);
    cudaFuncSetAttribute(proj_tc_kernel, cudaFuncAttributeMaxDynamicSharedMemorySize, proj_smem);
    cudaFuncSetAttribute(attn_tc_kernel, cudaFuncAttributeMaxDynamicSharedMemorySize, ATTN_SMEM);

    cpb_kernel<<<(MT + 31) / 32, 256>>>(rtable, cpb_w1, cpb_b1, cpb_w2);
    bias_gather_kernel<<<(NH * LQ * LQ) / 256, 256>>>(ridx, lscale);
    qkv_tc_kernel<<<dim3((NW * LQ) / 128, 3), 256, qkv_smem>>>(x, qkv_w, q_bias, v_bias, lscale);
    attn_tc_kernel<<<NW * NH * 2, 256, ATTN_SMEM>>>();
    proj_tc_kernel<<<(NW * LQ) / 128, 256, proj_smem>>>(proj_w, proj_b, out);
}